// round 1
// baseline (speedup 1.0000x reference)
#include <cuda_runtime.h>
#include <math.h>

#define SEQ 4096
#define EMB 2048
#define NKH 16
#define NVH 32
#define DK 128
#define DV 128
#define CHUNK 64
#define NC (SEQ/CHUNK)      /* 64 */
#define QKVZ_N 12288
#define CONV_DIM 8192
#define QSCALE 0.08838834764831845f  /* 1/sqrt(128) */

/* ---------------- scratch (device globals; no allocs allowed) ------------- */
__device__ float g_qkvz[(size_t)SEQ*QKVZ_N];            /* 192 MiB */
__device__ float g_ba[SEQ*64];
__device__ float g_qc[(size_t)SEQ*2048];                /* silu(conv(q)) * QSCALE */
__device__ float g_kc[(size_t)SEQ*2048];
__device__ float g_vc[(size_t)SEQ*4096];
__device__ float g_beta[NVH*SEQ];
__device__ float g_gcum[NVH*SEQ];
__device__ float g_attnA[(size_t)NVH*NC*CHUNK*CHUNK];   /* a_i matrices */
__device__ float g_vintra[(size_t)NVH*SEQ*DV];
__device__ float g_kcd[(size_t)NVH*SEQ*DK];
__device__ float g_core[(size_t)SEQ*NVH*DV];
__device__ float g_xf[(size_t)SEQ*4096];

/* ---------------- generic SGEMM: C[M,N] = A[M,K] @ B[K,N], row-major ------ */
/* requires M%128==0, N%128==0, K%16==0 */
__global__ __launch_bounds__(256)
void sgemm128(const float* __restrict__ A, const float* __restrict__ B,
              float* __restrict__ C, int M, int N, int K) {
    __shared__ float As[16][128];
    __shared__ float Bs[16][128];
    const int bx = blockIdx.x, by = blockIdx.y;
    const int tid = threadIdx.x;
    const int tcol = tid & 15, trow = tid >> 4;
    const int aRow = tid >> 2;            /* 0..63 */
    const int aCol4 = (tid & 3) << 2;     /* 0,4,8,12 */
    const int bRow = tid >> 5;            /* 0..7 */
    const int bCol4 = (tid & 31) << 2;    /* 0..124 */
    float acc[8][8];
#pragma unroll
    for (int i = 0; i < 8; i++)
#pragma unroll
        for (int j = 0; j < 8; j++) acc[i][j] = 0.f;

    const float* Ap = A + (size_t)(by*128)*K;
    const float* Bp = B + bx*128;

    for (int k0 = 0; k0 < K; k0 += 16) {
#pragma unroll
        for (int l = 0; l < 2; l++) {
            int r = aRow + l*64;
            float4 v = *(const float4*)(Ap + (size_t)r*K + k0 + aCol4);
            As[aCol4+0][r] = v.x; As[aCol4+1][r] = v.y;
            As[aCol4+2][r] = v.z; As[aCol4+3][r] = v.w;
        }
#pragma unroll
        for (int l = 0; l < 2; l++) {
            int r = bRow + l*8;
            float4 v = *(const float4*)(Bp + (size_t)(k0 + r)*N + bCol4);
            *(float4*)&Bs[r][bCol4] = v;
        }
        __syncthreads();
#pragma unroll
        for (int kk = 0; kk < 16; kk++) {
            float a[8], b[8];
#pragma unroll
            for (int i = 0; i < 8; i++) a[i] = As[kk][trow*8 + i];
#pragma unroll
            for (int j = 0; j < 8; j++) b[j] = Bs[kk][tcol*8 + j];
#pragma unroll
            for (int i = 0; i < 8; i++)
#pragma unroll
                for (int j = 0; j < 8; j++) acc[i][j] += a[i]*b[j];
        }
        __syncthreads();
    }
    float* Cp = C + (size_t)(by*128 + trow*8)*N + bx*128 + tcol*8;
#pragma unroll
    for (int i = 0; i < 8; i++) {
        *(float4*)(Cp + (size_t)i*N + 0) = make_float4(acc[i][0],acc[i][1],acc[i][2],acc[i][3]);
        *(float4*)(Cp + (size_t)i*N + 4) = make_float4(acc[i][4],acc[i][5],acc[i][6],acc[i][7]);
    }
}

/* ---------------- ba = hidden @ W_ba : M=4096, K=2048, N=64 --------------- */
__global__ __launch_bounds__(256)
void ba_gemm(const float* __restrict__ A, const float* __restrict__ B) {
    int c = threadIdx.x & 63;
    int rl = threadIdx.x >> 6;                  /* 0..3 */
    int row0 = blockIdx.x*16 + rl*4;
    float acc[4] = {0,0,0,0};
    for (int k = 0; k < 2048; k++) {
        float b = __ldg(&B[k*64 + c]);
#pragma unroll
        for (int r = 0; r < 4; r++)
            acc[r] += __ldg(&A[(size_t)(row0+r)*2048 + k]) * b;
    }
#pragma unroll
    for (int r = 0; r < 4; r++) g_ba[(size_t)(row0+r)*64 + c] = acc[r];
}

/* ---------------- depthwise causal conv (ksz=4) + SiLU -------------------- */
__global__ void conv_silu(const float* __restrict__ cw) {
    int idx = blockIdx.x*blockDim.x + threadIdx.x;
    if (idx >= SEQ*CONV_DIM) return;
    int s = idx >> 13;
    int c = idx & 8191;
    int col;
    if (c < 2048)      { int kh = c >> 7, d = c & 127;       col = kh*768 + d; }
    else if (c < 4096) { int c2 = c-2048; int kh = c2 >> 7;  col = kh*768 + 128 + (c2 & 127); }
    else               { int c2 = c-4096; int h16 = c2 >> 8; col = h16*768 + 256 + (c2 & 255); }
    float acc = 0.f;
#pragma unroll
    for (int j = 0; j < 4; j++) {
        int t = s - 3 + j;
        if (t >= 0) acc += g_qkvz[(size_t)t*QKVZ_N + col] * cw[j*CONV_DIM + c];
    }
    float r = acc / (1.f + expf(-acc));  /* silu */
    if (c < 2048)       g_qc[(size_t)s*2048 + c]        = r * QSCALE;
    else if (c < 4096)  g_kc[(size_t)s*2048 + (c-2048)] = r;
    else                g_vc[(size_t)s*4096 + (c-4096)] = r;
}

/* ---------------- beta, g, cumsum(g) within chunk ------------------------- */
__global__ void gates_kernel(const float* __restrict__ A_log,
                             const float* __restrict__ dt_bias) {
    int chunk = blockIdx.x, hv = blockIdx.y, t = threadIdx.x;
    int s = chunk*CHUNK + t;
    int base = ((hv >> 1) << 2) + (hv & 1);
    float bg = g_ba[(size_t)s*64 + base];
    float ag = g_ba[(size_t)s*64 + base + 2];
    g_beta[hv*SEQ + s] = 1.f / (1.f + expf(-bg));
    float x = ag + dt_bias[hv];
    float sp = (x > 20.f) ? x : log1pf(expf(x));
    float g = -expf(A_log[hv]) * sp;
    __shared__ float sh[64];
    sh[t] = g;
    __syncthreads();
    for (int off = 1; off < 64; off <<= 1) {
        float v = (t >= off) ? sh[t-off] : 0.f;
        __syncthreads();
        sh[t] += v;
        __syncthreads();
    }
    g_gcum[hv*SEQ + s] = sh[t];
}

/* ------------- per (head, chunk) parallel precompute ----------------------
   L, attn=(I-L)^-1, a_i, v_intra, k_cumdecay                                */
__global__ __launch_bounds__(256)
void precompute_kernel() {
    extern __shared__ float sm[];
    float* ks    = sm;              /* 64*129 */
    float* vs    = ks + 64*129;     /* 64*129 (q, then v) */
    float* Ls    = vs + 64*129;     /* 4096 */
    float* Xs    = Ls + 4096;       /* 4096 */
    float* betas = Xs + 4096;       /* 64 */
    float* gcs   = betas + 64;      /* 64 */
    float* bgm   = gcs + 64;        /* 64 */
    const int c = blockIdx.x, hv = blockIdx.y, kh = hv >> 1;
    const int tid = threadIdx.x;

    for (int l = tid; l < 2048; l += 256) {
        int row = l >> 5, c4 = (l & 31) << 2;
        float4 v = *(const float4*)&g_kc[(size_t)(c*CHUNK+row)*2048 + kh*128 + c4];
        float* p = &ks[row*129 + c4];
        p[0]=v.x; p[1]=v.y; p[2]=v.z; p[3]=v.w;
    }
    if (tid < 64) {
        int s = c*CHUNK + tid;
        betas[tid] = g_beta[hv*SEQ + s];
        gcs[tid]   = g_gcum[hv*SEQ + s];
    }
    __syncthreads();
    if (tid < 64) bgm[tid] = betas[tid]*expf(gcs[tid]);

    /* L[i][j] = -(beta_i k_i . k_j) exp(gc_i - gc_j), strictly lower */
    for (int idx = tid; idx < 4096; idx += 256) {
        int i = idx >> 6, j = idx & 63;
        float val = 0.f;
        if (i > j) {
            float dot = 0.f;
#pragma unroll 8
            for (int d = 0; d < 128; d++) dot += ks[i*129+d]*ks[j*129+d];
            val = -betas[i]*dot*expf(gcs[i]-gcs[j]);
        }
        Ls[idx] = val;
    }
    __syncthreads();

    /* load q into vs; threads<64 do forward substitution (per-column indep) */
    for (int l = tid; l < 2048; l += 256) {
        int row = l >> 5, c4 = (l & 31) << 2;
        float4 v = *(const float4*)&g_qc[(size_t)(c*CHUNK+row)*2048 + kh*128 + c4];
        float* p = &vs[row*129 + c4];
        p[0]=v.x; p[1]=v.y; p[2]=v.z; p[3]=v.w;
    }
    if (tid < 64) {
        int j = tid;
        for (int i = 0; i < 64; i++) {
            float acc = (i == j) ? 1.f : 0.f;
            for (int m = 0; m < i; m++) acc += Ls[i*64+m]*Xs[m*64+j];
            Xs[i*64+j] = acc;
        }
    }
    __syncthreads();

    /* a_i[i][j] = (q_i . k_j) exp(gc_i - gc_j), lower incl diag */
    {
        size_t outb = (size_t)(hv*NC + c)*4096;
        for (int idx = tid; idx < 4096; idx += 256) {
            int i = idx >> 6, j = idx & 63;
            float val = 0.f;
            if (i >= j) {
                float dot = 0.f;
#pragma unroll 8
                for (int d = 0; d < 128; d++) dot += vs[i*129+d]*ks[j*129+d];
                val = dot*expf(gcs[i]-gcs[j]);
            }
            g_attnA[outb + idx] = val;
        }
    }
    __syncthreads();

    /* overwrite vs with v chunk */
    for (int l = tid; l < 2048; l += 256) {
        int row = l >> 5, c4 = (l & 31) << 2;
        float4 v = *(const float4*)&g_vc[(size_t)(c*CHUNK+row)*4096 + hv*128 + c4];
        float* p = &vs[row*129 + c4];
        p[0]=v.x; p[1]=v.y; p[2]=v.z; p[3]=v.w;
    }
    __syncthreads();

    /* kcd = X @ (k*beta*exp(gc)),  v_intra = X @ (v*beta) */
    size_t ob = (size_t)(hv*NC + c)*CHUNK*128;
    for (int idx = tid; idx < 8192; idx += 256) {
        int i = idx >> 7, d = idx & 127;
        float aK = 0.f, aV = 0.f;
        for (int m = 0; m <= i; m++) {
            float x = Xs[i*64+m];
            aK += x*bgm[m]  *ks[m*129+d];
            aV += x*betas[m]*vs[m*129+d];
        }
        g_kcd[ob + idx]    = aK;
        g_vintra[ob + idx] = aV;
    }
}

/* ------------- sequential inter-chunk scan: 32 heads x 4 DV slices -------- */
__global__ __launch_bounds__(256)
void scan_kernel() {
    extern __shared__ float sm[];
    float* state = sm;              /* 128*33 */
    float* qs    = state + 128*33;  /* 64*128 */
    float* ksm   = qs + 8192;       /* 64*128 */
    float* kcds  = ksm + 8192;      /* 64*128 */
    float* as_   = kcds + 8192;     /* 64*64  */
    float* vn    = as_ + 4096;      /* 64*33  */
    float* gcs   = vn + 64*33;      /* 64     */
    float* wexp  = gcs + 64;        /* 64     */
    const int hv = blockIdx.y, j0 = blockIdx.x*32, kh = hv >> 1;
    const int tid = threadIdx.x, jj = tid & 31, ig = tid >> 5;

    for (int l = tid; l < 128*33; l += 256) state[l] = 0.f;
    __syncthreads();

    for (int c = 0; c < NC; c++) {
        const size_t rb = (size_t)(hv*NC + c)*CHUNK;
        for (int l = tid; l < 2048; l += 256) {
            int row = l >> 5, c4 = (l & 31) << 2;
            *(float4*)&qs[row*128 + c4]   = *(const float4*)&g_qc[(size_t)(c*CHUNK+row)*2048 + kh*128 + c4];
            *(float4*)&ksm[row*128 + c4]  = *(const float4*)&g_kc[(size_t)(c*CHUNK+row)*2048 + kh*128 + c4];
            *(float4*)&kcds[row*128 + c4] = *(const float4*)&g_kcd[rb*128 + (size_t)l*4];
        }
        for (int l = tid; l < 1024; l += 256)
            *(float4*)&as_[l*4] = *(const float4*)&g_attnA[rb*64 + (size_t)l*4];
        for (int l = tid; l < 2048; l += 256) {
            int i = l >> 5, j = l & 31;
            vn[i*33 + j] = g_vintra[(rb + i)*128 + j0 + j];
        }
        if (tid < 64) gcs[tid] = g_gcum[hv*SEQ + c*CHUNK + tid];
        __syncthreads();
        if (tid < 64) wexp[tid] = expf(gcs[63] - gcs[tid]);

        /* step 2: v_new = v_intra - kcd@state ; part of out = (q e^g)@state */
        const int i0 = ig*8;
        float vacc[8], oacc[8];
#pragma unroll
        for (int r = 0; r < 8; r++) { vacc[r] = vn[(i0+r)*33 + jj]; oacc[r] = 0.f; }
        for (int d = 0; d < 128; d++) {
            float sd = state[d*33 + jj];
#pragma unroll
            for (int r = 0; r < 8; r++) vacc[r] -= kcds[(i0+r)*128 + d]*sd;
#pragma unroll
            for (int r = 0; r < 8; r++) oacc[r] += qs[(i0+r)*128 + d]*sd;
        }
#pragma unroll
        for (int r = 0; r < 8; r++) oacc[r] *= expf(gcs[i0+r]);
#pragma unroll
        for (int r = 0; r < 8; r++) vn[(i0+r)*33 + jj] = vacc[r];
        __syncthreads();

        /* step 3: out += a @ v_new ; write core */
#pragma unroll
        for (int r = 0; r < 8; r++) {
            float o = oacc[r];
            for (int m = 0; m < 64; m++) o += as_[(i0+r)*64 + m]*vn[m*33 + jj];
            g_core[(size_t)(c*CHUNK + i0 + r)*4096 + hv*128 + j0 + jj] = o;
        }

        /* step 4: state = state*e^glast + (k * e^(glast-g))^T @ v_new */
        {
            float eg = expf(gcs[63]);
            float sacc[16];
            const int d0 = ig*16;
#pragma unroll
            for (int dd = 0; dd < 16; dd++) sacc[dd] = state[(d0+dd)*33 + jj]*eg;
            for (int i = 0; i < 64; i++) {
                float vw = wexp[i]*vn[i*33 + jj];
#pragma unroll
                for (int dd = 0; dd < 16; dd++) sacc[dd] += ksm[i*128 + d0 + dd]*vw;
            }
#pragma unroll
            for (int dd = 0; dd < 16; dd++) state[(d0+dd)*33 + jj] = sacc[dd];
        }
        __syncthreads();
    }
}

/* ---------------- gated RMSNorm: one warp per (s, hv) --------------------- */
__global__ void rmsnorm_kernel(const float* __restrict__ nw) {
    int gw = (blockIdx.x*blockDim.x + threadIdx.x) >> 5;
    int lane = threadIdx.x & 31;
    int s = gw >> 5;
    int hv = gw & 31;
    size_t zbase = (size_t)s*QKVZ_N + (hv >> 1)*768 + 512 + (hv & 1)*128;
    size_t cbase = (size_t)s*4096 + hv*128;
    float x[4];
    float ss = 0.f;
#pragma unroll
    for (int r = 0; r < 4; r++) {
        int d = lane + r*32;
        float cv = g_core[cbase + d];
        float zv = g_qkvz[zbase + d];
        float xv = cv * (zv / (1.f + expf(-zv)));
        x[r] = xv;
        ss += xv*xv;
    }
#pragma unroll
    for (int off = 16; off; off >>= 1) ss += __shfl_xor_sync(0xffffffffu, ss, off);
    float inv = rsqrtf(ss*(1.f/128.f) + 1e-6f);
#pragma unroll
    for (int r = 0; r < 4; r++) {
        int d = lane + r*32;
        g_xf[cbase + d] = x[r]*inv*nw[d];
    }
}

/* ---------------- launcher ------------------------------------------------ */
extern "C" void kernel_launch(void* const* d_in, const int* in_sizes, int n_in,
                              void* d_out, int out_size) {
    const float* hidden  = (const float*)d_in[0];
    const float* W_qkvz  = (const float*)d_in[1];
    const float* W_ba    = (const float*)d_in[2];
    const float* convk   = (const float*)d_in[3];
    const float* A_log   = (const float*)d_in[4];
    const float* dt_bias = (const float*)d_in[5];
    const float* normw   = (const float*)d_in[6];
    const float* W_out   = (const float*)d_in[7];
    float* out = (float*)d_out;

    float *qkvz_p, *xf_p;
    cudaGetSymbolAddress((void**)&qkvz_p, g_qkvz);
    cudaGetSymbolAddress((void**)&xf_p, g_xf);

    cudaFuncSetAttribute(precompute_kernel,
                         cudaFuncAttributeMaxDynamicSharedMemorySize, 99584);
    cudaFuncSetAttribute(scan_kernel,
                         cudaFuncAttributeMaxDynamicSharedMemorySize, 140544);

    /* 1. qkvz = hidden @ W_qkvz */
    sgemm128<<<dim3(QKVZ_N/128, SEQ/128), 256>>>(hidden, W_qkvz, qkvz_p, SEQ, QKVZ_N, EMB);
    /* 2. ba = hidden @ W_ba */
    ba_gemm<<<256, 256>>>(hidden, W_ba);
    /* 3. conv + silu (+ q scale) */
    conv_silu<<<(SEQ*CONV_DIM)/256, 256>>>(convk);
    /* 4. beta / g cumsum */
    gates_kernel<<<dim3(NC, NVH), 64>>>(A_log, dt_bias);
    /* 5. per-chunk precompute */
    precompute_kernel<<<dim3(NC, NVH), 256, 99584>>>();
    /* 6. sequential scan */
    scan_kernel<<<dim3(4, NVH), 256, 140544>>>();
    /* 7. gated rmsnorm */
    rmsnorm_kernel<<<(SEQ*NVH)/8, 256>>>(normw);
    /* 8. out = xf @ W_out */
    sgemm128<<<dim3(EMB/128, SEQ/128), 256>>>(xf_p, W_out, out, SEQ, EMB, SEQ);
}

// round 6
// speedup vs baseline: 1.7788x; 1.7788x over previous
#include <cuda_runtime.h>
#include <cuda_bf16.h>
#include <math.h>
#include <stdint.h>

#define SEQ 4096
#define EMB 2048
#define NKH 16
#define NVH 32
#define DK 128
#define DV 128
#define CHUNK 64
#define NC (SEQ/CHUNK)      /* 64 */
#define QKVZ_N 12288
#define CONV_DIM 8192
#define QSCALE 0.08838834764831845f  /* 1/sqrt(128) */

/* single shared dynamic-smem symbol for all kernels */
extern __shared__ char dynsm[];

/* ---------------- scratch (device globals; no allocs allowed) ------------- */
__device__ float g_qkvz[(size_t)SEQ*QKVZ_N];            /* 192 MiB */
__device__ float g_ba[SEQ*64];
__device__ float g_qc[(size_t)SEQ*2048];
__device__ float g_kc[(size_t)SEQ*2048];
__device__ float g_vc[(size_t)SEQ*4096];
__device__ float g_beta[NVH*SEQ];
__device__ float g_gcum[NVH*SEQ];
__device__ float g_attnA[(size_t)NVH*NC*CHUNK*CHUNK];
__device__ float g_vintra[(size_t)NVH*SEQ*DV];
__device__ float g_kcd[(size_t)NVH*SEQ*DK];
__device__ float g_core[(size_t)SEQ*NVH*DV];
__device__ float g_xf[(size_t)SEQ*4096];

/* split-bf16 extended-K operands: A'=[Ah|Ah|Al] (MxK'), B'^T=[Bh|Bl|Bh] (NxK') */
__device__ __nv_bfloat16 g_A1[(size_t)SEQ*3*EMB];        /* 4096 x 6144  */
__device__ __nv_bfloat16 g_B1[(size_t)QKVZ_N*3*EMB];     /* 12288 x 6144 */
__device__ __nv_bfloat16 g_A2[(size_t)SEQ*3*4096];       /* 4096 x 12288 */
__device__ __nv_bfloat16 g_B2[(size_t)EMB*3*4096];       /* 2048 x 12288 */

/* ======================= asm helpers (sm_80+ safe) ======================= */
__device__ __forceinline__ uint32_t smem_u32(const void* p) {
    uint32_t a;
    asm("{ .reg .u64 t; cvta.to.shared.u64 t, %1; cvt.u32.u64 %0, t; }" : "=r"(a) : "l"(p));
    return a;
}
#define CP_ASYNC16(sa, ga) \
    asm volatile("cp.async.cg.shared.global [%0], [%1], 16;" :: "r"(sa), "l"(ga))
#define CP_COMMIT() asm volatile("cp.async.commit_group;")
#define CP_WAIT2()  asm volatile("cp.async.wait_group 2;")
#define LDSM4(R, ad) \
    asm volatile("ldmatrix.sync.aligned.m8n8.x4.shared.b16 {%0,%1,%2,%3}, [%4];" \
        : "=r"((R)[0]), "=r"((R)[1]), "=r"((R)[2]), "=r"((R)[3]) : "r"(ad))
#define MMA16816(c, a, b0, b1) \
    asm volatile("mma.sync.aligned.m16n8k16.row.col.f32.bf16.bf16.f32 " \
        "{%0,%1,%2,%3}, {%4,%5,%6,%7}, {%8,%9}, {%0,%1,%2,%3};" \
        : "+f"((c)[0]), "+f"((c)[1]), "+f"((c)[2]), "+f"((c)[3]) \
        : "r"((a)[0]), "r"((a)[1]), "r"((a)[2]), "r"((a)[3]), "r"(b0), "r"(b1))

/* ======================= split-bf16 conversions ========================== */
/* A[M][K] fp32 -> A'[M][3K] bf16 = [hi | hi | lo]; kbits = log2(K) */
__global__ void cvtA(const float* __restrict__ src, __nv_bfloat16* __restrict__ dst,
                     int kbits) {
    int idx = blockIdx.x*blockDim.x + threadIdx.x;
    int K = 1 << kbits;
    int m = idx >> kbits, k = idx & (K - 1);
    float v = src[idx];
    __nv_bfloat16 h = __float2bfloat16(v);
    __nv_bfloat16 l = __float2bfloat16(v - __bfloat162float(h));
    size_t base = ((size_t)m*3) << kbits;
    dst[base + k]       = h;
    dst[base + K + k]   = h;
    dst[base + 2*K + k] = l;
}
/* W[K][N] fp32 -> B'[N][3K] bf16 = [hi | lo | hi] (transposed) */
__global__ void cvtBt(const float* __restrict__ W, __nv_bfloat16* __restrict__ dst,
                      int K, int N) {
    __shared__ float t[32][33];
    int k0 = blockIdx.x*32, n0 = blockIdx.y*32;
    int tx = threadIdx.x, ty = threadIdx.y;
#pragma unroll
    for (int i = 0; i < 4; i++) {
        int k = k0 + ty + i*8;
        t[ty + i*8][tx] = W[(size_t)k*N + n0 + tx];
    }
    __syncthreads();
#pragma unroll
    for (int i = 0; i < 4; i++) {
        int n = n0 + ty + i*8;
        float v = t[tx][ty + i*8];
        __nv_bfloat16 h = __float2bfloat16(v);
        __nv_bfloat16 l = __float2bfloat16(v - __bfloat162float(h));
        size_t base = (size_t)n*3*K;
        dst[base + k0 + tx]       = h;
        dst[base + K + k0 + tx]   = l;
        dst[base + 2*K + k0 + tx] = h;
    }
}

/* ======================= bf16 mma.sync GEMM ==============================
   C[M,N] fp32 = A'[M,Kp] x B'[N,Kp]^T.  128x128 block tile, Kstage=64,
   4-stage cp.async pipeline, 8 warps (2m x 4n), each warp 64x32 via
   m16n8k16.                                                               */
#define GSTAGE 32768
__global__ __launch_bounds__(256, 1)
void gemm_mma(const __nv_bfloat16* __restrict__ A, const __nv_bfloat16* __restrict__ B,
              float* __restrict__ C, int Kp, int N) {
    const int tid = threadIdx.x, lane = tid & 31, wid = tid >> 5;
    const int wm = wid & 1, wn = wid >> 1;
    const int m0 = blockIdx.y*128, n0 = blockIdx.x*128;
    const uint32_t sbase = smem_u32(dynsm);
    const int S = Kp >> 6;

    float acc[4][4][4];
#pragma unroll
    for (int mi = 0; mi < 4; mi++)
#pragma unroll
        for (int ni = 0; ni < 4; ni++)
#pragma unroll
            for (int e = 0; e < 4; e++) acc[mi][ni][e] = 0.f;

    /* per-thread copy coordinates (4 chunks of 16B per operand per stage) */
    int cr[4], cc[4];
    uint32_t sOffA[4];
#pragma unroll
    for (int i = 0; i < 4; i++) {
        int id = tid + (i << 8);
        cr[i] = id >> 3; cc[i] = id & 7;
        sOffA[i] = cr[i]*128 + ((cc[i] ^ (cr[i] & 7)) << 4);
    }

#define ISSUE_STAGE(t) do {                                                   \
        uint32_t stb = sbase + ((t) & 3)*GSTAGE;                              \
        _Pragma("unroll")                                                     \
        for (int i = 0; i < 4; i++) {                                         \
            const __nv_bfloat16* g = A + (size_t)(m0 + cr[i])*Kp + (t)*64 + (cc[i] << 3); \
            CP_ASYNC16(stb + sOffA[i], g);                                    \
        }                                                                     \
        _Pragma("unroll")                                                     \
        for (int i = 0; i < 4; i++) {                                         \
            const __nv_bfloat16* g = B + (size_t)(n0 + cr[i])*Kp + (t)*64 + (cc[i] << 3); \
            CP_ASYNC16(stb + 16384 + sOffA[i], g);                            \
        }                                                                     \
    } while (0)

    ISSUE_STAGE(0); CP_COMMIT();
    ISSUE_STAGE(1); CP_COMMIT();
    ISSUE_STAGE(2); CP_COMMIT();

    /* ldmatrix address components */
    int rowA[4], swzA[4], rowB[2], swzB[2];
#pragma unroll
    for (int mi = 0; mi < 4; mi++) {
        rowA[mi] = wm*64 + mi*16 + (lane & 15);
        swzA[mi] = rowA[mi] & 7;
    }
#pragma unroll
    for (int ni2 = 0; ni2 < 2; ni2++) {
        rowB[ni2] = wn*32 + ni2*16 + ((lane >> 4) << 3) + (lane & 7);
        swzB[ni2] = rowB[ni2] & 7;
    }
    const int hiA = lane >> 4;
    const int hiB = (lane >> 3) & 1;

    for (int s = 0; s < S; s++) {
        CP_WAIT2();
        __syncthreads();
        if (s + 3 < S) ISSUE_STAGE(s + 3);
        CP_COMMIT();

        uint32_t sA = sbase + (s & 3)*GSTAGE;
        uint32_t sB = sA + 16384;
#pragma unroll
        for (int kk = 0; kk < 4; kk++) {
            uint32_t a[4][4];
#pragma unroll
            for (int mi = 0; mi < 4; mi++) {
                uint32_t ad = sA + rowA[mi]*128 + ((((kk << 1) | hiA) ^ swzA[mi]) << 4);
                LDSM4(a[mi], ad);
            }
            uint32_t b[2][4];
#pragma unroll
            for (int ni2 = 0; ni2 < 2; ni2++) {
                uint32_t ad = sB + rowB[ni2]*128 + ((((kk << 1) | hiB) ^ swzB[ni2]) << 4);
                LDSM4(b[ni2], ad);
            }
#pragma unroll
            for (int mi = 0; mi < 4; mi++)
#pragma unroll
                for (int ni = 0; ni < 4; ni++)
                    MMA16816(acc[mi][ni], a[mi], b[ni >> 1][(ni & 1)*2], b[ni >> 1][(ni & 1)*2 + 1]);
        }
    }

    /* epilogue: direct fp32 stores */
    const int g = lane >> 2, tg = lane & 3;
#pragma unroll
    for (int mi = 0; mi < 4; mi++) {
#pragma unroll
        for (int ni = 0; ni < 4; ni++) {
            int row = m0 + wm*64 + mi*16 + g;
            int col = n0 + wn*32 + ni*8 + (tg << 1);
            *(float2*)&C[(size_t)row*N + col]     = make_float2(acc[mi][ni][0], acc[mi][ni][1]);
            *(float2*)&C[(size_t)(row+8)*N + col] = make_float2(acc[mi][ni][2], acc[mi][ni][3]);
        }
    }
#undef ISSUE_STAGE
}

/* ---------------- ba = hidden @ W_ba : M=4096, K=2048, N=64 --------------- */
__global__ __launch_bounds__(256)
void ba_gemm(const float* __restrict__ A, const float* __restrict__ B) {
    int c = threadIdx.x & 63;
    int rl = threadIdx.x >> 6;
    int row0 = blockIdx.x*16 + rl*4;
    float acc[4] = {0,0,0,0};
    for (int k = 0; k < 2048; k++) {
        float b = __ldg(&B[k*64 + c]);
#pragma unroll
        for (int r = 0; r < 4; r++)
            acc[r] += __ldg(&A[(size_t)(row0+r)*2048 + k]) * b;
    }
#pragma unroll
    for (int r = 0; r < 4; r++) g_ba[(size_t)(row0+r)*64 + c] = acc[r];
}

/* ---------------- depthwise causal conv (ksz=4) + SiLU -------------------- */
__global__ void conv_silu(const float* __restrict__ cw) {
    int idx = blockIdx.x*blockDim.x + threadIdx.x;
    if (idx >= SEQ*CONV_DIM) return;
    int s = idx >> 13;
    int c = idx & 8191;
    int col;
    if (c < 2048)      { int kh = c >> 7, d = c & 127;       col = kh*768 + d; }
    else if (c < 4096) { int c2 = c-2048; int kh = c2 >> 7;  col = kh*768 + 128 + (c2 & 127); }
    else               { int c2 = c-4096; int h16 = c2 >> 8; col = h16*768 + 256 + (c2 & 255); }
    float acc = 0.f;
#pragma unroll
    for (int j = 0; j < 4; j++) {
        int t = s - 3 + j;
        if (t >= 0) acc += g_qkvz[(size_t)t*QKVZ_N + col] * cw[j*CONV_DIM + c];
    }
    float r = acc / (1.f + expf(-acc));
    if (c < 2048)       g_qc[(size_t)s*2048 + c]        = r * QSCALE;
    else if (c < 4096)  g_kc[(size_t)s*2048 + (c-2048)] = r;
    else                g_vc[(size_t)s*4096 + (c-4096)] = r;
}

/* ---------------- beta, g, cumsum(g) within chunk ------------------------- */
__global__ void gates_kernel(const float* __restrict__ A_log,
                             const float* __restrict__ dt_bias) {
    int chunk = blockIdx.x, hv = blockIdx.y, t = threadIdx.x;
    int s = chunk*CHUNK + t;
    int base = ((hv >> 1) << 2) + (hv & 1);
    float bg = g_ba[(size_t)s*64 + base];
    float ag = g_ba[(size_t)s*64 + base + 2];
    g_beta[hv*SEQ + s] = 1.f / (1.f + expf(-bg));
    float x = ag + dt_bias[hv];
    float sp = (x > 20.f) ? x : log1pf(expf(x));
    float g = -expf(A_log[hv]) * sp;
    __shared__ float sh[64];
    sh[t] = g;
    __syncthreads();
    for (int off = 1; off < 64; off <<= 1) {
        float v = (t >= off) ? sh[t-off] : 0.f;
        __syncthreads();
        sh[t] += v;
        __syncthreads();
    }
    g_gcum[hv*SEQ + s] = sh[t];
}

/* ------------- per (head, chunk) parallel precompute ---------------------- */
__global__ __launch_bounds__(256)
void precompute_kernel() {
    float* sm    = (float*)dynsm;
    float* ks    = sm;
    float* vs    = ks + 64*129;
    float* Ls    = vs + 64*129;
    float* Xs    = Ls + 4096;
    float* betas = Xs + 4096;
    float* gcs   = betas + 64;
    float* bgm   = gcs + 64;
    const int c = blockIdx.x, hv = blockIdx.y, kh = hv >> 1;
    const int tid = threadIdx.x;

    for (int l = tid; l < 2048; l += 256) {
        int row = l >> 5, c4 = (l & 31) << 2;
        float4 v = *(const float4*)&g_kc[(size_t)(c*CHUNK+row)*2048 + kh*128 + c4];
        float* p = &ks[row*129 + c4];
        p[0]=v.x; p[1]=v.y; p[2]=v.z; p[3]=v.w;
    }
    if (tid < 64) {
        int s = c*CHUNK + tid;
        betas[tid] = g_beta[hv*SEQ + s];
        gcs[tid]   = g_gcum[hv*SEQ + s];
    }
    __syncthreads();
    if (tid < 64) bgm[tid] = betas[tid]*expf(gcs[tid]);

    for (int idx = tid; idx < 4096; idx += 256) {
        int i = idx >> 6, j = idx & 63;
        float val = 0.f;
        if (i > j) {
            float dot = 0.f;
#pragma unroll 8
            for (int d = 0; d < 128; d++) dot += ks[i*129+d]*ks[j*129+d];
            val = -betas[i]*dot*expf(gcs[i]-gcs[j]);
        }
        Ls[idx] = val;
    }
    __syncthreads();

    for (int l = tid; l < 2048; l += 256) {
        int row = l >> 5, c4 = (l & 31) << 2;
        float4 v = *(const float4*)&g_qc[(size_t)(c*CHUNK+row)*2048 + kh*128 + c4];
        float* p = &vs[row*129 + c4];
        p[0]=v.x; p[1]=v.y; p[2]=v.z; p[3]=v.w;
    }
    if (tid < 64) {
        int j = tid;
        for (int i = 0; i < 64; i++) {
            float acc = (i == j) ? 1.f : 0.f;
            for (int m = 0; m < i; m++) acc += Ls[i*64+m]*Xs[m*64+j];
            Xs[i*64+j] = acc;
        }
    }
    __syncthreads();

    {
        size_t outb = (size_t)(hv*NC + c)*4096;
        for (int idx = tid; idx < 4096; idx += 256) {
            int i = idx >> 6, j = idx & 63;
            float val = 0.f;
            if (i >= j) {
                float dot = 0.f;
#pragma unroll 8
                for (int d = 0; d < 128; d++) dot += vs[i*129+d]*ks[j*129+d];
                val = dot*expf(gcs[i]-gcs[j]);
            }
            g_attnA[outb + idx] = val;
        }
    }
    __syncthreads();

    for (int l = tid; l < 2048; l += 256) {
        int row = l >> 5, c4 = (l & 31) << 2;
        float4 v = *(const float4*)&g_vc[(size_t)(c*CHUNK+row)*4096 + hv*128 + c4];
        float* p = &vs[row*129 + c4];
        p[0]=v.x; p[1]=v.y; p[2]=v.z; p[3]=v.w;
    }
    __syncthreads();

    size_t ob = (size_t)(hv*NC + c)*CHUNK*128;
    for (int idx = tid; idx < 8192; idx += 256) {
        int i = idx >> 7, d = idx & 127;
        float aK = 0.f, aV = 0.f;
        for (int m = 0; m <= i; m++) {
            float x = Xs[i*64+m];
            aK += x*bgm[m]  *ks[m*129+d];
            aV += x*betas[m]*vs[m*129+d];
        }
        g_kcd[ob + idx]    = aK;
        g_vintra[ob + idx] = aV;
    }
}

/* ------------- sequential inter-chunk scan -------------------------------- */
__global__ __launch_bounds__(256)
void scan_kernel() {
    float* sm    = (float*)dynsm;
    float* state = sm;
    float* qs    = state + 128*33;
    float* ksm   = qs + 8192;
    float* kcds  = ksm + 8192;
    float* as_   = kcds + 8192;
    float* vn    = as_ + 4096;
    float* gcs   = vn + 64*33;
    float* wexp  = gcs + 64;
    const int hv = blockIdx.y, j0 = blockIdx.x*32, kh = hv >> 1;
    const int tid = threadIdx.x, jj = tid & 31, ig = tid >> 5;

    for (int l = tid; l < 128*33; l += 256) state[l] = 0.f;
    __syncthreads();

    for (int c = 0; c < NC; c++) {
        const size_t rb = (size_t)(hv*NC + c)*CHUNK;
        for (int l = tid; l < 2048; l += 256) {
            int row = l >> 5, c4 = (l & 31) << 2;
            *(float4*)&qs[row*128 + c4]   = *(const float4*)&g_qc[(size_t)(c*CHUNK+row)*2048 + kh*128 + c4];
            *(float4*)&ksm[row*128 + c4]  = *(const float4*)&g_kc[(size_t)(c*CHUNK+row)*2048 + kh*128 + c4];
            *(float4*)&kcds[row*128 + c4] = *(const float4*)&g_kcd[rb*128 + (size_t)l*4];
        }
        for (int l = tid; l < 1024; l += 256)
            *(float4*)&as_[l*4] = *(const float4*)&g_attnA[rb*64 + (size_t)l*4];
        for (int l = tid; l < 2048; l += 256) {
            int i = l >> 5, j = l & 31;
            vn[i*33 + j] = g_vintra[(rb + i)*128 + j0 + j];
        }
        if (tid < 64) gcs[tid] = g_gcum[hv*SEQ + c*CHUNK + tid];
        __syncthreads();
        if (tid < 64) wexp[tid] = expf(gcs[63] - gcs[tid]);

        const int i0 = ig*8;
        float vacc[8], oacc[8];
#pragma unroll
        for (int r = 0; r < 8; r++) { vacc[r] = vn[(i0+r)*33 + jj]; oacc[r] = 0.f; }
        for (int d = 0; d < 128; d++) {
            float sd = state[d*33 + jj];
#pragma unroll
            for (int r = 0; r < 8; r++) vacc[r] -= kcds[(i0+r)*128 + d]*sd;
#pragma unroll
            for (int r = 0; r < 8; r++) oacc[r] += qs[(i0+r)*128 + d]*sd;
        }
#pragma unroll
        for (int r = 0; r < 8; r++) oacc[r] *= expf(gcs[i0+r]);
#pragma unroll
        for (int r = 0; r < 8; r++) vn[(i0+r)*33 + jj] = vacc[r];
        __syncthreads();

#pragma unroll
        for (int r = 0; r < 8; r++) {
            float o = oacc[r];
            for (int m = 0; m < 64; m++) o += as_[(i0+r)*64 + m]*vn[m*33 + jj];
            g_core[(size_t)(c*CHUNK + i0 + r)*4096 + hv*128 + j0 + jj] = o;
        }

        {
            float eg = expf(gcs[63]);
            float sacc[16];
            const int d0 = ig*16;
#pragma unroll
            for (int dd = 0; dd < 16; dd++) sacc[dd] = state[(d0+dd)*33 + jj]*eg;
            for (int i = 0; i < 64; i++) {
                float vw = wexp[i]*vn[i*33 + jj];
#pragma unroll
                for (int dd = 0; dd < 16; dd++) sacc[dd] += ksm[i*128 + d0 + dd]*vw;
            }
#pragma unroll
            for (int dd = 0; dd < 16; dd++) state[(d0+dd)*33 + jj] = sacc[dd];
        }
        __syncthreads();
    }
}

/* ---------------- gated RMSNorm ------------------------------------------- */
__global__ void rmsnorm_kernel(const float* __restrict__ nw) {
    int gw = (blockIdx.x*blockDim.x + threadIdx.x) >> 5;
    int lane = threadIdx.x & 31;
    int s = gw >> 5;
    int hv = gw & 31;
    size_t zbase = (size_t)s*QKVZ_N + (hv >> 1)*768 + 512 + (hv & 1)*128;
    size_t cbase = (size_t)s*4096 + hv*128;
    float x[4];
    float ss = 0.f;
#pragma unroll
    for (int r = 0; r < 4; r++) {
        int d = lane + r*32;
        float cv = g_core[cbase + d];
        float zv = g_qkvz[zbase + d];
        float xv = cv * (zv / (1.f + expf(-zv)));
        x[r] = xv;
        ss += xv*xv;
    }
#pragma unroll
    for (int off = 16; off; off >>= 1) ss += __shfl_xor_sync(0xffffffffu, ss, off);
    float inv = rsqrtf(ss*(1.f/128.f) + 1e-6f);
#pragma unroll
    for (int r = 0; r < 4; r++) {
        int d = lane + r*32;
        g_xf[cbase + d] = x[r]*inv*nw[d];
    }
}

/* ---------------- launcher ------------------------------------------------ */
extern "C" void kernel_launch(void* const* d_in, const int* in_sizes, int n_in,
                              void* d_out, int out_size) {
    const float* hidden  = (const float*)d_in[0];
    const float* W_qkvz  = (const float*)d_in[1];
    const float* W_ba    = (const float*)d_in[2];
    const float* convk   = (const float*)d_in[3];
    const float* A_log   = (const float*)d_in[4];
    const float* dt_bias = (const float*)d_in[5];
    const float* normw   = (const float*)d_in[6];
    const float* W_out   = (const float*)d_in[7];
    float* out = (float*)d_out;

    float *qkvz_p, *xf_p;
    __nv_bfloat16 *A1, *B1, *A2, *B2;
    cudaGetSymbolAddress((void**)&qkvz_p, g_qkvz);
    cudaGetSymbolAddress((void**)&xf_p, g_xf);
    cudaGetSymbolAddress((void**)&A1, g_A1);
    cudaGetSymbolAddress((void**)&B1, g_B1);
    cudaGetSymbolAddress((void**)&A2, g_A2);
    cudaGetSymbolAddress((void**)&B2, g_B2);

    cudaFuncSetAttribute(precompute_kernel,
                         cudaFuncAttributeMaxDynamicSharedMemorySize, 99584);
    cudaFuncSetAttribute(scan_kernel,
                         cudaFuncAttributeMaxDynamicSharedMemorySize, 140544);
    cudaFuncSetAttribute(gemm_mma,
                         cudaFuncAttributeMaxDynamicSharedMemorySize, 4*GSTAGE);

    /* conversions for GEMM1 + static W_out for GEMM2 */
    cvtA<<<(SEQ*EMB)/256, 256>>>(hidden, A1, 11);              /* K=2048 */
    cvtBt<<<dim3(EMB/32, QKVZ_N/32), dim3(32,8)>>>(W_qkvz, B1, EMB, QKVZ_N);
    cvtBt<<<dim3(4096/32, EMB/32), dim3(32,8)>>>(W_out, B2, 4096, EMB);

    /* 1. qkvz = hidden @ W_qkvz  (bf16x3 mma.sync, K'=6144) */
    gemm_mma<<<dim3(QKVZ_N/128, SEQ/128), 256, 4*GSTAGE>>>(A1, B1, qkvz_p, 3*EMB, QKVZ_N);
    /* 2. ba */
    ba_gemm<<<256, 256>>>(hidden, W_ba);
    /* 3. conv + silu */
    conv_silu<<<(SEQ*CONV_DIM)/256, 256>>>(convk);
    /* 4. gates */
    gates_kernel<<<dim3(NC, NVH), 64>>>(A_log, dt_bias);
    /* 5. precompute */
    precompute_kernel<<<dim3(NC, NVH), 256, 99584>>>();
    /* 6. scan */
    scan_kernel<<<dim3(4, NVH), 256, 140544>>>();
    /* 7. rmsnorm */
    rmsnorm_kernel<<<(SEQ*NVH)/8, 256>>>(normw);
    /* 8. out = xf @ W_out  (bf16x3 mma.sync, K'=12288) */
    cvtA<<<(SEQ*4096)/256, 256>>>(xf_p, A2, 12);               /* K=4096 */
    gemm_mma<<<dim3(EMB/128, SEQ/128), 256, 4*GSTAGE>>>(A2, B2, out, 3*4096, EMB);
}

// round 8
// speedup vs baseline: 1.9152x; 1.0766x over previous
#include <cuda_runtime.h>
#include <cuda_bf16.h>
#include <math.h>
#include <stdint.h>

#define SEQ 4096
#define EMB 2048
#define NKH 16
#define NVH 32
#define DK 128
#define DV 128
#define CHUNK 64
#define NC (SEQ/CHUNK)      /* 64 */
#define QKVZ_N 12288
#define CONV_DIM 8192
#define QSCALE 0.08838834764831845f  /* 1/sqrt(128) */

/* single shared dynamic-smem symbol for all kernels */
extern __shared__ char dynsm[];

/* ---------------- scratch (device globals; no allocs allowed) ------------- */
__device__ float g_qkvz[(size_t)SEQ*QKVZ_N];            /* 192 MiB */
__device__ float g_ba[SEQ*64];
__device__ float g_qc[(size_t)SEQ*2048];
__device__ float g_kc[(size_t)SEQ*2048];
__device__ float g_vc[(size_t)SEQ*4096];
__device__ float g_beta[NVH*SEQ];
__device__ float g_gcum[NVH*SEQ];
__device__ float g_attnA[(size_t)NVH*NC*CHUNK*CHUNK];
__device__ float g_vintra[(size_t)NVH*SEQ*DV];
__device__ float g_kcd[(size_t)NVH*SEQ*DK];
__device__ float g_core[(size_t)SEQ*NVH*DV];

/* split-bf16 extended-K operands: A'=[Ah|Ah|Al] (MxK'), B'^T=[Bh|Bl|Bh] (NxK') */
__device__ __nv_bfloat16 g_A1[(size_t)SEQ*3*EMB];        /* 4096 x 6144  */
__device__ __nv_bfloat16 g_B1[(size_t)QKVZ_N*3*EMB];     /* 12288 x 6144 */
__device__ __nv_bfloat16 g_A2[(size_t)SEQ*3*4096];       /* 4096 x 12288 */
__device__ __nv_bfloat16 g_B2[(size_t)EMB*3*4096];       /* 2048 x 12288 */

/* ======================= asm helpers (sm_80+ safe) ======================= */
__device__ __forceinline__ uint32_t smem_u32(const void* p) {
    uint32_t a;
    asm("{ .reg .u64 t; cvta.to.shared.u64 t, %1; cvt.u32.u64 %0, t; }" : "=r"(a) : "l"(p));
    return a;
}
#define CP_ASYNC16(sa, ga) \
    asm volatile("cp.async.cg.shared.global [%0], [%1], 16;" :: "r"(sa), "l"(ga))
#define CP_COMMIT() asm volatile("cp.async.commit_group;")
#define CP_WAIT2()  asm volatile("cp.async.wait_group 2;")
#define LDSM4(R, ad) \
    asm volatile("ldmatrix.sync.aligned.m8n8.x4.shared.b16 {%0,%1,%2,%3}, [%4];" \
        : "=r"((R)[0]), "=r"((R)[1]), "=r"((R)[2]), "=r"((R)[3]) : "r"(ad))
#define MMA16816(c, a, b0, b1) \
    asm volatile("mma.sync.aligned.m16n8k16.row.col.f32.bf16.bf16.f32 " \
        "{%0,%1,%2,%3}, {%4,%5,%6,%7}, {%8,%9}, {%0,%1,%2,%3};" \
        : "+f"((c)[0]), "+f"((c)[1]), "+f"((c)[2]), "+f"((c)[3]) \
        : "r"((a)[0]), "r"((a)[1]), "r"((a)[2]), "r"((a)[3]), "r"(b0), "r"(b1))

__device__ __forceinline__ __nv_bfloat162 split_hi2(float a, float b,
                                                    float& la, float& lb) {
    __nv_bfloat16 ha = __float2bfloat16(a), hb = __float2bfloat16(b);
    la = a - __bfloat162float(ha);
    lb = b - __bfloat162float(hb);
    return __halves2bfloat162(ha, hb);
}

/* ======================= split-bf16 conversions ========================== */
/* A[M][K] fp32 -> A'[M][3K] bf16 = [hi | hi | lo]; 2 elems/thread */
__global__ void cvtA(const float* __restrict__ src, __nv_bfloat16* __restrict__ dst,
                     int kbits) {
    size_t idx = ((size_t)blockIdx.x*256 + threadIdx.x)*2;
    int K = 1 << kbits;
    int m = (int)(idx >> kbits), k = (int)(idx & (K - 1));
    float2 v = *(const float2*)&src[idx];
    float l0, l1;
    __nv_bfloat162 hh = split_hi2(v.x, v.y, l0, l1);
    __nv_bfloat162 ll = __halves2bfloat162(__float2bfloat16(l0), __float2bfloat16(l1));
    size_t base = (((size_t)m*3) << kbits) + k;
    *(__nv_bfloat162*)&dst[base]       = hh;
    *(__nv_bfloat162*)&dst[base + K]   = hh;
    *(__nv_bfloat162*)&dst[base + 2*K] = ll;
}
/* W[K][N] fp32 -> B'[N][3K] bf16 = [hi | lo | hi] (transposed).
   64k x 32n tile; warp-per-4-n-rows, lanes = consecutive k pairs -> coalesced. */
__global__ __launch_bounds__(256)
void cvtBt(const float* __restrict__ W, __nv_bfloat16* __restrict__ dst,
           int K, int N) {
    __shared__ float t[64][33];
    int k0 = blockIdx.x*64, n0 = blockIdx.y*32;
    int tid = threadIdx.x;
    int tx = tid & 31, tw = tid >> 5;
#pragma unroll
    for (int i = 0; i < 8; i++) {
        int row = tw + i*8;
        t[row][tx] = W[(size_t)(k0+row)*N + n0 + tx];
    }
    __syncthreads();
#pragma unroll
    for (int i = 0; i < 4; i++) {
        int nc = tw*4 + i;
        float v0 = t[tx*2][nc];
        float v1 = t[tx*2+1][nc];
        float l0, l1;
        __nv_bfloat162 hh = split_hi2(v0, v1, l0, l1);
        __nv_bfloat162 ll = __halves2bfloat162(__float2bfloat16(l0), __float2bfloat16(l1));
        size_t base = (size_t)(n0 + nc)*3*K + k0 + tx*2;
        *(__nv_bfloat162*)&dst[base]       = hh;
        *(__nv_bfloat162*)&dst[base + K]   = ll;
        *(__nv_bfloat162*)&dst[base + 2*K] = hh;
    }
}

/* ======================= bf16 mma.sync GEMM (unchanged) ================== */
#define GSTAGE 32768
__global__ __launch_bounds__(256, 1)
void gemm_mma(const __nv_bfloat16* __restrict__ A, const __nv_bfloat16* __restrict__ B,
              float* __restrict__ C, int Kp, int N) {
    const int tid = threadIdx.x, lane = tid & 31, wid = tid >> 5;
    const int wm = wid & 1, wn = wid >> 1;
    const int m0 = blockIdx.y*128, n0 = blockIdx.x*128;
    const uint32_t sbase = smem_u32(dynsm);
    const int S = Kp >> 6;

    float acc[4][4][4];
#pragma unroll
    for (int mi = 0; mi < 4; mi++)
#pragma unroll
        for (int ni = 0; ni < 4; ni++)
#pragma unroll
            for (int e = 0; e < 4; e++) acc[mi][ni][e] = 0.f;

    int cr[4], cc[4];
    uint32_t sOffA[4];
#pragma unroll
    for (int i = 0; i < 4; i++) {
        int id = tid + (i << 8);
        cr[i] = id >> 3; cc[i] = id & 7;
        sOffA[i] = cr[i]*128 + ((cc[i] ^ (cr[i] & 7)) << 4);
    }

#define ISSUE_STAGE(t) do {                                                   \
        uint32_t stb = sbase + ((t) & 3)*GSTAGE;                              \
        _Pragma("unroll")                                                     \
        for (int i = 0; i < 4; i++) {                                         \
            const __nv_bfloat16* g = A + (size_t)(m0 + cr[i])*Kp + (t)*64 + (cc[i] << 3); \
            CP_ASYNC16(stb + sOffA[i], g);                                    \
        }                                                                     \
        _Pragma("unroll")                                                     \
        for (int i = 0; i < 4; i++) {                                         \
            const __nv_bfloat16* g = B + (size_t)(n0 + cr[i])*Kp + (t)*64 + (cc[i] << 3); \
            CP_ASYNC16(stb + 16384 + sOffA[i], g);                            \
        }                                                                     \
    } while (0)

    ISSUE_STAGE(0); CP_COMMIT();
    ISSUE_STAGE(1); CP_COMMIT();
    ISSUE_STAGE(2); CP_COMMIT();

    int rowA[4], swzA[4], rowB[2], swzB[2];
#pragma unroll
    for (int mi = 0; mi < 4; mi++) {
        rowA[mi] = wm*64 + mi*16 + (lane & 15);
        swzA[mi] = rowA[mi] & 7;
    }
#pragma unroll
    for (int ni2 = 0; ni2 < 2; ni2++) {
        rowB[ni2] = wn*32 + ni2*16 + ((lane >> 4) << 3) + (lane & 7);
        swzB[ni2] = rowB[ni2] & 7;
    }
    const int hiA = lane >> 4;
    const int hiB = (lane >> 3) & 1;

    for (int s = 0; s < S; s++) {
        CP_WAIT2();
        __syncthreads();
        if (s + 3 < S) ISSUE_STAGE(s + 3);
        CP_COMMIT();

        uint32_t sA = sbase + (s & 3)*GSTAGE;
        uint32_t sB = sA + 16384;
#pragma unroll
        for (int kk = 0; kk < 4; kk++) {
            uint32_t a[4][4];
#pragma unroll
            for (int mi = 0; mi < 4; mi++) {
                uint32_t ad = sA + rowA[mi]*128 + ((((kk << 1) | hiA) ^ swzA[mi]) << 4);
                LDSM4(a[mi], ad);
            }
            uint32_t b[2][4];
#pragma unroll
            for (int ni2 = 0; ni2 < 2; ni2++) {
                uint32_t ad = sB + rowB[ni2]*128 + ((((kk << 1) | hiB) ^ swzB[ni2]) << 4);
                LDSM4(b[ni2], ad);
            }
#pragma unroll
            for (int mi = 0; mi < 4; mi++)
#pragma unroll
                for (int ni = 0; ni < 4; ni++)
                    MMA16816(acc[mi][ni], a[mi], b[ni >> 1][(ni & 1)*2], b[ni >> 1][(ni & 1)*2 + 1]);
        }
    }

    const int g = lane >> 2, tg = lane & 3;
#pragma unroll
    for (int mi = 0; mi < 4; mi++) {
#pragma unroll
        for (int ni = 0; ni < 4; ni++) {
            int row = m0 + wm*64 + mi*16 + g;
            int col = n0 + wn*32 + ni*8 + (tg << 1);
            *(float2*)&C[(size_t)row*N + col]     = make_float2(acc[mi][ni][0], acc[mi][ni][1]);
            *(float2*)&C[(size_t)(row+8)*N + col] = make_float2(acc[mi][ni][2], acc[mi][ni][3]);
        }
    }
#undef ISSUE_STAGE
}

/* ---------------- ba = hidden @ W_ba : M=4096, K=2048, N=64 --------------- */
__global__ __launch_bounds__(256)
void ba_gemm(const float* __restrict__ A, const float* __restrict__ B) {
    int c = threadIdx.x & 63;
    int rl = threadIdx.x >> 6;
    int row0 = blockIdx.x*16 + rl*4;
    float acc[4] = {0,0,0,0};
    for (int k = 0; k < 2048; k++) {
        float b = __ldg(&B[k*64 + c]);
#pragma unroll
        for (int r = 0; r < 4; r++)
            acc[r] += __ldg(&A[(size_t)(row0+r)*2048 + k]) * b;
    }
#pragma unroll
    for (int r = 0; r < 4; r++) g_ba[(size_t)(row0+r)*64 + c] = acc[r];
}

/* ---------------- depthwise causal conv (ksz=4) + SiLU -------------------- */
__global__ void conv_silu(const float* __restrict__ cw) {
    int idx = blockIdx.x*blockDim.x + threadIdx.x;
    if (idx >= SEQ*CONV_DIM) return;
    int s = idx >> 13;
    int c = idx & 8191;
    int col;
    if (c < 2048)      { int kh = c >> 7, d = c & 127;       col = kh*768 + d; }
    else if (c < 4096) { int c2 = c-2048; int kh = c2 >> 7;  col = kh*768 + 128 + (c2 & 127); }
    else               { int c2 = c-4096; int h16 = c2 >> 8; col = h16*768 + 256 + (c2 & 255); }
    float acc = 0.f;
#pragma unroll
    for (int j = 0; j < 4; j++) {
        int t = s - 3 + j;
        if (t >= 0) acc += g_qkvz[(size_t)t*QKVZ_N + col] * cw[j*CONV_DIM + c];
    }
    float r = acc / (1.f + expf(-acc));
    if (c < 2048)       g_qc[(size_t)s*2048 + c]        = r * QSCALE;
    else if (c < 4096)  g_kc[(size_t)s*2048 + (c-2048)] = r;
    else                g_vc[(size_t)s*4096 + (c-4096)] = r;
}

/* ---------------- beta, g, cumsum(g) within chunk ------------------------- */
__global__ void gates_kernel(const float* __restrict__ A_log,
                             const float* __restrict__ dt_bias) {
    int chunk = blockIdx.x, hv = blockIdx.y, t = threadIdx.x;
    int s = chunk*CHUNK + t;
    int base = ((hv >> 1) << 2) + (hv & 1);
    float bg = g_ba[(size_t)s*64 + base];
    float ag = g_ba[(size_t)s*64 + base + 2];
    g_beta[hv*SEQ + s] = 1.f / (1.f + expf(-bg));
    float x = ag + dt_bias[hv];
    float sp = (x > 20.f) ? x : log1pf(expf(x));
    float g = -expf(A_log[hv]) * sp;
    __shared__ float sh[64];
    sh[t] = g;
    __syncthreads();
    for (int off = 1; off < 64; off <<= 1) {
        float v = (t >= off) ? sh[t-off] : 0.f;
        __syncthreads();
        sh[t] += v;
        __syncthreads();
    }
    g_gcum[hv*SEQ + s] = sh[t];
}

/* ------------- per (head, chunk) parallel precompute ----------------------
   Register-tiled: L/attnA 4x4 tiles; kcd/vintra 8x4 tiles; 2 blocks/SM.    */
__global__ __launch_bounds__(256, 2)
void precompute_kernel() {
    float* sm    = (float*)dynsm;
    float* ks    = sm;              /* 64*129 */
    float* vs    = ks + 64*129;     /* q, then v */
    float* Ls    = vs + 64*129;     /* 4096 */
    float* Xs    = Ls + 4096;       /* 4096 */
    float* betas = Xs + 4096;
    float* gcs   = betas + 64;
    float* bgm   = gcs + 64;
    const int c = blockIdx.x, hv = blockIdx.y, kh = hv >> 1;
    const int tid = threadIdx.x;
    const int ti = tid >> 4, tj = tid & 15;       /* 16x16 tile grid of 4x4 */

    for (int l = tid; l < 2048; l += 256) {
        int row = l >> 5, c4 = (l & 31) << 2;
        float4 v = *(const float4*)&g_kc[(size_t)(c*CHUNK+row)*2048 + kh*128 + c4];
        float* p = &ks[row*129 + c4];
        p[0]=v.x; p[1]=v.y; p[2]=v.z; p[3]=v.w;
    }
    if (tid < 64) {
        int s = c*CHUNK + tid;
        betas[tid] = g_beta[hv*SEQ + s];
        gcs[tid]   = g_gcum[hv*SEQ + s];
    }
    __syncthreads();
    if (tid < 64) bgm[tid] = betas[tid]*expf(gcs[tid]);

    /* L: 4x4 register tile per thread */
    {
        float acc[4][4];
#pragma unroll
        for (int r = 0; r < 4; r++)
#pragma unroll
            for (int q = 0; q < 4; q++) acc[r][q] = 0.f;
        for (int d = 0; d < 128; d++) {
            float a[4], b[4];
#pragma unroll
            for (int r = 0; r < 4; r++) a[r] = ks[(ti*4+r)*129 + d];
#pragma unroll
            for (int q = 0; q < 4; q++) b[q] = ks[(tj*4+q)*129 + d];
#pragma unroll
            for (int r = 0; r < 4; r++)
#pragma unroll
                for (int q = 0; q < 4; q++) acc[r][q] += a[r]*b[q];
        }
#pragma unroll
        for (int r = 0; r < 4; r++) {
            int i = ti*4 + r;
#pragma unroll
            for (int q = 0; q < 4; q++) {
                int j = tj*4 + q;
                Ls[i*64 + j] = (i > j) ? -betas[i]*acc[r][q]*expf(gcs[i]-gcs[j]) : 0.f;
            }
        }
    }
    __syncthreads();

    /* load q into vs; fwd substitution on 64 threads (columns independent) */
    for (int l = tid; l < 2048; l += 256) {
        int row = l >> 5, c4 = (l & 31) << 2;
        float4 v = *(const float4*)&g_qc[(size_t)(c*CHUNK+row)*2048 + kh*128 + c4];
        float* p = &vs[row*129 + c4];
        p[0]=v.x; p[1]=v.y; p[2]=v.z; p[3]=v.w;
    }
    if (tid < 64) {
        int j = tid;
        for (int i = 0; i < 64; i++) {
            float acc = (i == j) ? 1.f : 0.f;
            for (int m = 0; m < i; m++) acc += Ls[i*64+m]*Xs[m*64+j];
            Xs[i*64+j] = acc;   /* full matrix written; zeros for i<j */
        }
    }
    __syncthreads();

    /* attnA: q_i . k_j, 4x4 tiles */
    {
        float acc[4][4];
#pragma unroll
        for (int r = 0; r < 4; r++)
#pragma unroll
            for (int q = 0; q < 4; q++) acc[r][q] = 0.f;
        for (int d = 0; d < 128; d++) {
            float a[4], b[4];
#pragma unroll
            for (int r = 0; r < 4; r++) a[r] = vs[(ti*4+r)*129 + d];
#pragma unroll
            for (int q = 0; q < 4; q++) b[q] = ks[(tj*4+q)*129 + d];
#pragma unroll
            for (int r = 0; r < 4; r++)
#pragma unroll
                for (int q = 0; q < 4; q++) acc[r][q] += a[r]*b[q];
        }
        size_t outb = (size_t)(hv*NC + c)*4096;
#pragma unroll
        for (int r = 0; r < 4; r++) {
            int i = ti*4 + r;
#pragma unroll
            for (int q = 0; q < 4; q++) {
                int j = tj*4 + q;
                g_attnA[outb + i*64 + j] = (i >= j) ? acc[r][q]*expf(gcs[i]-gcs[j]) : 0.f;
            }
        }
    }
    __syncthreads();

    /* overwrite vs with v chunk */
    for (int l = tid; l < 2048; l += 256) {
        int row = l >> 5, c4 = (l & 31) << 2;
        float4 v = *(const float4*)&g_vc[(size_t)(c*CHUNK+row)*4096 + hv*128 + c4];
        float* p = &vs[row*129 + c4];
        p[0]=v.x; p[1]=v.y; p[2]=v.z; p[3]=v.w;
    }
    __syncthreads();

    /* kcd = X @ (k*beta*e^gc), v_intra = X @ (v*beta); 8 rows x 4 cols/thread
       lane-major d mapping: d = lane + 32*cc (conflict-free LDS, coalesced STG) */
    {
        const int iq = tid >> 5;      /* warp id 0..7 -> i0 = iq*8 */
        const int ln = tid & 31;
        const int i0 = iq*8;
        float aK[8][4], aV[8][4];
#pragma unroll
        for (int r = 0; r < 8; r++)
#pragma unroll
            for (int q = 0; q < 4; q++) { aK[r][q] = 0.f; aV[r][q] = 0.f; }
        for (int m = 0; m < 64; m++) {
            float bg = bgm[m], bt = betas[m];
            float kk[4], vv[4];
#pragma unroll
            for (int q = 0; q < 4; q++) {
                kk[q] = ks[m*129 + ln + 32*q];
                vv[q] = vs[m*129 + ln + 32*q];
            }
#pragma unroll
            for (int r = 0; r < 8; r++) {
                float x  = Xs[(i0+r)*64 + m];
                float xb = x*bg, xv = x*bt;
#pragma unroll
                for (int q = 0; q < 4; q++) {
                    aK[r][q] += xb*kk[q];
                    aV[r][q] += xv*vv[q];
                }
            }
        }
        size_t ob = (size_t)(hv*NC + c)*CHUNK*128;
#pragma unroll
        for (int r = 0; r < 8; r++)
#pragma unroll
            for (int q = 0; q < 4; q++) {
                size_t o = ob + (size_t)(i0+r)*128 + ln + 32*q;
                g_kcd[o]    = aK[r][q];
                g_vintra[o] = aV[r][q];
            }
    }
}

/* ------------- sequential inter-chunk scan (unchanged) -------------------- */
__global__ __launch_bounds__(256)
void scan_kernel() {
    float* sm    = (float*)dynsm;
    float* state = sm;
    float* qs    = state + 128*33;
    float* ksm   = qs + 8192;
    float* kcds  = ksm + 8192;
    float* as_   = kcds + 8192;
    float* vn    = as_ + 4096;
    float* gcs   = vn + 64*33;
    float* wexp  = gcs + 64;
    const int hv = blockIdx.y, j0 = blockIdx.x*32, kh = hv >> 1;
    const int tid = threadIdx.x, jj = tid & 31, ig = tid >> 5;

    for (int l = tid; l < 128*33; l += 256) state[l] = 0.f;
    __syncthreads();

    for (int c = 0; c < NC; c++) {
        const size_t rb = (size_t)(hv*NC + c)*CHUNK;
        for (int l = tid; l < 2048; l += 256) {
            int row = l >> 5, c4 = (l & 31) << 2;
            *(float4*)&qs[row*128 + c4]   = *(const float4*)&g_qc[(size_t)(c*CHUNK+row)*2048 + kh*128 + c4];
            *(float4*)&ksm[row*128 + c4]  = *(const float4*)&g_kc[(size_t)(c*CHUNK+row)*2048 + kh*128 + c4];
            *(float4*)&kcds[row*128 + c4] = *(const float4*)&g_kcd[rb*128 + (size_t)l*4];
        }
        for (int l = tid; l < 1024; l += 256)
            *(float4*)&as_[l*4] = *(const float4*)&g_attnA[rb*64 + (size_t)l*4];
        for (int l = tid; l < 2048; l += 256) {
            int i = l >> 5, j = l & 31;
            vn[i*33 + j] = g_vintra[(rb + i)*128 + j0 + j];
        }
        if (tid < 64) gcs[tid] = g_gcum[hv*SEQ + c*CHUNK + tid];
        __syncthreads();
        if (tid < 64) wexp[tid] = expf(gcs[63] - gcs[tid]);

        const int i0 = ig*8;
        float vacc[8], oacc[8];
#pragma unroll
        for (int r = 0; r < 8; r++) { vacc[r] = vn[(i0+r)*33 + jj]; oacc[r] = 0.f; }
        for (int d = 0; d < 128; d++) {
            float sd = state[d*33 + jj];
#pragma unroll
            for (int r = 0; r < 8; r++) vacc[r] -= kcds[(i0+r)*128 + d]*sd;
#pragma unroll
            for (int r = 0; r < 8; r++) oacc[r] += qs[(i0+r)*128 + d]*sd;
        }
#pragma unroll
        for (int r = 0; r < 8; r++) oacc[r] *= expf(gcs[i0+r]);
#pragma unroll
        for (int r = 0; r < 8; r++) vn[(i0+r)*33 + jj] = vacc[r];
        __syncthreads();

#pragma unroll
        for (int r = 0; r < 8; r++) {
            float o = oacc[r];
            for (int m = 0; m < 64; m++) o += as_[(i0+r)*64 + m]*vn[m*33 + jj];
            g_core[(size_t)(c*CHUNK + i0 + r)*4096 + hv*128 + j0 + jj] = o;
        }

        {
            float eg = expf(gcs[63]);
            float sacc[16];
            const int d0 = ig*16;
#pragma unroll
            for (int dd = 0; dd < 16; dd++) sacc[dd] = state[(d0+dd)*33 + jj]*eg;
            for (int i = 0; i < 64; i++) {
                float vw = wexp[i]*vn[i*33 + jj];
#pragma unroll
                for (int dd = 0; dd < 16; dd++) sacc[dd] += ksm[i*128 + d0 + dd]*vw;
            }
#pragma unroll
            for (int dd = 0; dd < 16; dd++) state[(d0+dd)*33 + jj] = sacc[dd];
        }
        __syncthreads();
    }
}

/* ------- gated RMSNorm fused with split-bf16 A2 emission ------------------ */
__global__ void rmsnorm_kernel(const float* __restrict__ nw) {
    int gw = (blockIdx.x*blockDim.x + threadIdx.x) >> 5;
    int lane = threadIdx.x & 31;
    int s = gw >> 5;
    int hv = gw & 31;
    int d0 = lane*4;
    size_t zbase = (size_t)s*QKVZ_N + (hv >> 1)*768 + 512 + (hv & 1)*128 + d0;
    size_t cbase = (size_t)s*4096 + hv*128 + d0;
    float4 cv = *(const float4*)&g_core[cbase];
    float4 zv = *(const float4*)&g_qkvz[zbase];
    float x[4];
    x[0] = cv.x * (zv.x / (1.f + expf(-zv.x)));
    x[1] = cv.y * (zv.y / (1.f + expf(-zv.y)));
    x[2] = cv.z * (zv.z / (1.f + expf(-zv.z)));
    x[3] = cv.w * (zv.w / (1.f + expf(-zv.w)));
    float ss = x[0]*x[0] + x[1]*x[1] + x[2]*x[2] + x[3]*x[3];
#pragma unroll
    for (int off = 16; off; off >>= 1) ss += __shfl_xor_sync(0xffffffffu, ss, off);
    float inv = rsqrtf(ss*(1.f/128.f) + 1e-6f);
    float y[4];
#pragma unroll
    for (int r = 0; r < 4; r++) y[r] = x[r]*inv*nw[d0 + r];
    /* emit split-bf16 A2 row: [hi | hi | lo], K=4096 */
    float l0, l1, l2, l3;
    __nv_bfloat162 h01 = split_hi2(y[0], y[1], l0, l1);
    __nv_bfloat162 h23 = split_hi2(y[2], y[3], l2, l3);
    __nv_bfloat162 l01 = __halves2bfloat162(__float2bfloat16(l0), __float2bfloat16(l1));
    __nv_bfloat162 l23 = __halves2bfloat162(__float2bfloat16(l2), __float2bfloat16(l3));
    size_t base = (size_t)s*12288 + hv*128 + d0;
    *(__nv_bfloat162*)&g_A2[base]          = h01;
    *(__nv_bfloat162*)&g_A2[base + 2]      = h23;
    *(__nv_bfloat162*)&g_A2[base + 4096]   = h01;
    *(__nv_bfloat162*)&g_A2[base + 4098]   = h23;
    *(__nv_bfloat162*)&g_A2[base + 8192]   = l01;
    *(__nv_bfloat162*)&g_A2[base + 8194]   = l23;
}

/* ---------------- launcher ------------------------------------------------ */
extern "C" void kernel_launch(void* const* d_in, const int* in_sizes, int n_in,
                              void* d_out, int out_size) {
    const float* hidden  = (const float*)d_in[0];
    const float* W_qkvz  = (const float*)d_in[1];
    const float* W_ba    = (const float*)d_in[2];
    const float* convk   = (const float*)d_in[3];
    const float* A_log   = (const float*)d_in[4];
    const float* dt_bias = (const float*)d_in[5];
    const float* normw   = (const float*)d_in[6];
    const float* W_out   = (const float*)d_in[7];
    float* out = (float*)d_out;

    float *qkvz_p;
    __nv_bfloat16 *A1, *B1, *A2, *B2;
    cudaGetSymbolAddress((void**)&qkvz_p, g_qkvz);
    cudaGetSymbolAddress((void**)&A1, g_A1);
    cudaGetSymbolAddress((void**)&B1, g_B1);
    cudaGetSymbolAddress((void**)&A2, g_A2);
    cudaGetSymbolAddress((void**)&B2, g_B2);

    cudaFuncSetAttribute(precompute_kernel,
                         cudaFuncAttributeMaxDynamicSharedMemorySize, 99584);
    cudaFuncSetAttribute(scan_kernel,
                         cudaFuncAttributeMaxDynamicSharedMemorySize, 140544);
    cudaFuncSetAttribute(gemm_mma,
                         cudaFuncAttributeMaxDynamicSharedMemorySize, 4*GSTAGE);

    /* conversions for GEMM1 + static W_out for GEMM2 */
    cvtA<<<(SEQ*EMB)/512, 256>>>(hidden, A1, 11);              /* K=2048 */
    cvtBt<<<dim3(EMB/64, QKVZ_N/32), 256>>>(W_qkvz, B1, EMB, QKVZ_N);
    cvtBt<<<dim3(4096/64, EMB/32), 256>>>(W_out, B2, 4096, EMB);

    /* 1. qkvz = hidden @ W_qkvz  (bf16x3 mma.sync, K'=6144) */
    gemm_mma<<<dim3(QKVZ_N/128, SEQ/128), 256, 4*GSTAGE>>>(A1, B1, qkvz_p, 3*EMB, QKVZ_N);
    /* 2. ba */
    ba_gemm<<<256, 256>>>(hidden, W_ba);
    /* 3. conv + silu */
    conv_silu<<<(SEQ*CONV_DIM)/256, 256>>>(convk);
    /* 4. gates */
    gates_kernel<<<dim3(NC, NVH), 64>>>(A_log, dt_bias);
    /* 5. precompute */
    precompute_kernel<<<dim3(NC, NVH), 256, 99584>>>();
    /* 6. scan */
    scan_kernel<<<dim3(4, NVH), 256, 140544>>>();
    /* 7. rmsnorm + A2 emission (fused) */
    rmsnorm_kernel<<<(SEQ*NVH)/8, 256>>>(normw);
    /* 8. out = xf @ W_out  (bf16x3 mma.sync, K'=12288) */
    gemm_mma<<<dim3(EMB/128, SEQ/128), 256, 4*GSTAGE>>>(A2, B2, out, 3*4096, EMB);
}

// round 9
// speedup vs baseline: 2.0994x; 1.0962x over previous
#include <cuda_runtime.h>
#include <cuda_bf16.h>
#include <math.h>
#include <stdint.h>

#define SEQ 4096
#define EMB 2048
#define NKH 16
#define NVH 32
#define DK 128
#define DV 128
#define CHUNK 64
#define NC (SEQ/CHUNK)      /* 64 */
#define QKVZ_N 12288
#define CONV_DIM 8192
#define QSCALE 0.08838834764831845f  /* 1/sqrt(128) */

/* single shared dynamic-smem symbol for all kernels */
extern __shared__ char dynsm[];

/* ---------------- scratch (device globals; no allocs allowed) ------------- */
__device__ float g_qkvz[(size_t)SEQ*QKVZ_N];            /* 192 MiB */
__device__ float g_ba[SEQ*64];
__device__ float g_qc[(size_t)SEQ*2048];
__device__ float g_kc[(size_t)SEQ*2048];
__device__ float g_vc[(size_t)SEQ*4096];
__device__ float g_beta[NVH*SEQ];
__device__ float g_gcum[NVH*SEQ];
__device__ float g_attnA[(size_t)NVH*NC*CHUNK*CHUNK];
__device__ float g_vintra[(size_t)NVH*SEQ*DV];
__device__ float g_kcd[(size_t)NVH*SEQ*DK];
__device__ float g_core[(size_t)SEQ*NVH*DV];

/* split-bf16 extended-K operands: A'=[Ah|Ah|Al] (MxK'), B'^T=[Bh|Bl|Bh] (NxK') */
__device__ __nv_bfloat16 g_A1[(size_t)SEQ*3*EMB];        /* 4096 x 6144  */
__device__ __nv_bfloat16 g_B1[(size_t)QKVZ_N*3*EMB];     /* 12288 x 6144 */
__device__ __nv_bfloat16 g_A2[(size_t)SEQ*3*4096];       /* 4096 x 12288 */
__device__ __nv_bfloat16 g_B2[(size_t)EMB*3*4096];       /* 2048 x 12288 */

/* ======================= asm helpers ===================================== */
__device__ __forceinline__ uint32_t smem_u32(const void* p) {
    uint32_t a;
    asm("{ .reg .u64 t; cvta.to.shared.u64 t, %1; cvt.u32.u64 %0, t; }" : "=r"(a) : "l"(p));
    return a;
}
#define CP_ASYNC16(sa, ga) \
    asm volatile("cp.async.cg.shared.global [%0], [%1], 16;" :: "r"(sa), "l"(ga))
#define CP_COMMIT() asm volatile("cp.async.commit_group;")
#define CP_WAIT1()  asm volatile("cp.async.wait_group 1;")
#define LDSM4(R, ad) \
    asm volatile("ldmatrix.sync.aligned.m8n8.x4.shared.b16 {%0,%1,%2,%3}, [%4];" \
        : "=r"((R)[0]), "=r"((R)[1]), "=r"((R)[2]), "=r"((R)[3]) : "r"(ad))
#define MMA16816(c, a, b0, b1) \
    asm volatile("mma.sync.aligned.m16n8k16.row.col.f32.bf16.bf16.f32 " \
        "{%0,%1,%2,%3}, {%4,%5,%6,%7}, {%8,%9}, {%0,%1,%2,%3};" \
        : "+f"((c)[0]), "+f"((c)[1]), "+f"((c)[2]), "+f"((c)[3]) \
        : "r"((a)[0]), "r"((a)[1]), "r"((a)[2]), "r"((a)[3]), "r"(b0), "r"(b1))

/* packed f32x2 fma: c += a*b componentwise (Blackwell, base sm_100+ feature) */
__device__ __forceinline__ void ffma2(float2& c, float2 a, float2 b) {
    asm("fma.rn.f32x2 %0, %1, %2, %0;"
        : "+l"(*reinterpret_cast<unsigned long long*>(&c))
        : "l"(*reinterpret_cast<unsigned long long*>(&a)),
          "l"(*reinterpret_cast<unsigned long long*>(&b)));
}

__device__ __forceinline__ __nv_bfloat162 split_hi2(float a, float b,
                                                    float& la, float& lb) {
    __nv_bfloat16 ha = __float2bfloat16(a), hb = __float2bfloat16(b);
    la = a - __bfloat162float(ha);
    lb = b - __bfloat162float(hb);
    return __halves2bfloat162(ha, hb);
}

/* ======================= split-bf16 conversions ========================== */
__global__ void cvtA(const float* __restrict__ src, __nv_bfloat16* __restrict__ dst,
                     int kbits) {
    size_t idx = ((size_t)blockIdx.x*256 + threadIdx.x)*2;
    int K = 1 << kbits;
    int m = (int)(idx >> kbits), k = (int)(idx & (K - 1));
    float2 v = *(const float2*)&src[idx];
    float l0, l1;
    __nv_bfloat162 hh = split_hi2(v.x, v.y, l0, l1);
    __nv_bfloat162 ll = __halves2bfloat162(__float2bfloat16(l0), __float2bfloat16(l1));
    size_t base = (((size_t)m*3) << kbits) + k;
    *(__nv_bfloat162*)&dst[base]       = hh;
    *(__nv_bfloat162*)&dst[base + K]   = hh;
    *(__nv_bfloat162*)&dst[base + 2*K] = ll;
}
__global__ __launch_bounds__(256)
void cvtBt(const float* __restrict__ W, __nv_bfloat16* __restrict__ dst,
           int K, int N) {
    __shared__ float t[64][33];
    int k0 = blockIdx.x*64, n0 = blockIdx.y*32;
    int tid = threadIdx.x;
    int tx = tid & 31, tw = tid >> 5;
#pragma unroll
    for (int i = 0; i < 8; i++) {
        int row = tw + i*8;
        t[row][tx] = W[(size_t)(k0+row)*N + n0 + tx];
    }
    __syncthreads();
#pragma unroll
    for (int i = 0; i < 4; i++) {
        int nc = tw*4 + i;
        float v0 = t[tx*2][nc];
        float v1 = t[tx*2+1][nc];
        float l0, l1;
        __nv_bfloat162 hh = split_hi2(v0, v1, l0, l1);
        __nv_bfloat162 ll = __halves2bfloat162(__float2bfloat16(l0), __float2bfloat16(l1));
        size_t base = (size_t)(n0 + nc)*3*K + k0 + tx*2;
        *(__nv_bfloat162*)&dst[base]       = hh;
        *(__nv_bfloat162*)&dst[base + K]   = ll;
        *(__nv_bfloat162*)&dst[base + 2*K] = hh;
    }
}

/* ======================= bf16 mma.sync GEMM ==============================
   3-stage cp.async pipeline (96KB smem) -> 2 CTAs/SM; 8-row CTA swizzle.  */
#define GSTAGE 32768
__global__ __launch_bounds__(256, 2)
void gemm_mma(const __nv_bfloat16* __restrict__ A, const __nv_bfloat16* __restrict__ B,
              float* __restrict__ C, int Kp, int N) {
    const int tid = threadIdx.x, lane = tid & 31, wid = tid >> 5;
    const int wm = wid & 1, wn = wid >> 1;
    /* swizzle: groups of 8 m-blocks iterate all n-blocks (B L2 reuse x8) */
    int bid = blockIdx.y * gridDim.x + blockIdx.x;
    int nb = gridDim.x;
    int gsz = nb << 3;
    int grp = bid / gsz;
    int rem = bid - grp*gsz;
    const int m0 = (grp*8 + (rem & 7))*128;
    const int n0 = (rem >> 3)*128;
    const uint32_t sbase = smem_u32(dynsm);
    const int S = Kp >> 6;

    float acc[4][4][4];
#pragma unroll
    for (int mi = 0; mi < 4; mi++)
#pragma unroll
        for (int ni = 0; ni < 4; ni++)
#pragma unroll
            for (int e = 0; e < 4; e++) acc[mi][ni][e] = 0.f;

    int cr[4], cc[4];
    uint32_t sOffA[4];
#pragma unroll
    for (int i = 0; i < 4; i++) {
        int id = tid + (i << 8);
        cr[i] = id >> 3; cc[i] = id & 7;
        sOffA[i] = cr[i]*128 + ((cc[i] ^ (cr[i] & 7)) << 4);
    }

#define ISSUE_STAGE(t) do {                                                   \
        uint32_t stb = sbase + ((t) % 3)*GSTAGE;                              \
        _Pragma("unroll")                                                     \
        for (int i = 0; i < 4; i++) {                                         \
            const __nv_bfloat16* g = A + (size_t)(m0 + cr[i])*Kp + (t)*64 + (cc[i] << 3); \
            CP_ASYNC16(stb + sOffA[i], g);                                    \
        }                                                                     \
        _Pragma("unroll")                                                     \
        for (int i = 0; i < 4; i++) {                                         \
            const __nv_bfloat16* g = B + (size_t)(n0 + cr[i])*Kp + (t)*64 + (cc[i] << 3); \
            CP_ASYNC16(stb + 16384 + sOffA[i], g);                            \
        }                                                                     \
    } while (0)

    ISSUE_STAGE(0); CP_COMMIT();
    ISSUE_STAGE(1); CP_COMMIT();

    int rowA[4], swzA[4], rowB[2], swzB[2];
#pragma unroll
    for (int mi = 0; mi < 4; mi++) {
        rowA[mi] = wm*64 + mi*16 + (lane & 15);
        swzA[mi] = rowA[mi] & 7;
    }
#pragma unroll
    for (int ni2 = 0; ni2 < 2; ni2++) {
        rowB[ni2] = wn*32 + ni2*16 + ((lane >> 4) << 3) + (lane & 7);
        swzB[ni2] = rowB[ni2] & 7;
    }
    const int hiA = lane >> 4;
    const int hiB = (lane >> 3) & 1;

    for (int s = 0; s < S; s++) {
        CP_WAIT1();
        __syncthreads();
        if (s + 2 < S) ISSUE_STAGE(s + 2);
        CP_COMMIT();

        uint32_t sA = sbase + (s % 3)*GSTAGE;
        uint32_t sB = sA + 16384;
#pragma unroll
        for (int kk = 0; kk < 4; kk++) {
            uint32_t a[4][4];
#pragma unroll
            for (int mi = 0; mi < 4; mi++) {
                uint32_t ad = sA + rowA[mi]*128 + ((((kk << 1) | hiA) ^ swzA[mi]) << 4);
                LDSM4(a[mi], ad);
            }
            uint32_t b[2][4];
#pragma unroll
            for (int ni2 = 0; ni2 < 2; ni2++) {
                uint32_t ad = sB + rowB[ni2]*128 + ((((kk << 1) | hiB) ^ swzB[ni2]) << 4);
                LDSM4(b[ni2], ad);
            }
#pragma unroll
            for (int mi = 0; mi < 4; mi++)
#pragma unroll
                for (int ni = 0; ni < 4; ni++)
                    MMA16816(acc[mi][ni], a[mi], b[ni >> 1][(ni & 1)*2], b[ni >> 1][(ni & 1)*2 + 1]);
        }
    }

    const int g = lane >> 2, tg = lane & 3;
#pragma unroll
    for (int mi = 0; mi < 4; mi++) {
#pragma unroll
        for (int ni = 0; ni < 4; ni++) {
            int row = m0 + wm*64 + mi*16 + g;
            int col = n0 + wn*32 + ni*8 + (tg << 1);
            *(float2*)&C[(size_t)row*N + col]     = make_float2(acc[mi][ni][0], acc[mi][ni][1]);
            *(float2*)&C[(size_t)(row+8)*N + col] = make_float2(acc[mi][ni][2], acc[mi][ni][3]);
        }
    }
#undef ISSUE_STAGE
}

/* ---------------- ba = hidden @ W_ba : M=4096, K=2048, N=64 --------------- */
__global__ __launch_bounds__(256)
void ba_gemm(const float* __restrict__ A, const float* __restrict__ B) {
    int c = threadIdx.x & 63;
    int rl = threadIdx.x >> 6;
    int row0 = blockIdx.x*16 + rl*4;
    float acc[4] = {0,0,0,0};
#pragma unroll 8
    for (int k = 0; k < 2048; k++) {
        float b = __ldg(&B[k*64 + c]);
#pragma unroll
        for (int r = 0; r < 4; r++)
            acc[r] += __ldg(&A[(size_t)(row0+r)*2048 + k]) * b;
    }
#pragma unroll
    for (int r = 0; r < 4; r++) g_ba[(size_t)(row0+r)*64 + c] = acc[r];
}

/* ---------------- depthwise causal conv (ksz=4) + SiLU -------------------- */
__global__ void conv_silu(const float* __restrict__ cw) {
    int idx = blockIdx.x*blockDim.x + threadIdx.x;
    if (idx >= SEQ*CONV_DIM) return;
    int s = idx >> 13;
    int c = idx & 8191;
    int col;
    if (c < 2048)      { int kh = c >> 7, d = c & 127;       col = kh*768 + d; }
    else if (c < 4096) { int c2 = c-2048; int kh = c2 >> 7;  col = kh*768 + 128 + (c2 & 127); }
    else               { int c2 = c-4096; int h16 = c2 >> 8; col = h16*768 + 256 + (c2 & 255); }
    float acc = 0.f;
#pragma unroll
    for (int j = 0; j < 4; j++) {
        int t = s - 3 + j;
        if (t >= 0) acc += g_qkvz[(size_t)t*QKVZ_N + col] * cw[j*CONV_DIM + c];
    }
    float r = acc / (1.f + __expf(-acc));
    if (c < 2048)       g_qc[(size_t)s*2048 + c]        = r * QSCALE;
    else if (c < 4096)  g_kc[(size_t)s*2048 + (c-2048)] = r;
    else                g_vc[(size_t)s*4096 + (c-4096)] = r;
}

/* ---------------- beta, g, cumsum(g) within chunk ------------------------- */
__global__ void gates_kernel(const float* __restrict__ A_log,
                             const float* __restrict__ dt_bias) {
    int chunk = blockIdx.x, hv = blockIdx.y, t = threadIdx.x;
    int s = chunk*CHUNK + t;
    int base = ((hv >> 1) << 2) + (hv & 1);
    float bg = g_ba[(size_t)s*64 + base];
    float ag = g_ba[(size_t)s*64 + base + 2];
    g_beta[hv*SEQ + s] = 1.f / (1.f + expf(-bg));
    float x = ag + dt_bias[hv];
    float sp = (x > 20.f) ? x : log1pf(expf(x));
    float g = -expf(A_log[hv]) * sp;
    __shared__ float sh[64];
    sh[t] = g;
    __syncthreads();
    for (int off = 1; off < 64; off <<= 1) {
        float v = (t >= off) ? sh[t-off] : 0.f;
        __syncthreads();
        sh[t] += v;
        __syncthreads();
    }
    g_gcum[hv*SEQ + s] = sh[t];
}

/* ------------- per (head, chunk) parallel precompute (unchanged) ---------- */
__global__ __launch_bounds__(256, 2)
void precompute_kernel() {
    float* sm    = (float*)dynsm;
    float* ks    = sm;
    float* vs    = ks + 64*129;
    float* Ls    = vs + 64*129;
    float* Xs    = Ls + 4096;
    float* betas = Xs + 4096;
    float* gcs   = betas + 64;
    float* bgm   = gcs + 64;
    const int c = blockIdx.x, hv = blockIdx.y, kh = hv >> 1;
    const int tid = threadIdx.x;
    const int ti = tid >> 4, tj = tid & 15;

    for (int l = tid; l < 2048; l += 256) {
        int row = l >> 5, c4 = (l & 31) << 2;
        float4 v = *(const float4*)&g_kc[(size_t)(c*CHUNK+row)*2048 + kh*128 + c4];
        float* p = &ks[row*129 + c4];
        p[0]=v.x; p[1]=v.y; p[2]=v.z; p[3]=v.w;
    }
    if (tid < 64) {
        int s = c*CHUNK + tid;
        betas[tid] = g_beta[hv*SEQ + s];
        gcs[tid]   = g_gcum[hv*SEQ + s];
    }
    __syncthreads();
    if (tid < 64) bgm[tid] = betas[tid]*expf(gcs[tid]);

    {
        float acc[4][4];
#pragma unroll
        for (int r = 0; r < 4; r++)
#pragma unroll
            for (int q = 0; q < 4; q++) acc[r][q] = 0.f;
        for (int d = 0; d < 128; d++) {
            float a[4], b[4];
#pragma unroll
            for (int r = 0; r < 4; r++) a[r] = ks[(ti*4+r)*129 + d];
#pragma unroll
            for (int q = 0; q < 4; q++) b[q] = ks[(tj*4+q)*129 + d];
#pragma unroll
            for (int r = 0; r < 4; r++)
#pragma unroll
                for (int q = 0; q < 4; q++) acc[r][q] += a[r]*b[q];
        }
#pragma unroll
        for (int r = 0; r < 4; r++) {
            int i = ti*4 + r;
#pragma unroll
            for (int q = 0; q < 4; q++) {
                int j = tj*4 + q;
                Ls[i*64 + j] = (i > j) ? -betas[i]*acc[r][q]*expf(gcs[i]-gcs[j]) : 0.f;
            }
        }
    }
    __syncthreads();

    for (int l = tid; l < 2048; l += 256) {
        int row = l >> 5, c4 = (l & 31) << 2;
        float4 v = *(const float4*)&g_qc[(size_t)(c*CHUNK+row)*2048 + kh*128 + c4];
        float* p = &vs[row*129 + c4];
        p[0]=v.x; p[1]=v.y; p[2]=v.z; p[3]=v.w;
    }
    if (tid < 64) {
        int j = tid;
        for (int i = 0; i < 64; i++) {
            float acc = (i == j) ? 1.f : 0.f;
            for (int m = 0; m < i; m++) acc += Ls[i*64+m]*Xs[m*64+j];
            Xs[i*64+j] = acc;
        }
    }
    __syncthreads();

    {
        float acc[4][4];
#pragma unroll
        for (int r = 0; r < 4; r++)
#pragma unroll
            for (int q = 0; q < 4; q++) acc[r][q] = 0.f;
        for (int d = 0; d < 128; d++) {
            float a[4], b[4];
#pragma unroll
            for (int r = 0; r < 4; r++) a[r] = vs[(ti*4+r)*129 + d];
#pragma unroll
            for (int q = 0; q < 4; q++) b[q] = ks[(tj*4+q)*129 + d];
#pragma unroll
            for (int r = 0; r < 4; r++)
#pragma unroll
                for (int q = 0; q < 4; q++) acc[r][q] += a[r]*b[q];
        }
        size_t outb = (size_t)(hv*NC + c)*4096;
#pragma unroll
        for (int r = 0; r < 4; r++) {
            int i = ti*4 + r;
#pragma unroll
            for (int q = 0; q < 4; q++) {
                int j = tj*4 + q;
                g_attnA[outb + i*64 + j] = (i >= j) ? acc[r][q]*expf(gcs[i]-gcs[j]) : 0.f;
            }
        }
    }
    __syncthreads();

    for (int l = tid; l < 2048; l += 256) {
        int row = l >> 5, c4 = (l & 31) << 2;
        float4 v = *(const float4*)&g_vc[(size_t)(c*CHUNK+row)*4096 + hv*128 + c4];
        float* p = &vs[row*129 + c4];
        p[0]=v.x; p[1]=v.y; p[2]=v.z; p[3]=v.w;
    }
    __syncthreads();

    {
        const int iq = tid >> 5;
        const int ln = tid & 31;
        const int i0 = iq*8;
        float aK[8][4], aV[8][4];
#pragma unroll
        for (int r = 0; r < 8; r++)
#pragma unroll
            for (int q = 0; q < 4; q++) { aK[r][q] = 0.f; aV[r][q] = 0.f; }
        for (int m = 0; m < 64; m++) {
            float bg = bgm[m], bt = betas[m];
            float kk[4], vv[4];
#pragma unroll
            for (int q = 0; q < 4; q++) {
                kk[q] = ks[m*129 + ln + 32*q];
                vv[q] = vs[m*129 + ln + 32*q];
            }
#pragma unroll
            for (int r = 0; r < 8; r++) {
                float x  = Xs[(i0+r)*64 + m];
                float xb = x*bg, xv = x*bt;
#pragma unroll
                for (int q = 0; q < 4; q++) {
                    aK[r][q] += xb*kk[q];
                    aV[r][q] += xv*vv[q];
                }
            }
        }
        size_t ob = (size_t)(hv*NC + c)*CHUNK*128;
#pragma unroll
        for (int r = 0; r < 8; r++)
#pragma unroll
            for (int q = 0; q < 4; q++) {
                size_t o = ob + (size_t)(i0+r)*128 + ln + 32*q;
                g_kcd[o]    = aK[r][q];
                g_vintra[o] = aV[r][q];
            }
    }
}

/* ------------- sequential inter-chunk scan: f32x2 packed ------------------
   state: float2[64 dpair][32 jj]; vn: float2[32 rpair][32 jj].             */
__global__ __launch_bounds__(256)
void scan_kernel() {
    float* smf     = (float*)dynsm;
    float2* statev = (float2*)smf;            /* 4096 floats */
    float* qs      = smf + 4096;              /* [64][128]   */
    float* ksm     = qs + 8192;
    float* kcds    = ksm + 8192;
    float* as_     = kcds + 8192;             /* [64][64]    */
    float* vnf     = as_ + 4096;              /* 2048 floats */
    float2* vn2    = (float2*)vnf;
    float* gcs     = vnf + 2048;
    float* wexp    = gcs + 64;
    const int hv = blockIdx.y, j0 = blockIdx.x*32, kh = hv >> 1;
    const int tid = threadIdx.x, jj = tid & 31, ig = tid >> 5;
    const int i0 = ig*8;

    for (int l = tid; l < 2048; l += 256) statev[l] = make_float2(0.f, 0.f);
    __syncthreads();

    for (int c = 0; c < NC; c++) {
        const size_t rb = (size_t)(hv*NC + c)*CHUNK;
        for (int l = tid; l < 2048; l += 256) {
            int row = l >> 5, c4 = (l & 31) << 2;
            *(float4*)&qs[row*128 + c4]   = *(const float4*)&g_qc[(size_t)(c*CHUNK+row)*2048 + kh*128 + c4];
            *(float4*)&ksm[row*128 + c4]  = *(const float4*)&g_kc[(size_t)(c*CHUNK+row)*2048 + kh*128 + c4];
            *(float4*)&kcds[row*128 + c4] = *(const float4*)&g_kcd[rb*128 + (size_t)l*4];
        }
        for (int l = tid; l < 1024; l += 256)
            *(float4*)&as_[l*4] = *(const float4*)&g_attnA[rb*64 + (size_t)l*4];
        for (int l = tid; l < 2048; l += 256) {
            int i = l >> 5, j = l & 31;
            vnf[(i >> 1)*64 + j*2 + (i & 1)] = g_vintra[(rb + i)*128 + j0 + j];
        }
        if (tid < 64) gcs[tid] = g_gcum[hv*SEQ + c*CHUNK + tid];
        __syncthreads();
        if (tid < 64) wexp[tid] = expf(gcs[63] - gcs[tid]);

        /* step2: v_new = v_intra - kcd@state ; o_part = q@state (f32x2) */
        float2 kacc[8], qacc[8];
#pragma unroll
        for (int r = 0; r < 8; r++) {
            kacc[r] = make_float2(0.f, 0.f);
            qacc[r] = make_float2(0.f, 0.f);
        }
        for (int dp = 0; dp < 64; dp++) {
            float2 sv = statev[dp*32 + jj];
#pragma unroll
            for (int r = 0; r < 8; r++) {
                ffma2(kacc[r], *(float2*)&kcds[(i0+r)*128 + dp*2], sv);
                ffma2(qacc[r], *(float2*)&qs[(i0+r)*128 + dp*2], sv);
            }
        }
        float vnew[8], oo[8];
#pragma unroll
        for (int r = 0; r < 8; r++) {
            vnew[r] = vnf[((i0+r) >> 1)*64 + jj*2 + ((i0+r) & 1)] - (kacc[r].x + kacc[r].y);
            oo[r]   = (qacc[r].x + qacc[r].y) * expf(gcs[i0+r]);
        }
#pragma unroll
        for (int rp = 0; rp < 4; rp++)
            vn2[((i0 >> 1) + rp)*32 + jj] = make_float2(vnew[2*rp], vnew[2*rp+1]);
        __syncthreads();

        /* step3: out += a @ v_new (f32x2 over m-pairs) */
        float2 oacc[8];
#pragma unroll
        for (int r = 0; r < 8; r++) oacc[r] = make_float2(0.f, 0.f);
        for (int mp = 0; mp < 32; mp++) {
            float2 vv = vn2[mp*32 + jj];
#pragma unroll
            for (int r = 0; r < 8; r++)
                ffma2(oacc[r], *(float2*)&as_[(i0+r)*64 + mp*2], vv);
        }
#pragma unroll
        for (int r = 0; r < 8; r++) {
            float o = oo[r] + oacc[r].x + oacc[r].y;
            g_core[(size_t)(c*CHUNK + i0 + r)*4096 + hv*128 + j0 + jj] = o;
        }

        /* step4: state = state*e^glast + k'^T @ v_new (f32x2 over d-pairs) */
        {
            float eg = expf(gcs[63]);
            float2 sacc[8];
#pragma unroll
            for (int dd = 0; dd < 8; dd++) {
                float2 sv = statev[(i0 + dd)*32 + jj];
                sacc[dd] = make_float2(sv.x*eg, sv.y*eg);
            }
            for (int i = 0; i < 64; i++) {
                float vw = wexp[i] * vnf[(i >> 1)*64 + jj*2 + (i & 1)];
                float2 vw2 = make_float2(vw, vw);
#pragma unroll
                for (int dd = 0; dd < 8; dd++)
                    ffma2(sacc[dd], *(float2*)&ksm[i*128 + (i0 + dd)*2], vw2);
            }
#pragma unroll
            for (int dd = 0; dd < 8; dd++)
                statev[(i0 + dd)*32 + jj] = sacc[dd];
        }
        __syncthreads();
    }
}

/* ------- gated RMSNorm fused with split-bf16 A2 emission ------------------ */
__global__ void rmsnorm_kernel(const float* __restrict__ nw) {
    int gw = (blockIdx.x*blockDim.x + threadIdx.x) >> 5;
    int lane = threadIdx.x & 31;
    int s = gw >> 5;
    int hv = gw & 31;
    int d0 = lane*4;
    size_t zbase = (size_t)s*QKVZ_N + (hv >> 1)*768 + 512 + (hv & 1)*128 + d0;
    size_t cbase = (size_t)s*4096 + hv*128 + d0;
    float4 cv = *(const float4*)&g_core[cbase];
    float4 zv = *(const float4*)&g_qkvz[zbase];
    float x[4];
    x[0] = cv.x * (zv.x / (1.f + expf(-zv.x)));
    x[1] = cv.y * (zv.y / (1.f + expf(-zv.y)));
    x[2] = cv.z * (zv.z / (1.f + expf(-zv.z)));
    x[3] = cv.w * (zv.w / (1.f + expf(-zv.w)));
    float ss = x[0]*x[0] + x[1]*x[1] + x[2]*x[2] + x[3]*x[3];
#pragma unroll
    for (int off = 16; off; off >>= 1) ss += __shfl_xor_sync(0xffffffffu, ss, off);
    float inv = rsqrtf(ss*(1.f/128.f) + 1e-6f);
    float y[4];
#pragma unroll
    for (int r = 0; r < 4; r++) y[r] = x[r]*inv*nw[d0 + r];
    float l0, l1, l2, l3;
    __nv_bfloat162 h01 = split_hi2(y[0], y[1], l0, l1);
    __nv_bfloat162 h23 = split_hi2(y[2], y[3], l2, l3);
    __nv_bfloat162 l01 = __halves2bfloat162(__float2bfloat16(l0), __float2bfloat16(l1));
    __nv_bfloat162 l23 = __halves2bfloat162(__float2bfloat16(l2), __float2bfloat16(l3));
    size_t base = (size_t)s*12288 + hv*128 + d0;
    *(__nv_bfloat162*)&g_A2[base]          = h01;
    *(__nv_bfloat162*)&g_A2[base + 2]      = h23;
    *(__nv_bfloat162*)&g_A2[base + 4096]   = h01;
    *(__nv_bfloat162*)&g_A2[base + 4098]   = h23;
    *(__nv_bfloat162*)&g_A2[base + 8192]   = l01;
    *(__nv_bfloat162*)&g_A2[base + 8194]   = l23;
}

/* ---------------- launcher ------------------------------------------------ */
extern "C" void kernel_launch(void* const* d_in, const int* in_sizes, int n_in,
                              void* d_out, int out_size) {
    const float* hidden  = (const float*)d_in[0];
    const float* W_qkvz  = (const float*)d_in[1];
    const float* W_ba    = (const float*)d_in[2];
    const float* convk   = (const float*)d_in[3];
    const float* A_log   = (const float*)d_in[4];
    const float* dt_bias = (const float*)d_in[5];
    const float* normw   = (const float*)d_in[6];
    const float* W_out   = (const float*)d_in[7];
    float* out = (float*)d_out;

    float *qkvz_p;
    __nv_bfloat16 *A1, *B1, *A2, *B2;
    cudaGetSymbolAddress((void**)&qkvz_p, g_qkvz);
    cudaGetSymbolAddress((void**)&A1, g_A1);
    cudaGetSymbolAddress((void**)&B1, g_B1);
    cudaGetSymbolAddress((void**)&A2, g_A2);
    cudaGetSymbolAddress((void**)&B2, g_B2);

    cudaFuncSetAttribute(precompute_kernel,
                         cudaFuncAttributeMaxDynamicSharedMemorySize, 99584);
    cudaFuncSetAttribute(scan_kernel,
                         cudaFuncAttributeMaxDynamicSharedMemorySize, 139776);
    cudaFuncSetAttribute(gemm_mma,
                         cudaFuncAttributeMaxDynamicSharedMemorySize, 3*GSTAGE);

    /* conversions for GEMM1 + static W_out for GEMM2 */
    cvtA<<<(SEQ*EMB)/512, 256>>>(hidden, A1, 11);              /* K=2048 */
    cvtBt<<<dim3(EMB/64, QKVZ_N/32), 256>>>(W_qkvz, B1, EMB, QKVZ_N);
    cvtBt<<<dim3(4096/64, EMB/32), 256>>>(W_out, B2, 4096, EMB);

    /* 1. qkvz = hidden @ W_qkvz  (bf16x3 mma.sync, K'=6144) */
    gemm_mma<<<dim3(QKVZ_N/128, SEQ/128), 256, 3*GSTAGE>>>(A1, B1, qkvz_p, 3*EMB, QKVZ_N);
    /* 2. ba */
    ba_gemm<<<256, 256>>>(hidden, W_ba);
    /* 3. conv + silu */
    conv_silu<<<(SEQ*CONV_DIM)/256, 256>>>(convk);
    /* 4. gates */
    gates_kernel<<<dim3(NC, NVH), 64>>>(A_log, dt_bias);
    /* 5. precompute */
    precompute_kernel<<<dim3(NC, NVH), 256, 99584>>>();
    /* 6. scan (f32x2) */
    scan_kernel<<<dim3(4, NVH), 256, 139776>>>();
    /* 7. rmsnorm + A2 emission (fused) */
    rmsnorm_kernel<<<(SEQ*NVH)/8, 256>>>(normw);
    /* 8. out = xf @ W_out  (bf16x3 mma.sync, K'=12288) */
    gemm_mma<<<dim3(EMB/128, SEQ/128), 256, 3*GSTAGE>>>(A2, B2, out, 3*4096, EMB);
}

// round 13
// speedup vs baseline: 2.4292x; 1.1571x over previous
#include <cuda_runtime.h>
#include <cuda_bf16.h>
#include <math.h>
#include <stdint.h>

#define SEQ 4096
#define EMB 2048
#define NKH 16
#define NVH 32
#define DK 128
#define DV 128
#define CHUNK 64
#define NC (SEQ/CHUNK)      /* 64 */
#define QKVZ_N 12288
#define CONV_DIM 8192
#define QSCALE 0.08838834764831845f  /* 1/sqrt(128) */

/* single shared dynamic-smem symbol for all kernels */
extern __shared__ char dynsm[];

/* ---------------- scratch (device globals; no allocs allowed) ------------- */
__device__ float g_qkvz[(size_t)SEQ*QKVZ_N];            /* 192 MiB */
__device__ float g_ba[SEQ*64];
__device__ float g_qc[(size_t)SEQ*2048];
__device__ float g_kc[(size_t)SEQ*2048];
__device__ float g_vc[(size_t)SEQ*4096];
__device__ float g_beta[NVH*SEQ];
__device__ float g_gcum[NVH*SEQ];
__device__ float g_attnA[(size_t)NVH*NC*CHUNK*CHUNK];
__device__ float g_vintra[(size_t)NVH*SEQ*DV];
__device__ float g_kcd[(size_t)NVH*SEQ*DK];
__device__ float g_core[(size_t)SEQ*NVH*DV];

/* split-bf16 extended-K operands: A'=[Ah|Ah|Al] (MxK'), B'^T=[Bh|Bl|Bh] (NxK') */
__device__ __nv_bfloat16 g_A1[(size_t)SEQ*3*EMB];        /* 4096 x 6144  */
__device__ __nv_bfloat16 g_B1[(size_t)QKVZ_N*3*EMB];     /* 12288 x 6144 */
__device__ __nv_bfloat16 g_A2[(size_t)SEQ*3*4096];       /* 4096 x 12288 */
__device__ __nv_bfloat16 g_B2[(size_t)EMB*3*4096];       /* 2048 x 12288 */

/* ======================= asm helpers ===================================== */
__device__ __forceinline__ uint32_t smem_u32(const void* p) {
    uint32_t a;
    asm("{ .reg .u64 t; cvta.to.shared.u64 t, %1; cvt.u32.u64 %0, t; }" : "=r"(a) : "l"(p));
    return a;
}
#define CP_ASYNC16(sa, ga) \
    asm volatile("cp.async.cg.shared.global [%0], [%1], 16;" :: "r"(sa), "l"(ga))
#define CP_COMMIT() asm volatile("cp.async.commit_group;")
#define CP_WAIT1()  asm volatile("cp.async.wait_group 1;")
#define CP_WAIT0()  asm volatile("cp.async.wait_group 0;")
#define LDSM4(R, ad) \
    asm volatile("ldmatrix.sync.aligned.m8n8.x4.shared.b16 {%0,%1,%2,%3}, [%4];" \
        : "=r"((R)[0]), "=r"((R)[1]), "=r"((R)[2]), "=r"((R)[3]) : "r"(ad))
#define MMA16816(c, a, b0, b1) \
    asm volatile("mma.sync.aligned.m16n8k16.row.col.f32.bf16.bf16.f32 " \
        "{%0,%1,%2,%3}, {%4,%5,%6,%7}, {%8,%9}, {%0,%1,%2,%3};" \
        : "+f"((c)[0]), "+f"((c)[1]), "+f"((c)[2]), "+f"((c)[3]) \
        : "r"((a)[0]), "r"((a)[1]), "r"((a)[2]), "r"((a)[3]), "r"(b0), "r"(b1))

/* packed f32x2 fma: c += a*b componentwise (Blackwell, base sm_100+ feature) */
__device__ __forceinline__ void ffma2(float2& c, float2 a, float2 b) {
    asm("fma.rn.f32x2 %0, %1, %2, %0;"
        : "+l"(*reinterpret_cast<unsigned long long*>(&c))
        : "l"(*reinterpret_cast<unsigned long long*>(&a)),
          "l"(*reinterpret_cast<unsigned long long*>(&b)));
}

__device__ __forceinline__ __nv_bfloat162 split_hi2(float a, float b,
                                                    float& la, float& lb) {
    __nv_bfloat16 ha = __float2bfloat16(a), hb = __float2bfloat16(b);
    la = a - __bfloat162float(ha);
    lb = b - __bfloat162float(hb);
    return __halves2bfloat162(ha, hb);
}

/* ======================= split-bf16 conversions ========================== */
__global__ void cvtA(const float* __restrict__ src, __nv_bfloat16* __restrict__ dst,
                     int kbits) {
    size_t idx = ((size_t)blockIdx.x*256 + threadIdx.x)*2;
    int K = 1 << kbits;
    int m = (int)(idx >> kbits), k = (int)(idx & (K - 1));
    float2 v = *(const float2*)&src[idx];
    float l0, l1;
    __nv_bfloat162 hh = split_hi2(v.x, v.y, l0, l1);
    __nv_bfloat162 ll = __halves2bfloat162(__float2bfloat16(l0), __float2bfloat16(l1));
    size_t base = (((size_t)m*3) << kbits) + k;
    *(__nv_bfloat162*)&dst[base]       = hh;
    *(__nv_bfloat162*)&dst[base + K]   = hh;
    *(__nv_bfloat162*)&dst[base + 2*K] = ll;
}
__global__ __launch_bounds__(256)
void cvtBt(const float* __restrict__ W, __nv_bfloat16* __restrict__ dst,
           int K, int N) {
    __shared__ float t[64][33];
    int k0 = blockIdx.x*64, n0 = blockIdx.y*32;
    int tid = threadIdx.x;
    int tx = tid & 31, tw = tid >> 5;
#pragma unroll
    for (int i = 0; i < 8; i++) {
        int row = tw + i*8;
        t[row][tx] = W[(size_t)(k0+row)*N + n0 + tx];
    }
    __syncthreads();
#pragma unroll
    for (int i = 0; i < 4; i++) {
        int nc = tw*4 + i;
        float v0 = t[tx*2][nc];
        float v1 = t[tx*2+1][nc];
        float l0, l1;
        __nv_bfloat162 hh = split_hi2(v0, v1, l0, l1);
        __nv_bfloat162 ll = __halves2bfloat162(__float2bfloat16(l0), __float2bfloat16(l1));
        size_t base = (size_t)(n0 + nc)*3*K + k0 + tx*2;
        *(__nv_bfloat162*)&dst[base]       = hh;
        *(__nv_bfloat162*)&dst[base + K]   = ll;
        *(__nv_bfloat162*)&dst[base + 2*K] = hh;
    }
}

/* ======================= bf16 mma.sync GEMM ==============================
   3-stage cp.async pipeline (96KB smem), 2 CTAs/SM, 8-row CTA swizzle,
   stage loop unrolled by 3 (S always divisible by 3 here).               */
#define GSTAGE 32768
__global__ __launch_bounds__(256, 2)
void gemm_mma(const __nv_bfloat16* __restrict__ A, const __nv_bfloat16* __restrict__ B,
              float* __restrict__ C, int Kp, int N) {
    const int tid = threadIdx.x, lane = tid & 31, wid = tid >> 5;
    const int wm = wid & 1, wn = wid >> 1;
    int bid = blockIdx.y * gridDim.x + blockIdx.x;
    int nb = gridDim.x;
    int gsz = nb << 3;
    int grp = bid / gsz;
    int rem = bid - grp*gsz;
    const int m0 = (grp*8 + (rem & 7))*128;
    const int n0 = (rem >> 3)*128;
    const uint32_t sbase = smem_u32(dynsm);
    const int S = Kp >> 6;

    float acc[4][4][4];
#pragma unroll
    for (int mi = 0; mi < 4; mi++)
#pragma unroll
        for (int ni = 0; ni < 4; ni++)
#pragma unroll
            for (int e = 0; e < 4; e++) acc[mi][ni][e] = 0.f;

    int cr[4], cc[4];
    uint32_t sOffA[4];
#pragma unroll
    for (int i = 0; i < 4; i++) {
        int id = tid + (i << 8);
        cr[i] = id >> 3; cc[i] = id & 7;
        sOffA[i] = cr[i]*128 + ((cc[i] ^ (cr[i] & 7)) << 4);
    }

    auto issue_stage = [&](int t, int buf) {
        uint32_t stb = sbase + buf*GSTAGE;
#pragma unroll
        for (int i = 0; i < 4; i++) {
            const __nv_bfloat16* g = A + (size_t)(m0 + cr[i])*Kp + t*64 + (cc[i] << 3);
            CP_ASYNC16(stb + sOffA[i], g);
        }
#pragma unroll
        for (int i = 0; i < 4; i++) {
            const __nv_bfloat16* g = B + (size_t)(n0 + cr[i])*Kp + t*64 + (cc[i] << 3);
            CP_ASYNC16(stb + 16384 + sOffA[i], g);
        }
    };

    issue_stage(0, 0); CP_COMMIT();
    issue_stage(1, 1); CP_COMMIT();

    int rowA[4], swzA[4], rowB[2], swzB[2];
#pragma unroll
    for (int mi = 0; mi < 4; mi++) {
        rowA[mi] = wm*64 + mi*16 + (lane & 15);
        swzA[mi] = rowA[mi] & 7;
    }
#pragma unroll
    for (int ni2 = 0; ni2 < 2; ni2++) {
        rowB[ni2] = wn*32 + ni2*16 + ((lane >> 4) << 3) + (lane & 7);
        swzB[ni2] = rowB[ni2] & 7;
    }
    const int hiA = lane >> 4;
    const int hiB = (lane >> 3) & 1;

    auto do_stage = [&](int s, int bufc) {
        CP_WAIT1();
        __syncthreads();
        if (s + 2 < S) issue_stage(s + 2, (bufc + 2) % 3);
        CP_COMMIT();

        uint32_t sA = sbase + bufc*GSTAGE;
        uint32_t sB = sA + 16384;
#pragma unroll
        for (int kk = 0; kk < 4; kk++) {
            uint32_t a[4][4];
#pragma unroll
            for (int mi = 0; mi < 4; mi++) {
                uint32_t ad = sA + rowA[mi]*128 + ((((kk << 1) | hiA) ^ swzA[mi]) << 4);
                LDSM4(a[mi], ad);
            }
            uint32_t b[2][4];
#pragma unroll
            for (int ni2 = 0; ni2 < 2; ni2++) {
                uint32_t ad = sB + rowB[ni2]*128 + ((((kk << 1) | hiB) ^ swzB[ni2]) << 4);
                LDSM4(b[ni2], ad);
            }
#pragma unroll
            for (int mi = 0; mi < 4; mi++)
#pragma unroll
                for (int ni = 0; ni < 4; ni++)
                    MMA16816(acc[mi][ni], a[mi], b[ni >> 1][(ni & 1)*2], b[ni >> 1][(ni & 1)*2 + 1]);
        }
    };

    int s = 0;
    for (; s + 3 <= S; s += 3) { do_stage(s, 0); do_stage(s + 1, 1); do_stage(s + 2, 2); }
    for (; s < S; s++) do_stage(s, s % 3);

    const int g = lane >> 2, tg = lane & 3;
#pragma unroll
    for (int mi = 0; mi < 4; mi++) {
#pragma unroll
        for (int ni = 0; ni < 4; ni++) {
            int row = m0 + wm*64 + mi*16 + g;
            int col = n0 + wn*32 + ni*8 + (tg << 1);
            *(float2*)&C[(size_t)row*N + col]     = make_float2(acc[mi][ni][0], acc[mi][ni][1]);
            *(float2*)&C[(size_t)(row+8)*N + col] = make_float2(acc[mi][ni][2], acc[mi][ni][3]);
        }
    }
}

/* ---------------- ba = hidden @ W_ba : M=4096, K=2048, N=64 --------------- */
__global__ __launch_bounds__(256)
void ba_gemm(const float* __restrict__ A, const float* __restrict__ B) {
    int c = threadIdx.x & 63;
    int rl = threadIdx.x >> 6;
    int row0 = blockIdx.x*16 + rl*4;
    float acc[4] = {0,0,0,0};
#pragma unroll 4
    for (int k4 = 0; k4 < 512; k4++) {
        int k = k4 << 2;
        float b0 = __ldg(&B[(k+0)*64 + c]);
        float b1 = __ldg(&B[(k+1)*64 + c]);
        float b2 = __ldg(&B[(k+2)*64 + c]);
        float b3 = __ldg(&B[(k+3)*64 + c]);
#pragma unroll
        for (int r = 0; r < 4; r++) {
            float4 a = *(const float4*)&A[(size_t)(row0+r)*2048 + k];
            acc[r] += a.x*b0 + a.y*b1 + a.z*b2 + a.w*b3;
        }
    }
#pragma unroll
    for (int r = 0; r < 4; r++) g_ba[(size_t)(row0+r)*64 + c] = acc[r];
}

/* ---------------- depthwise causal conv (ksz=4) + SiLU, float4 ----------- */
__global__ void conv_silu(const float* __restrict__ cw) {
    int idx = (blockIdx.x*blockDim.x + threadIdx.x)*4;
    int s = idx >> 13;
    int c = idx & 8191;
    int col;
    if (c < 2048)      { int kh = c >> 7, d = c & 127;       col = kh*768 + d; }
    else if (c < 4096) { int c2 = c-2048; int kh = c2 >> 7;  col = kh*768 + 128 + (c2 & 127); }
    else               { int c2 = c-4096; int h16 = c2 >> 8; col = h16*768 + 256 + (c2 & 255); }
    float4 acc = make_float4(0.f, 0.f, 0.f, 0.f);
#pragma unroll
    for (int j = 0; j < 4; j++) {
        int t = s - 3 + j;
        if (t >= 0) {
            float4 x = *(const float4*)&g_qkvz[(size_t)t*QKVZ_N + col];
            float4 w = *(const float4*)&cw[j*CONV_DIM + c];
            acc.x += x.x*w.x; acc.y += x.y*w.y; acc.z += x.z*w.z; acc.w += x.w*w.w;
        }
    }
    float4 r;
    r.x = acc.x / (1.f + __expf(-acc.x));
    r.y = acc.y / (1.f + __expf(-acc.y));
    r.z = acc.z / (1.f + __expf(-acc.z));
    r.w = acc.w / (1.f + __expf(-acc.w));
    if (c < 2048) {
        r.x *= QSCALE; r.y *= QSCALE; r.z *= QSCALE; r.w *= QSCALE;
        *(float4*)&g_qc[(size_t)s*2048 + c] = r;
    } else if (c < 4096) {
        *(float4*)&g_kc[(size_t)s*2048 + (c-2048)] = r;
    } else {
        *(float4*)&g_vc[(size_t)s*4096 + (c-4096)] = r;
    }
}

/* ---------------- beta, g, cumsum(g) within chunk ------------------------- */
__global__ void gates_kernel(const float* __restrict__ A_log,
                             const float* __restrict__ dt_bias) {
    int chunk = blockIdx.x, hv = blockIdx.y, t = threadIdx.x;
    int s = chunk*CHUNK + t;
    int base = ((hv >> 1) << 2) + (hv & 1);
    float bg = g_ba[(size_t)s*64 + base];
    float ag = g_ba[(size_t)s*64 + base + 2];
    g_beta[hv*SEQ + s] = 1.f / (1.f + expf(-bg));
    float x = ag + dt_bias[hv];
    float sp = (x > 20.f) ? x : log1pf(expf(x));
    float g = -expf(A_log[hv]) * sp;
    __shared__ float sh[64];
    sh[t] = g;
    __syncthreads();
    for (int off = 1; off < 64; off <<= 1) {
        float v = (t >= off) ? sh[t-off] : 0.f;
        __syncthreads();
        sh[t] += v;
        __syncthreads();
    }
    g_gcum[hv*SEQ + s] = sh[t];
}

/* ------------- per (head, chunk) parallel precompute (unchanged) ---------- */
__global__ __launch_bounds__(256, 2)
void precompute_kernel() {
    float* sm    = (float*)dynsm;
    float* ks    = sm;
    float* vs    = ks + 64*129;
    float* Ls    = vs + 64*129;
    float* Xs    = Ls + 4096;
    float* betas = Xs + 4096;
    float* gcs   = betas + 64;
    float* bgm   = gcs + 64;
    const int c = blockIdx.x, hv = blockIdx.y, kh = hv >> 1;
    const int tid = threadIdx.x;
    const int ti = tid >> 4, tj = tid & 15;

    for (int l = tid; l < 2048; l += 256) {
        int row = l >> 5, c4 = (l & 31) << 2;
        float4 v = *(const float4*)&g_kc[(size_t)(c*CHUNK+row)*2048 + kh*128 + c4];
        float* p = &ks[row*129 + c4];
        p[0]=v.x; p[1]=v.y; p[2]=v.z; p[3]=v.w;
    }
    if (tid < 64) {
        int s = c*CHUNK + tid;
        betas[tid] = g_beta[hv*SEQ + s];
        gcs[tid]   = g_gcum[hv*SEQ + s];
    }
    __syncthreads();
    if (tid < 64) bgm[tid] = betas[tid]*expf(gcs[tid]);

    {
        float acc[4][4];
#pragma unroll
        for (int r = 0; r < 4; r++)
#pragma unroll
            for (int q = 0; q < 4; q++) acc[r][q] = 0.f;
        for (int d = 0; d < 128; d++) {
            float a[4], b[4];
#pragma unroll
            for (int r = 0; r < 4; r++) a[r] = ks[(ti*4+r)*129 + d];
#pragma unroll
            for (int q = 0; q < 4; q++) b[q] = ks[(tj*4+q)*129 + d];
#pragma unroll
            for (int r = 0; r < 4; r++)
#pragma unroll
                for (int q = 0; q < 4; q++) acc[r][q] += a[r]*b[q];
        }
#pragma unroll
        for (int r = 0; r < 4; r++) {
            int i = ti*4 + r;
#pragma unroll
            for (int q = 0; q < 4; q++) {
                int j = tj*4 + q;
                Ls[i*64 + j] = (i > j) ? -betas[i]*acc[r][q]*expf(gcs[i]-gcs[j]) : 0.f;
            }
        }
    }
    __syncthreads();

    for (int l = tid; l < 2048; l += 256) {
        int row = l >> 5, c4 = (l & 31) << 2;
        float4 v = *(const float4*)&g_qc[(size_t)(c*CHUNK+row)*2048 + kh*128 + c4];
        float* p = &vs[row*129 + c4];
        p[0]=v.x; p[1]=v.y; p[2]=v.z; p[3]=v.w;
    }
    if (tid < 64) {
        int j = tid;
        for (int i = 0; i < 64; i++) {
            float acc = (i == j) ? 1.f : 0.f;
            for (int m = 0; m < i; m++) acc += Ls[i*64+m]*Xs[m*64+j];
            Xs[i*64+j] = acc;
        }
    }
    __syncthreads();

    {
        float acc[4][4];
#pragma unroll
        for (int r = 0; r < 4; r++)
#pragma unroll
            for (int q = 0; q < 4; q++) acc[r][q] = 0.f;
        for (int d = 0; d < 128; d++) {
            float a[4], b[4];
#pragma unroll
            for (int r = 0; r < 4; r++) a[r] = vs[(ti*4+r)*129 + d];
#pragma unroll
            for (int q = 0; q < 4; q++) b[q] = ks[(tj*4+q)*129 + d];
#pragma unroll
            for (int r = 0; r < 4; r++)
#pragma unroll
                for (int q = 0; q < 4; q++) acc[r][q] += a[r]*b[q];
        }
        size_t outb = (size_t)(hv*NC + c)*4096;
#pragma unroll
        for (int r = 0; r < 4; r++) {
            int i = ti*4 + r;
#pragma unroll
            for (int q = 0; q < 4; q++) {
                int j = tj*4 + q;
                g_attnA[outb + i*64 + j] = (i >= j) ? acc[r][q]*expf(gcs[i]-gcs[j]) : 0.f;
            }
        }
    }
    __syncthreads();

    for (int l = tid; l < 2048; l += 256) {
        int row = l >> 5, c4 = (l & 31) << 2;
        float4 v = *(const float4*)&g_vc[(size_t)(c*CHUNK+row)*4096 + hv*128 + c4];
        float* p = &vs[row*129 + c4];
        p[0]=v.x; p[1]=v.y; p[2]=v.z; p[3]=v.w;
    }
    __syncthreads();

    {
        const int iq = tid >> 5;
        const int ln = tid & 31;
        const int i0 = iq*8;
        float aK[8][4], aV[8][4];
#pragma unroll
        for (int r = 0; r < 8; r++)
#pragma unroll
            for (int q = 0; q < 4; q++) { aK[r][q] = 0.f; aV[r][q] = 0.f; }
        for (int m = 0; m < 64; m++) {
            float bg = bgm[m], bt = betas[m];
            float kk[4], vv[4];
#pragma unroll
            for (int q = 0; q < 4; q++) {
                kk[q] = ks[m*129 + ln + 32*q];
                vv[q] = vs[m*129 + ln + 32*q];
            }
#pragma unroll
            for (int r = 0; r < 8; r++) {
                float x  = Xs[(i0+r)*64 + m];
                float xb = x*bg, xv = x*bt;
#pragma unroll
                for (int q = 0; q < 4; q++) {
                    aK[r][q] += xb*kk[q];
                    aV[r][q] += xv*vv[q];
                }
            }
        }
        size_t ob = (size_t)(hv*NC + c)*CHUNK*128;
#pragma unroll
        for (int r = 0; r < 8; r++)
#pragma unroll
            for (int q = 0; q < 4; q++) {
                size_t o = ob + (size_t)(i0+r)*128 + ln + 32*q;
                g_kcd[o]    = aK[r][q];
                g_vintra[o] = aV[r][q];
            }
    }
}

/* ------------- sequential inter-chunk scan: f32x2 + cp.async prefetch -----
   smem floats: statev 0..4095 | qs 4096 | ksm 12288 | kcds{0,1} 20480/+8192
   | as{0,1} 36864/+4096 | vnraw{0,1} 45056/+2048 | vnf 49152 | gcs 51200
   | wexp 51264.  Total 51328 floats = 205312 B.                            */
__global__ __launch_bounds__(256)
void scan_kernel() {
    float* smf     = (float*)dynsm;
    float2* statev = (float2*)smf;
    float* qs      = smf + 4096;
    float* ksm     = smf + 12288;
    float* vnf     = smf + 49152;
    float2* vn2    = (float2*)vnf;
    float* gcs     = smf + 51200;
    float* wexp    = smf + 51264;
    const uint32_t sb = smem_u32(dynsm);
    const int hv = blockIdx.y, j0 = blockIdx.x*32, kh = hv >> 1;
    const int tid = threadIdx.x, jj = tid & 31, ig = tid >> 5;
    const int i0 = ig*8;

    for (int l = tid; l < 2048; l += 256) statev[l] = make_float2(0.f, 0.f);
    __syncthreads();

    /* cp.async prefetch of chunk c's kcd / attnA / vintra slice into buf */
    auto prefetch = [&](int c, int buf) {
        const size_t rb = (size_t)(hv*NC + c)*CHUNK;
        uint32_t kb = sb + (20480 + buf*8192)*4;
        const char* ks_src = (const char*)(g_kcd + rb*128);
        for (int i = tid; i < 2048; i += 256)
            CP_ASYNC16(kb + i*16, ks_src + i*16);
        uint32_t ab = sb + (36864 + buf*4096)*4;
        const char* as_src = (const char*)(g_attnA + rb*64);
        for (int i = tid; i < 1024; i += 256)
            CP_ASYNC16(ab + i*16, as_src + i*16);
        uint32_t vb = sb + (45056 + buf*2048)*4;
        for (int i = tid; i < 512; i += 256) {
            int row = i >> 3, off = (i & 7)*16;
            CP_ASYNC16(vb + row*128 + off,
                       (const char*)(g_vintra + (rb+row)*128 + j0) + off);
        }
    };

    prefetch(0, 0); CP_COMMIT();

    for (int c = 0; c < NC; c++) {
        const int cur = c & 1;
        float* kcds   = smf + 20480 + cur*8192;
        float* as_    = smf + 36864 + cur*4096;
        float* vnraw  = smf + 45056 + cur*2048;

        /* L2-hot regular loads */
        for (int l = tid; l < 2048; l += 256) {
            int row = l >> 5, c4 = (l & 31) << 2;
            *(float4*)&qs[row*128 + c4]  = *(const float4*)&g_qc[(size_t)(c*CHUNK+row)*2048 + kh*128 + c4];
            *(float4*)&ksm[row*128 + c4] = *(const float4*)&g_kc[(size_t)(c*CHUNK+row)*2048 + kh*128 + c4];
        }
        if (tid < 64) gcs[tid] = g_gcum[hv*SEQ + c*CHUNK + tid];
        CP_WAIT0();
        __syncthreads();
        if (c + 1 < NC) { prefetch(c + 1, cur ^ 1); }
        CP_COMMIT();
        if (tid < 64) wexp[tid] = expf(gcs[63] - gcs[tid]);

        /* step2: v_new = v_intra - kcd@state ; o_part = q@state (f32x2) */
        float2 kacc[8], qacc[8];
#pragma unroll
        for (int r = 0; r < 8; r++) {
            kacc[r] = make_float2(0.f, 0.f);
            qacc[r] = make_float2(0.f, 0.f);
        }
        for (int dp = 0; dp < 64; dp++) {
            float2 sv = statev[dp*32 + jj];
#pragma unroll
            for (int r = 0; r < 8; r++) {
                ffma2(kacc[r], *(float2*)&kcds[(i0+r)*128 + dp*2], sv);
                ffma2(qacc[r], *(float2*)&qs[(i0+r)*128 + dp*2], sv);
            }
        }
        float vnew[8], oo[8];
#pragma unroll
        for (int r = 0; r < 8; r++) {
            vnew[r] = vnraw[(i0+r)*32 + jj] - (kacc[r].x + kacc[r].y);
            oo[r]   = (qacc[r].x + qacc[r].y) * expf(gcs[i0+r]);
        }
#pragma unroll
        for (int rp = 0; rp < 4; rp++)
            vn2[((i0 >> 1) + rp)*32 + jj] = make_float2(vnew[2*rp], vnew[2*rp+1]);
        __syncthreads();

        /* step3: out += a @ v_new (f32x2 over m-pairs) */
        float2 oacc[8];
#pragma unroll
        for (int r = 0; r < 8; r++) oacc[r] = make_float2(0.f, 0.f);
        for (int mp = 0; mp < 32; mp++) {
            float2 vv = vn2[mp*32 + jj];
#pragma unroll
            for (int r = 0; r < 8; r++)
                ffma2(oacc[r], *(float2*)&as_[(i0+r)*64 + mp*2], vv);
        }
#pragma unroll
        for (int r = 0; r < 8; r++) {
            float o = oo[r] + oacc[r].x + oacc[r].y;
            g_core[(size_t)(c*CHUNK + i0 + r)*4096 + hv*128 + j0 + jj] = o;
        }

        /* step4: state = state*e^glast + k'^T @ v_new (f32x2 over d-pairs) */
        {
            float eg = expf(gcs[63]);
            float2 sacc[8];
#pragma unroll
            for (int dd = 0; dd < 8; dd++) {
                float2 sv = statev[(i0 + dd)*32 + jj];
                sacc[dd] = make_float2(sv.x*eg, sv.y*eg);
            }
            for (int i = 0; i < 64; i++) {
                float vw = wexp[i] * vnf[(i >> 1)*64 + jj*2 + (i & 1)];
                float2 vw2 = make_float2(vw, vw);
#pragma unroll
                for (int dd = 0; dd < 8; dd++)
                    ffma2(sacc[dd], *(float2*)&ksm[i*128 + (i0 + dd)*2], vw2);
            }
#pragma unroll
            for (int dd = 0; dd < 8; dd++)
                statev[(i0 + dd)*32 + jj] = sacc[dd];
        }
        __syncthreads();
    }
}

/* ------- gated RMSNorm fused with split-bf16 A2 emission ------------------ */
__global__ void rmsnorm_kernel(const float* __restrict__ nw) {
    int gw = (blockIdx.x*blockDim.x + threadIdx.x) >> 5;
    int lane = threadIdx.x & 31;
    int s = gw >> 5;
    int hv = gw & 31;
    int d0 = lane*4;
    size_t zbase = (size_t)s*QKVZ_N + (hv >> 1)*768 + 512 + (hv & 1)*128 + d0;
    size_t cbase = (size_t)s*4096 + hv*128 + d0;
    float4 cv = *(const float4*)&g_core[cbase];
    float4 zv = *(const float4*)&g_qkvz[zbase];
    float x[4];
    x[0] = cv.x * (zv.x / (1.f + expf(-zv.x)));
    x[1] = cv.y * (zv.y / (1.f + expf(-zv.y)));
    x[2] = cv.z * (zv.z / (1.f + expf(-zv.z)));
    x[3] = cv.w * (zv.w / (1.f + expf(-zv.w)));
    float ss = x[0]*x[0] + x[1]*x[1] + x[2]*x[2] + x[3]*x[3];
#pragma unroll
    for (int off = 16; off; off >>= 1) ss += __shfl_xor_sync(0xffffffffu, ss, off);
    float inv = rsqrtf(ss*(1.f/128.f) + 1e-6f);
    float y[4];
#pragma unroll
    for (int r = 0; r < 4; r++) y[r] = x[r]*inv*nw[d0 + r];
    float l0, l1, l2, l3;
    __nv_bfloat162 h01 = split_hi2(y[0], y[1], l0, l1);
    __nv_bfloat162 h23 = split_hi2(y[2], y[3], l2, l3);
    __nv_bfloat162 l01 = __halves2bfloat162(__float2bfloat16(l0), __float2bfloat16(l1));
    __nv_bfloat162 l23 = __halves2bfloat162(__float2bfloat16(l2), __float2bfloat16(l3));
    size_t base = (size_t)s*12288 + hv*128 + d0;
    *(__nv_bfloat162*)&g_A2[base]          = h01;
    *(__nv_bfloat162*)&g_A2[base + 2]      = h23;
    *(__nv_bfloat162*)&g_A2[base + 4096]   = h01;
    *(__nv_bfloat162*)&g_A2[base + 4098]   = h23;
    *(__nv_bfloat162*)&g_A2[base + 8192]   = l01;
    *(__nv_bfloat162*)&g_A2[base + 8194]   = l23;
}

/* ---------------- launcher ------------------------------------------------ */
extern "C" void kernel_launch(void* const* d_in, const int* in_sizes, int n_in,
                              void* d_out, int out_size) {
    const float* hidden  = (const float*)d_in[0];
    const float* W_qkvz  = (const float*)d_in[1];
    const float* W_ba    = (const float*)d_in[2];
    const float* convk   = (const float*)d_in[3];
    const float* A_log   = (const float*)d_in[4];
    const float* dt_bias = (const float*)d_in[5];
    const float* normw   = (const float*)d_in[6];
    const float* W_out   = (const float*)d_in[7];
    float* out = (float*)d_out;

    float *qkvz_p;
    __nv_bfloat16 *A1, *B1, *A2, *B2;
    cudaGetSymbolAddress((void**)&qkvz_p, g_qkvz);
    cudaGetSymbolAddress((void**)&A1, g_A1);
    cudaGetSymbolAddress((void**)&B1, g_B1);
    cudaGetSymbolAddress((void**)&A2, g_A2);
    cudaGetSymbolAddress((void**)&B2, g_B2);

    cudaFuncSetAttribute(precompute_kernel,
                         cudaFuncAttributeMaxDynamicSharedMemorySize, 99584);
    cudaFuncSetAttribute(scan_kernel,
                         cudaFuncAttributeMaxDynamicSharedMemorySize, 205312);
    cudaFuncSetAttribute(gemm_mma,
                         cudaFuncAttributeMaxDynamicSharedMemorySize, 3*GSTAGE);

    /* conversions for GEMM1 + static W_out for GEMM2 */
    cvtA<<<(SEQ*EMB)/512, 256>>>(hidden, A1, 11);              /* K=2048 */
    cvtBt<<<dim3(EMB/64, QKVZ_N/32), 256>>>(W_qkvz, B1, EMB, QKVZ_N);
    cvtBt<<<dim3(4096/64, EMB/32), 256>>>(W_out, B2, 4096, EMB);

    /* 1. qkvz = hidden @ W_qkvz  (bf16x3 mma.sync, K'=6144) */
    gemm_mma<<<dim3(QKVZ_N/128, SEQ/128), 256, 3*GSTAGE>>>(A1, B1, qkvz_p, 3*EMB, QKVZ_N);
    /* 2. ba */
    ba_gemm<<<256, 256>>>(hidden, W_ba);
    /* 3. conv + silu (float4) */
    conv_silu<<<(SEQ*CONV_DIM)/1024, 256>>>(convk);
    /* 4. gates */
    gates_kernel<<<dim3(NC, NVH), 64>>>(A_log, dt_bias);
    /* 5. precompute */
    precompute_kernel<<<dim3(NC, NVH), 256, 99584>>>();
    /* 6. scan (f32x2 + cp.async prefetch) */
    scan_kernel<<<dim3(4, NVH), 256, 205312>>>();
    /* 7. rmsnorm + A2 emission (fused) */
    rmsnorm_kernel<<<(SEQ*NVH)/8, 256>>>(normw);
    /* 8. out = xf @ W_out  (bf16x3 mma.sync, K'=12288) */
    gemm_mma<<<dim3(EMB/128, SEQ/128), 256, 3*GSTAGE>>>(A2, B2, out, 3*4096, EMB);
}

// round 14
// speedup vs baseline: 2.4486x; 1.0080x over previous
#include <cuda_runtime.h>
#include <cuda_bf16.h>
#include <math.h>
#include <stdint.h>

#define SEQ 4096
#define EMB 2048
#define NKH 16
#define NVH 32
#define DK 128
#define DV 128
#define CHUNK 64
#define NC (SEQ/CHUNK)      /* 64 */
#define QKVZ_N 12288
#define CONV_DIM 8192
#define QSCALE 0.08838834764831845f  /* 1/sqrt(128) */

/* single shared dynamic-smem symbol for all kernels */
extern __shared__ char dynsm[];

/* ---------------- scratch (device globals; no allocs allowed) ------------- */
__device__ float g_qkvz[(size_t)SEQ*QKVZ_N];            /* 192 MiB */
__device__ float g_ba[SEQ*64];
__device__ float g_qc[(size_t)SEQ*2048];
__device__ float g_kc[(size_t)SEQ*2048];
__device__ float g_vc[(size_t)SEQ*4096];
__device__ float g_beta[NVH*SEQ];
__device__ float g_gcum[NVH*SEQ];
__device__ float g_attnA[(size_t)NVH*NC*CHUNK*CHUNK];
__device__ float g_vintra[(size_t)NVH*SEQ*DV];
__device__ float g_kcd[(size_t)NVH*SEQ*DK];
__device__ float g_core[(size_t)SEQ*NVH*DV];

/* split-bf16 extended-K operands: A'=[Ah|Ah|Al] (MxK'), B'^T=[Bh|Bl|Bh] (NxK') */
__device__ __nv_bfloat16 g_A1[(size_t)SEQ*3*EMB];        /* 4096 x 6144  */
__device__ __nv_bfloat16 g_B1[(size_t)QKVZ_N*3*EMB];     /* 12288 x 6144 */
__device__ __nv_bfloat16 g_A2[(size_t)SEQ*3*4096];       /* 4096 x 12288 */
__device__ __nv_bfloat16 g_B2[(size_t)EMB*3*4096];       /* 2048 x 12288 */

/* ======================= asm helpers ===================================== */
__device__ __forceinline__ uint32_t smem_u32(const void* p) {
    uint32_t a;
    asm("{ .reg .u64 t; cvta.to.shared.u64 t, %1; cvt.u32.u64 %0, t; }" : "=r"(a) : "l"(p));
    return a;
}
#define CP_ASYNC16(sa, ga) \
    asm volatile("cp.async.cg.shared.global [%0], [%1], 16;" :: "r"(sa), "l"(ga))
#define CP_COMMIT() asm volatile("cp.async.commit_group;")
#define CP_WAIT1()  asm volatile("cp.async.wait_group 1;")
#define CP_WAIT0()  asm volatile("cp.async.wait_group 0;")
#define LDSM4(R, ad) \
    asm volatile("ldmatrix.sync.aligned.m8n8.x4.shared.b16 {%0,%1,%2,%3}, [%4];" \
        : "=r"((R)[0]), "=r"((R)[1]), "=r"((R)[2]), "=r"((R)[3]) : "r"(ad))
#define MMA16816(c, a, b0, b1) \
    asm volatile("mma.sync.aligned.m16n8k16.row.col.f32.bf16.bf16.f32 " \
        "{%0,%1,%2,%3}, {%4,%5,%6,%7}, {%8,%9}, {%0,%1,%2,%3};" \
        : "+f"((c)[0]), "+f"((c)[1]), "+f"((c)[2]), "+f"((c)[3]) \
        : "r"((a)[0]), "r"((a)[1]), "r"((a)[2]), "r"((a)[3]), "r"(b0), "r"(b1))

/* packed f32x2 fma: c += a*b componentwise (Blackwell, base sm_100+ feature) */
__device__ __forceinline__ void ffma2(float2& c, float2 a, float2 b) {
    asm("fma.rn.f32x2 %0, %1, %2, %0;"
        : "+l"(*reinterpret_cast<unsigned long long*>(&c))
        : "l"(*reinterpret_cast<unsigned long long*>(&a)),
          "l"(*reinterpret_cast<unsigned long long*>(&b)));
}

__device__ __forceinline__ __nv_bfloat162 split_hi2(float a, float b,
                                                    float& la, float& lb) {
    __nv_bfloat16 ha = __float2bfloat16(a), hb = __float2bfloat16(b);
    la = a - __bfloat162float(ha);
    lb = b - __bfloat162float(hb);
    return __halves2bfloat162(ha, hb);
}

/* ======================= split-bf16 conversions ========================== */
__global__ void cvtA(const float* __restrict__ src, __nv_bfloat16* __restrict__ dst,
                     int kbits) {
    size_t idx = ((size_t)blockIdx.x*256 + threadIdx.x)*2;
    int K = 1 << kbits;
    int m = (int)(idx >> kbits), k = (int)(idx & (K - 1));
    float2 v = *(const float2*)&src[idx];
    float l0, l1;
    __nv_bfloat162 hh = split_hi2(v.x, v.y, l0, l1);
    __nv_bfloat162 ll = __halves2bfloat162(__float2bfloat16(l0), __float2bfloat16(l1));
    size_t base = (((size_t)m*3) << kbits) + k;
    *(__nv_bfloat162*)&dst[base]       = hh;
    *(__nv_bfloat162*)&dst[base + K]   = hh;
    *(__nv_bfloat162*)&dst[base + 2*K] = ll;
}
__global__ __launch_bounds__(256)
void cvtBt(const float* __restrict__ W, __nv_bfloat16* __restrict__ dst,
           int K, int N) {
    __shared__ float t[64][33];
    int k0 = blockIdx.x*64, n0 = blockIdx.y*32;
    int tid = threadIdx.x;
    int tx = tid & 31, tw = tid >> 5;
#pragma unroll
    for (int i = 0; i < 8; i++) {
        int row = tw + i*8;
        t[row][tx] = W[(size_t)(k0+row)*N + n0 + tx];
    }
    __syncthreads();
#pragma unroll
    for (int i = 0; i < 4; i++) {
        int nc = tw*4 + i;
        float v0 = t[tx*2][nc];
        float v1 = t[tx*2+1][nc];
        float l0, l1;
        __nv_bfloat162 hh = split_hi2(v0, v1, l0, l1);
        __nv_bfloat162 ll = __halves2bfloat162(__float2bfloat16(l0), __float2bfloat16(l1));
        size_t base = (size_t)(n0 + nc)*3*K + k0 + tx*2;
        *(__nv_bfloat162*)&dst[base]       = hh;
        *(__nv_bfloat162*)&dst[base + K]   = ll;
        *(__nv_bfloat162*)&dst[base + 2*K] = hh;
    }
}

/* ======================= bf16 mma.sync GEMM (unchanged) ================== */
#define GSTAGE 32768
__global__ __launch_bounds__(256, 2)
void gemm_mma(const __nv_bfloat16* __restrict__ A, const __nv_bfloat16* __restrict__ B,
              float* __restrict__ C, int Kp, int N) {
    const int tid = threadIdx.x, lane = tid & 31, wid = tid >> 5;
    const int wm = wid & 1, wn = wid >> 1;
    int bid = blockIdx.y * gridDim.x + blockIdx.x;
    int nb = gridDim.x;
    int gsz = nb << 3;
    int grp = bid / gsz;
    int rem = bid - grp*gsz;
    const int m0 = (grp*8 + (rem & 7))*128;
    const int n0 = (rem >> 3)*128;
    const uint32_t sbase = smem_u32(dynsm);
    const int S = Kp >> 6;

    float acc[4][4][4];
#pragma unroll
    for (int mi = 0; mi < 4; mi++)
#pragma unroll
        for (int ni = 0; ni < 4; ni++)
#pragma unroll
            for (int e = 0; e < 4; e++) acc[mi][ni][e] = 0.f;

    int cr[4], cc[4];
    uint32_t sOffA[4];
#pragma unroll
    for (int i = 0; i < 4; i++) {
        int id = tid + (i << 8);
        cr[i] = id >> 3; cc[i] = id & 7;
        sOffA[i] = cr[i]*128 + ((cc[i] ^ (cr[i] & 7)) << 4);
    }

    auto issue_stage = [&](int t, int buf) {
        uint32_t stb = sbase + buf*GSTAGE;
#pragma unroll
        for (int i = 0; i < 4; i++) {
            const __nv_bfloat16* g = A + (size_t)(m0 + cr[i])*Kp + t*64 + (cc[i] << 3);
            CP_ASYNC16(stb + sOffA[i], g);
        }
#pragma unroll
        for (int i = 0; i < 4; i++) {
            const __nv_bfloat16* g = B + (size_t)(n0 + cr[i])*Kp + t*64 + (cc[i] << 3);
            CP_ASYNC16(stb + 16384 + sOffA[i], g);
        }
    };

    issue_stage(0, 0); CP_COMMIT();
    issue_stage(1, 1); CP_COMMIT();

    int rowA[4], swzA[4], rowB[2], swzB[2];
#pragma unroll
    for (int mi = 0; mi < 4; mi++) {
        rowA[mi] = wm*64 + mi*16 + (lane & 15);
        swzA[mi] = rowA[mi] & 7;
    }
#pragma unroll
    for (int ni2 = 0; ni2 < 2; ni2++) {
        rowB[ni2] = wn*32 + ni2*16 + ((lane >> 4) << 3) + (lane & 7);
        swzB[ni2] = rowB[ni2] & 7;
    }
    const int hiA = lane >> 4;
    const int hiB = (lane >> 3) & 1;

    auto do_stage = [&](int s, int bufc) {
        CP_WAIT1();
        __syncthreads();
        if (s + 2 < S) issue_stage(s + 2, (bufc + 2) % 3);
        CP_COMMIT();

        uint32_t sA = sbase + bufc*GSTAGE;
        uint32_t sB = sA + 16384;
#pragma unroll
        for (int kk = 0; kk < 4; kk++) {
            uint32_t a[4][4];
#pragma unroll
            for (int mi = 0; mi < 4; mi++) {
                uint32_t ad = sA + rowA[mi]*128 + ((((kk << 1) | hiA) ^ swzA[mi]) << 4);
                LDSM4(a[mi], ad);
            }
            uint32_t b[2][4];
#pragma unroll
            for (int ni2 = 0; ni2 < 2; ni2++) {
                uint32_t ad = sB + rowB[ni2]*128 + ((((kk << 1) | hiB) ^ swzB[ni2]) << 4);
                LDSM4(b[ni2], ad);
            }
#pragma unroll
            for (int mi = 0; mi < 4; mi++)
#pragma unroll
                for (int ni = 0; ni < 4; ni++)
                    MMA16816(acc[mi][ni], a[mi], b[ni >> 1][(ni & 1)*2], b[ni >> 1][(ni & 1)*2 + 1]);
        }
    };

    int s = 0;
    for (; s + 3 <= S; s += 3) { do_stage(s, 0); do_stage(s + 1, 1); do_stage(s + 2, 2); }
    for (; s < S; s++) do_stage(s, s % 3);

    const int g = lane >> 2, tg = lane & 3;
#pragma unroll
    for (int mi = 0; mi < 4; mi++) {
#pragma unroll
        for (int ni = 0; ni < 4; ni++) {
            int row = m0 + wm*64 + mi*16 + g;
            int col = n0 + wn*32 + ni*8 + (tg << 1);
            *(float2*)&C[(size_t)row*N + col]     = make_float2(acc[mi][ni][0], acc[mi][ni][1]);
            *(float2*)&C[(size_t)(row+8)*N + col] = make_float2(acc[mi][ni][2], acc[mi][ni][3]);
        }
    }
}

/* ---------------- ba = hidden @ W_ba : M=4096, K=2048, N=64 --------------- */
__global__ __launch_bounds__(256)
void ba_gemm(const float* __restrict__ A, const float* __restrict__ B) {
    int c = threadIdx.x & 63;
    int rl = threadIdx.x >> 6;
    int row0 = blockIdx.x*16 + rl*4;
    float acc[4] = {0,0,0,0};
#pragma unroll 4
    for (int k4 = 0; k4 < 512; k4++) {
        int k = k4 << 2;
        float b0 = __ldg(&B[(k+0)*64 + c]);
        float b1 = __ldg(&B[(k+1)*64 + c]);
        float b2 = __ldg(&B[(k+2)*64 + c]);
        float b3 = __ldg(&B[(k+3)*64 + c]);
#pragma unroll
        for (int r = 0; r < 4; r++) {
            float4 a = *(const float4*)&A[(size_t)(row0+r)*2048 + k];
            acc[r] += a.x*b0 + a.y*b1 + a.z*b2 + a.w*b3;
        }
    }
#pragma unroll
    for (int r = 0; r < 4; r++) g_ba[(size_t)(row0+r)*64 + c] = acc[r];
}

/* ---------------- depthwise causal conv (ksz=4) + SiLU, float4 ----------- */
__global__ void conv_silu(const float* __restrict__ cw) {
    int idx = (blockIdx.x*blockDim.x + threadIdx.x)*4;
    int s = idx >> 13;
    int c = idx & 8191;
    int col;
    if (c < 2048)      { int kh = c >> 7, d = c & 127;       col = kh*768 + d; }
    else if (c < 4096) { int c2 = c-2048; int kh = c2 >> 7;  col = kh*768 + 128 + (c2 & 127); }
    else               { int c2 = c-4096; int h16 = c2 >> 8; col = h16*768 + 256 + (c2 & 255); }
    float4 acc = make_float4(0.f, 0.f, 0.f, 0.f);
#pragma unroll
    for (int j = 0; j < 4; j++) {
        int t = s - 3 + j;
        if (t >= 0) {
            float4 x = *(const float4*)&g_qkvz[(size_t)t*QKVZ_N + col];
            float4 w = *(const float4*)&cw[j*CONV_DIM + c];
            acc.x += x.x*w.x; acc.y += x.y*w.y; acc.z += x.z*w.z; acc.w += x.w*w.w;
        }
    }
    float4 r;
    r.x = acc.x / (1.f + __expf(-acc.x));
    r.y = acc.y / (1.f + __expf(-acc.y));
    r.z = acc.z / (1.f + __expf(-acc.z));
    r.w = acc.w / (1.f + __expf(-acc.w));
    if (c < 2048) {
        r.x *= QSCALE; r.y *= QSCALE; r.z *= QSCALE; r.w *= QSCALE;
        *(float4*)&g_qc[(size_t)s*2048 + c] = r;
    } else if (c < 4096) {
        *(float4*)&g_kc[(size_t)s*2048 + (c-2048)] = r;
    } else {
        *(float4*)&g_vc[(size_t)s*4096 + (c-4096)] = r;
    }
}

/* ---------------- beta, g, cumsum(g) within chunk ------------------------- */
__global__ void gates_kernel(const float* __restrict__ A_log,
                             const float* __restrict__ dt_bias) {
    int chunk = blockIdx.x, hv = blockIdx.y, t = threadIdx.x;
    int s = chunk*CHUNK + t;
    int base = ((hv >> 1) << 2) + (hv & 1);
    float bg = g_ba[(size_t)s*64 + base];
    float ag = g_ba[(size_t)s*64 + base + 2];
    g_beta[hv*SEQ + s] = 1.f / (1.f + expf(-bg));
    float x = ag + dt_bias[hv];
    float sp = (x > 20.f) ? x : log1pf(expf(x));
    float g = -expf(A_log[hv]) * sp;
    __shared__ float sh[64];
    sh[t] = g;
    __syncthreads();
    for (int off = 1; off < 64; off <<= 1) {
        float v = (t >= off) ? sh[t-off] : 0.f;
        __syncthreads();
        sh[t] += v;
        __syncthreads();
    }
    g_gcum[hv*SEQ + s] = sh[t];
}

/* ------------- per (head, chunk) parallel precompute ----------------------
   f32x2 FFMA + float4 row loads; k/v tiles padded to stride 132.           */
#define KSTR 132
__global__ __launch_bounds__(256, 2)
void precompute_kernel() {
    float* sm    = (float*)dynsm;
    float* ks    = sm;                  /* 64*132 */
    float* vs    = ks + 64*KSTR;        /* q, then v */
    float* Ls    = vs + 64*KSTR;        /* 4096 */
    float* Xs    = Ls + 4096;           /* 4096 */
    float* betas = Xs + 4096;
    float* gcs   = betas + 64;
    float* bgm   = gcs + 64;
    const int c = blockIdx.x, hv = blockIdx.y, kh = hv >> 1;
    const int tid = threadIdx.x;
    const int ti = tid >> 4, tj = tid & 15;

    for (int l = tid; l < 2048; l += 256) {
        int row = l >> 5, c4 = (l & 31) << 2;
        *(float4*)&ks[row*KSTR + c4] =
            *(const float4*)&g_kc[(size_t)(c*CHUNK+row)*2048 + kh*128 + c4];
    }
    if (tid < 64) {
        int s = c*CHUNK + tid;
        betas[tid] = g_beta[hv*SEQ + s];
        gcs[tid]   = g_gcum[hv*SEQ + s];
    }
    __syncthreads();
    if (tid < 64) bgm[tid] = betas[tid]*expf(gcs[tid]);

    /* L: 4x4 tile, d-pairs in f32x2, float4 row loads */
    {
        float2 accP[4][4];
#pragma unroll
        for (int r = 0; r < 4; r++)
#pragma unroll
            for (int q = 0; q < 4; q++) accP[r][q] = make_float2(0.f, 0.f);
        for (int d4 = 0; d4 < 128; d4 += 4) {
            float4 a4[4], b4[4];
#pragma unroll
            for (int r = 0; r < 4; r++) a4[r] = *(float4*)&ks[(ti*4+r)*KSTR + d4];
#pragma unroll
            for (int q = 0; q < 4; q++) b4[q] = *(float4*)&ks[(tj*4+q)*KSTR + d4];
#pragma unroll
            for (int r = 0; r < 4; r++)
#pragma unroll
                for (int q = 0; q < 4; q++) {
                    ffma2(accP[r][q], make_float2(a4[r].x, a4[r].y), make_float2(b4[q].x, b4[q].y));
                    ffma2(accP[r][q], make_float2(a4[r].z, a4[r].w), make_float2(b4[q].z, b4[q].w));
                }
        }
#pragma unroll
        for (int r = 0; r < 4; r++) {
            int i = ti*4 + r;
#pragma unroll
            for (int q = 0; q < 4; q++) {
                int j = tj*4 + q;
                float dot = accP[r][q].x + accP[r][q].y;
                Ls[i*64 + j] = (i > j) ? -betas[i]*dot*expf(gcs[i]-gcs[j]) : 0.f;
            }
        }
    }
    __syncthreads();

    /* load q into vs; fwd substitution on 64 threads */
    for (int l = tid; l < 2048; l += 256) {
        int row = l >> 5, c4 = (l & 31) << 2;
        *(float4*)&vs[row*KSTR + c4] =
            *(const float4*)&g_qc[(size_t)(c*CHUNK+row)*2048 + kh*128 + c4];
    }
    if (tid < 64) {
        int j = tid;
        for (int i = 0; i < 64; i++) {
            float acc = (i == j) ? 1.f : 0.f;
            for (int m = 0; m < i; m++) acc += Ls[i*64+m]*Xs[m*64+j];
            Xs[i*64+j] = acc;
        }
    }
    __syncthreads();

    /* attnA: q_i . k_j, same f32x2 scheme */
    {
        float2 accP[4][4];
#pragma unroll
        for (int r = 0; r < 4; r++)
#pragma unroll
            for (int q = 0; q < 4; q++) accP[r][q] = make_float2(0.f, 0.f);
        for (int d4 = 0; d4 < 128; d4 += 4) {
            float4 a4[4], b4[4];
#pragma unroll
            for (int r = 0; r < 4; r++) a4[r] = *(float4*)&vs[(ti*4+r)*KSTR + d4];
#pragma unroll
            for (int q = 0; q < 4; q++) b4[q] = *(float4*)&ks[(tj*4+q)*KSTR + d4];
#pragma unroll
            for (int r = 0; r < 4; r++)
#pragma unroll
                for (int q = 0; q < 4; q++) {
                    ffma2(accP[r][q], make_float2(a4[r].x, a4[r].y), make_float2(b4[q].x, b4[q].y));
                    ffma2(accP[r][q], make_float2(a4[r].z, a4[r].w), make_float2(b4[q].z, b4[q].w));
                }
        }
        size_t outb = (size_t)(hv*NC + c)*4096;
#pragma unroll
        for (int r = 0; r < 4; r++) {
            int i = ti*4 + r;
#pragma unroll
            for (int q = 0; q < 4; q++) {
                int j = tj*4 + q;
                float dot = accP[r][q].x + accP[r][q].y;
                g_attnA[outb + i*64 + j] = (i >= j) ? dot*expf(gcs[i]-gcs[j]) : 0.f;
            }
        }
    }
    __syncthreads();

    /* overwrite vs with v chunk */
    for (int l = tid; l < 2048; l += 256) {
        int row = l >> 5, c4 = (l & 31) << 2;
        *(float4*)&vs[row*KSTR + c4] =
            *(const float4*)&g_vc[(size_t)(c*CHUNK+row)*4096 + hv*128 + c4];
    }
    __syncthreads();

    /* kcd/vintra: q-pairs in f32x2 */
    {
        const int iq = tid >> 5;
        const int ln = tid & 31;
        const int i0 = iq*8;
        float2 aK[8][2], aV[8][2];
#pragma unroll
        for (int r = 0; r < 8; r++)
#pragma unroll
            for (int q = 0; q < 2; q++) { aK[r][q] = make_float2(0.f, 0.f); aV[r][q] = make_float2(0.f, 0.f); }
        for (int m = 0; m < 64; m++) {
            float bg = bgm[m], bt = betas[m];
            float2 k01 = make_float2(ks[m*KSTR + ln],      ks[m*KSTR + ln + 32]);
            float2 k23 = make_float2(ks[m*KSTR + ln + 64], ks[m*KSTR + ln + 96]);
            float2 v01 = make_float2(vs[m*KSTR + ln],      vs[m*KSTR + ln + 32]);
            float2 v23 = make_float2(vs[m*KSTR + ln + 64], vs[m*KSTR + ln + 96]);
#pragma unroll
            for (int r = 0; r < 8; r++) {
                float x  = Xs[(i0+r)*64 + m];
                float2 xb2 = make_float2(x*bg, x*bg);
                float2 xv2 = make_float2(x*bt, x*bt);
                ffma2(aK[r][0], k01, xb2);
                ffma2(aK[r][1], k23, xb2);
                ffma2(aV[r][0], v01, xv2);
                ffma2(aV[r][1], v23, xv2);
            }
        }
        size_t ob = (size_t)(hv*NC + c)*CHUNK*128;
#pragma unroll
        for (int r = 0; r < 8; r++) {
            size_t o = ob + (size_t)(i0+r)*128 + ln;
            g_kcd[o]       = aK[r][0].x;  g_kcd[o + 32]   = aK[r][0].y;
            g_kcd[o + 64]  = aK[r][1].x;  g_kcd[o + 96]   = aK[r][1].y;
            g_vintra[o]      = aV[r][0].x;  g_vintra[o + 32] = aV[r][0].y;
            g_vintra[o + 64] = aV[r][1].x;  g_vintra[o + 96] = aV[r][1].y;
        }
    }
}
#define PRE_SMEM ((2*64*KSTR + 4096*2 + 192)*4)

/* ------------- sequential inter-chunk scan: f32x2 + float4 broadcast ------ */
__global__ __launch_bounds__(256)
void scan_kernel() {
    float* smf     = (float*)dynsm;
    float2* statev = (float2*)smf;
    float* qs      = smf + 4096;
    float* ksm     = smf + 12288;
    float* vnf     = smf + 49152;
    float2* vn2    = (float2*)vnf;
    float* gcs     = smf + 51200;
    float* wexp    = smf + 51264;
    const uint32_t sb = smem_u32(dynsm);
    const int hv = blockIdx.y, j0 = blockIdx.x*32, kh = hv >> 1;
    const int tid = threadIdx.x, jj = tid & 31, ig = tid >> 5;
    const int i0 = ig*8;

    for (int l = tid; l < 2048; l += 256) statev[l] = make_float2(0.f, 0.f);
    __syncthreads();

    auto prefetch = [&](int c, int buf) {
        const size_t rb = (size_t)(hv*NC + c)*CHUNK;
        uint32_t kb = sb + (20480 + buf*8192)*4;
        const char* ks_src = (const char*)(g_kcd + rb*128);
        for (int i = tid; i < 2048; i += 256)
            CP_ASYNC16(kb + i*16, ks_src + i*16);
        uint32_t ab = sb + (36864 + buf*4096)*4;
        const char* as_src = (const char*)(g_attnA + rb*64);
        for (int i = tid; i < 1024; i += 256)
            CP_ASYNC16(ab + i*16, as_src + i*16);
        uint32_t vb = sb + (45056 + buf*2048)*4;
        for (int i = tid; i < 512; i += 256) {
            int row = i >> 3, off = (i & 7)*16;
            CP_ASYNC16(vb + row*128 + off,
                       (const char*)(g_vintra + (rb+row)*128 + j0) + off);
        }
    };

    prefetch(0, 0); CP_COMMIT();

    for (int c = 0; c < NC; c++) {
        const int cur = c & 1;
        float* kcds   = smf + 20480 + cur*8192;
        float* as_    = smf + 36864 + cur*4096;
        float* vnraw  = smf + 45056 + cur*2048;

        for (int l = tid; l < 2048; l += 256) {
            int row = l >> 5, c4 = (l & 31) << 2;
            *(float4*)&qs[row*128 + c4]  = *(const float4*)&g_qc[(size_t)(c*CHUNK+row)*2048 + kh*128 + c4];
            *(float4*)&ksm[row*128 + c4] = *(const float4*)&g_kc[(size_t)(c*CHUNK+row)*2048 + kh*128 + c4];
        }
        if (tid < 64) gcs[tid] = g_gcum[hv*SEQ + c*CHUNK + tid];
        CP_WAIT0();
        __syncthreads();
        if (c + 1 < NC) { prefetch(c + 1, cur ^ 1); }
        CP_COMMIT();
        if (tid < 64) wexp[tid] = expf(gcs[63] - gcs[tid]);

        /* step2: v_new = v_intra - kcd@state ; o_part = q@state */
        float2 kacc[8], qacc[8];
#pragma unroll
        for (int r = 0; r < 8; r++) {
            kacc[r] = make_float2(0.f, 0.f);
            qacc[r] = make_float2(0.f, 0.f);
        }
        for (int dp2 = 0; dp2 < 32; dp2++) {
            float2 sv0 = statev[(dp2*2)*32 + jj];
            float2 sv1 = statev[(dp2*2+1)*32 + jj];
#pragma unroll
            for (int r = 0; r < 8; r++) {
                float4 kq = *(float4*)&kcds[(i0+r)*128 + dp2*4];
                ffma2(kacc[r], make_float2(kq.x, kq.y), sv0);
                ffma2(kacc[r], make_float2(kq.z, kq.w), sv1);
                float4 qq = *(float4*)&qs[(i0+r)*128 + dp2*4];
                ffma2(qacc[r], make_float2(qq.x, qq.y), sv0);
                ffma2(qacc[r], make_float2(qq.z, qq.w), sv1);
            }
        }
        float vnew[8], oo[8];
#pragma unroll
        for (int r = 0; r < 8; r++) {
            vnew[r] = vnraw[(i0+r)*32 + jj] - (kacc[r].x + kacc[r].y);
            oo[r]   = (qacc[r].x + qacc[r].y) * expf(gcs[i0+r]);
        }
#pragma unroll
        for (int rp = 0; rp < 4; rp++)
            vn2[((i0 >> 1) + rp)*32 + jj] = make_float2(vnew[2*rp], vnew[2*rp+1]);
        __syncthreads();

        /* step3: out += a @ v_new */
        float2 oacc[8];
#pragma unroll
        for (int r = 0; r < 8; r++) oacc[r] = make_float2(0.f, 0.f);
        for (int mp2 = 0; mp2 < 16; mp2++) {
            float2 vv0 = vn2[(mp2*2)*32 + jj];
            float2 vv1 = vn2[(mp2*2+1)*32 + jj];
#pragma unroll
            for (int r = 0; r < 8; r++) {
                float4 aa = *(float4*)&as_[(i0+r)*64 + mp2*4];
                ffma2(oacc[r], make_float2(aa.x, aa.y), vv0);
                ffma2(oacc[r], make_float2(aa.z, aa.w), vv1);
            }
        }
#pragma unroll
        for (int r = 0; r < 8; r++) {
            float o = oo[r] + oacc[r].x + oacc[r].y;
            g_core[(size_t)(c*CHUNK + i0 + r)*4096 + hv*128 + j0 + jj] = o;
        }

        /* step4: state = state*e^glast + k'^T @ v_new */
        {
            float eg = expf(gcs[63]);
            float2 sacc[8];
#pragma unroll
            for (int dd = 0; dd < 8; dd++) {
                float2 sv = statev[(i0 + dd)*32 + jj];
                sacc[dd] = make_float2(sv.x*eg, sv.y*eg);
            }
            for (int i = 0; i < 64; i++) {
                float vw = wexp[i] * vnf[(i >> 1)*64 + jj*2 + (i & 1)];
                float2 vw2 = make_float2(vw, vw);
#pragma unroll
                for (int e = 0; e < 4; e++) {
                    float4 kk = *(float4*)&ksm[i*128 + i0*2 + e*4];
                    ffma2(sacc[2*e],   make_float2(kk.x, kk.y), vw2);
                    ffma2(sacc[2*e+1], make_float2(kk.z, kk.w), vw2);
                }
            }
#pragma unroll
            for (int dd = 0; dd < 8; dd++)
                statev[(i0 + dd)*32 + jj] = sacc[dd];
        }
        __syncthreads();
    }
}

/* ------- gated RMSNorm fused with split-bf16 A2 emission ------------------ */
__global__ void rmsnorm_kernel(const float* __restrict__ nw) {
    int gw = (blockIdx.x*blockDim.x + threadIdx.x) >> 5;
    int lane = threadIdx.x & 31;
    int s = gw >> 5;
    int hv = gw & 31;
    int d0 = lane*4;
    size_t zbase = (size_t)s*QKVZ_N + (hv >> 1)*768 + 512 + (hv & 1)*128 + d0;
    size_t cbase = (size_t)s*4096 + hv*128 + d0;
    float4 cv = *(const float4*)&g_core[cbase];
    float4 zv = *(const float4*)&g_qkvz[zbase];
    float x[4];
    x[0] = cv.x * (zv.x / (1.f + expf(-zv.x)));
    x[1] = cv.y * (zv.y / (1.f + expf(-zv.y)));
    x[2] = cv.z * (zv.z / (1.f + expf(-zv.z)));
    x[3] = cv.w * (zv.w / (1.f + expf(-zv.w)));
    float ss = x[0]*x[0] + x[1]*x[1] + x[2]*x[2] + x[3]*x[3];
#pragma unroll
    for (int off = 16; off; off >>= 1) ss += __shfl_xor_sync(0xffffffffu, ss, off);
    float inv = rsqrtf(ss*(1.f/128.f) + 1e-6f);
    float y[4];
#pragma unroll
    for (int r = 0; r < 4; r++) y[r] = x[r]*inv*nw[d0 + r];
    float l0, l1, l2, l3;
    __nv_bfloat162 h01 = split_hi2(y[0], y[1], l0, l1);
    __nv_bfloat162 h23 = split_hi2(y[2], y[3], l2, l3);
    __nv_bfloat162 l01 = __halves2bfloat162(__float2bfloat16(l0), __float2bfloat16(l1));
    __nv_bfloat162 l23 = __halves2bfloat162(__float2bfloat16(l2), __float2bfloat16(l3));
    size_t base = (size_t)s*12288 + hv*128 + d0;
    *(__nv_bfloat162*)&g_A2[base]          = h01;
    *(__nv_bfloat162*)&g_A2[base + 2]      = h23;
    *(__nv_bfloat162*)&g_A2[base + 4096]   = h01;
    *(__nv_bfloat162*)&g_A2[base + 4098]   = h23;
    *(__nv_bfloat162*)&g_A2[base + 8192]   = l01;
    *(__nv_bfloat162*)&g_A2[base + 8194]   = l23;
}

/* ---------------- launcher ------------------------------------------------ */
extern "C" void kernel_launch(void* const* d_in, const int* in_sizes, int n_in,
                              void* d_out, int out_size) {
    const float* hidden  = (const float*)d_in[0];
    const float* W_qkvz  = (const float*)d_in[1];
    const float* W_ba    = (const float*)d_in[2];
    const float* convk   = (const float*)d_in[3];
    const float* A_log   = (const float*)d_in[4];
    const float* dt_bias = (const float*)d_in[5];
    const float* normw   = (const float*)d_in[6];
    const float* W_out   = (const float*)d_in[7];
    float* out = (float*)d_out;

    float *qkvz_p;
    __nv_bfloat16 *A1, *B1, *A2, *B2;
    cudaGetSymbolAddress((void**)&qkvz_p, g_qkvz);
    cudaGetSymbolAddress((void**)&A1, g_A1);
    cudaGetSymbolAddress((void**)&B1, g_B1);
    cudaGetSymbolAddress((void**)&A2, g_A2);
    cudaGetSymbolAddress((void**)&B2, g_B2);

    cudaFuncSetAttribute(precompute_kernel,
                         cudaFuncAttributeMaxDynamicSharedMemorySize, PRE_SMEM);
    cudaFuncSetAttribute(scan_kernel,
                         cudaFuncAttributeMaxDynamicSharedMemorySize, 205312);
    cudaFuncSetAttribute(gemm_mma,
                         cudaFuncAttributeMaxDynamicSharedMemorySize, 3*GSTAGE);

    /* conversions for GEMM1 + static W_out for GEMM2 */
    cvtA<<<(SEQ*EMB)/512, 256>>>(hidden, A1, 11);              /* K=2048 */
    cvtBt<<<dim3(EMB/64, QKVZ_N/32), 256>>>(W_qkvz, B1, EMB, QKVZ_N);
    cvtBt<<<dim3(4096/64, EMB/32), 256>>>(W_out, B2, 4096, EMB);

    /* 1. qkvz = hidden @ W_qkvz  (bf16x3 mma.sync, K'=6144) */
    gemm_mma<<<dim3(QKVZ_N/128, SEQ/128), 256, 3*GSTAGE>>>(A1, B1, qkvz_p, 3*EMB, QKVZ_N);
    /* 2. ba */
    ba_gemm<<<256, 256>>>(hidden, W_ba);
    /* 3. conv + silu (float4) */
    conv_silu<<<(SEQ*CONV_DIM)/1024, 256>>>(convk);
    /* 4. gates */
    gates_kernel<<<dim3(NC, NVH), 64>>>(A_log, dt_bias);
    /* 5. precompute (f32x2) */
    precompute_kernel<<<dim3(NC, NVH), 256, PRE_SMEM>>>();
    /* 6. scan (f32x2 + float4 + cp.async prefetch) */
    scan_kernel<<<dim3(4, NVH), 256, 205312>>>();
    /* 7. rmsnorm + A2 emission (fused) */
    rmsnorm_kernel<<<(SEQ*NVH)/8, 256>>>(normw);
    /* 8. out = xf @ W_out  (bf16x3 mma.sync, K'=12288) */
    gemm_mma<<<dim3(EMB/128, SEQ/128), 256, 3*GSTAGE>>>(A2, B2, out, 3*4096, EMB);
}

// round 16
// speedup vs baseline: 2.7651x; 1.1292x over previous
#include <cuda_runtime.h>
#include <cuda_bf16.h>
#include <cuda_fp16.h>
#include <math.h>
#include <stdint.h>

#define SEQ 4096
#define EMB 2048
#define NKH 16
#define NVH 32
#define DK 128
#define DV 128
#define CHUNK 64
#define NC (SEQ/CHUNK)      /* 64 */
#define QKVZ_N 12288
#define CONV_DIM 8192
#define QSCALE 0.08838834764831845f  /* 1/sqrt(128) */

/* single shared dynamic-smem symbol for all kernels */
extern __shared__ char dynsm[];

/* ---------------- scratch (device globals; no allocs allowed) ------------- */
__device__ float g_qkvz[(size_t)SEQ*QKVZ_N];            /* 192 MiB */
__device__ float g_ba[SEQ*64];
__device__ float g_qc[(size_t)SEQ*2048];
__device__ float g_kc[(size_t)SEQ*2048];
__device__ float g_vc[(size_t)SEQ*4096];
__device__ float g_beta[NVH*SEQ];
__device__ float g_gcum[NVH*SEQ];
__device__ float g_attnA[(size_t)NVH*NC*CHUNK*CHUNK];
__device__ float g_vintra[(size_t)NVH*SEQ*DV];
__device__ float g_kcd[(size_t)NVH*SEQ*DK];
__device__ float g_core[(size_t)SEQ*NVH*DV];

/* GEMM1 operands: split-bf16 extended-K.  GEMM2 operands: plain fp16. */
__device__ __nv_bfloat16 g_A1[(size_t)SEQ*3*EMB];        /* 4096 x 6144  */
__device__ __nv_bfloat16 g_B1[(size_t)QKVZ_N*3*EMB];     /* 12288 x 6144 */
__device__ __half        g_A2h[(size_t)SEQ*4096];        /* 4096 x 4096  */
__device__ __half        g_B2h[(size_t)EMB*4096];        /* 2048 x 4096  */

/* ======================= asm helpers ===================================== */
__device__ __forceinline__ uint32_t smem_u32(const void* p) {
    uint32_t a;
    asm("{ .reg .u64 t; cvta.to.shared.u64 t, %1; cvt.u32.u64 %0, t; }" : "=r"(a) : "l"(p));
    return a;
}
#define CP_ASYNC16(sa, ga) \
    asm volatile("cp.async.cg.shared.global [%0], [%1], 16;" :: "r"(sa), "l"(ga))
#define CP_COMMIT() asm volatile("cp.async.commit_group;")
#define CP_WAIT1()  asm volatile("cp.async.wait_group 1;")
#define CP_WAIT0()  asm volatile("cp.async.wait_group 0;")
#define LDSM4(R, ad) \
    asm volatile("ldmatrix.sync.aligned.m8n8.x4.shared.b16 {%0,%1,%2,%3}, [%4];" \
        : "=r"((R)[0]), "=r"((R)[1]), "=r"((R)[2]), "=r"((R)[3]) : "r"(ad))
#define MMA16816B(c, a, b0, b1) \
    asm volatile("mma.sync.aligned.m16n8k16.row.col.f32.bf16.bf16.f32 " \
        "{%0,%1,%2,%3}, {%4,%5,%6,%7}, {%8,%9}, {%0,%1,%2,%3};" \
        : "+f"((c)[0]), "+f"((c)[1]), "+f"((c)[2]), "+f"((c)[3]) \
        : "r"((a)[0]), "r"((a)[1]), "r"((a)[2]), "r"((a)[3]), "r"(b0), "r"(b1))
#define MMA16816H(c, a, b0, b1) \
    asm volatile("mma.sync.aligned.m16n8k16.row.col.f32.f16.f16.f32 " \
        "{%0,%1,%2,%3}, {%4,%5,%6,%7}, {%8,%9}, {%0,%1,%2,%3};" \
        : "+f"((c)[0]), "+f"((c)[1]), "+f"((c)[2]), "+f"((c)[3]) \
        : "r"((a)[0]), "r"((a)[1]), "r"((a)[2]), "r"((a)[3]), "r"(b0), "r"(b1))

/* packed f32x2 fma: c += a*b componentwise (Blackwell, base sm_100+ feature) */
__device__ __forceinline__ void ffma2(float2& c, float2 a, float2 b) {
    asm("fma.rn.f32x2 %0, %1, %2, %0;"
        : "+l"(*reinterpret_cast<unsigned long long*>(&c))
        : "l"(*reinterpret_cast<unsigned long long*>(&a)),
          "l"(*reinterpret_cast<unsigned long long*>(&b)));
}

__device__ __forceinline__ __nv_bfloat162 split_hi2(float a, float b,
                                                    float& la, float& lb) {
    __nv_bfloat16 ha = __float2bfloat16(a), hb = __float2bfloat16(b);
    la = a - __bfloat162float(ha);
    lb = b - __bfloat162float(hb);
    return __halves2bfloat162(ha, hb);
}

/* ======================= conversions ===================================== */
/* A[M][K] fp32 -> A'[M][3K] bf16 = [hi | hi | lo] */
__global__ void cvtA(const float* __restrict__ src, __nv_bfloat16* __restrict__ dst,
                     int kbits) {
    size_t idx = ((size_t)blockIdx.x*256 + threadIdx.x)*2;
    int K = 1 << kbits;
    int m = (int)(idx >> kbits), k = (int)(idx & (K - 1));
    float2 v = *(const float2*)&src[idx];
    float l0, l1;
    __nv_bfloat162 hh = split_hi2(v.x, v.y, l0, l1);
    __nv_bfloat162 ll = __halves2bfloat162(__float2bfloat16(l0), __float2bfloat16(l1));
    size_t base = (((size_t)m*3) << kbits) + k;
    *(__nv_bfloat162*)&dst[base]       = hh;
    *(__nv_bfloat162*)&dst[base + K]   = hh;
    *(__nv_bfloat162*)&dst[base + 2*K] = ll;
}
/* W[K][N] fp32 -> B'[N][3K] bf16 = [hi | lo | hi] (transposed, split) */
__global__ __launch_bounds__(256)
void cvtBt(const float* __restrict__ W, __nv_bfloat16* __restrict__ dst,
           int K, int N) {
    __shared__ float t[64][33];
    int k0 = blockIdx.x*64, n0 = blockIdx.y*32;
    int tid = threadIdx.x;
    int tx = tid & 31, tw = tid >> 5;
#pragma unroll
    for (int i = 0; i < 8; i++) {
        int row = tw + i*8;
        t[row][tx] = W[(size_t)(k0+row)*N + n0 + tx];
    }
    __syncthreads();
#pragma unroll
    for (int i = 0; i < 4; i++) {
        int nc = tw*4 + i;
        float v0 = t[tx*2][nc];
        float v1 = t[tx*2+1][nc];
        float l0, l1;
        __nv_bfloat162 hh = split_hi2(v0, v1, l0, l1);
        __nv_bfloat162 ll = __halves2bfloat162(__float2bfloat16(l0), __float2bfloat16(l1));
        size_t base = (size_t)(n0 + nc)*3*K + k0 + tx*2;
        *(__nv_bfloat162*)&dst[base]       = hh;
        *(__nv_bfloat162*)&dst[base + K]   = ll;
        *(__nv_bfloat162*)&dst[base + 2*K] = hh;
    }
}
/* W[K][N] fp32 -> B[N][K] fp16 (transposed, single) */
__global__ __launch_bounds__(256)
void cvtBth(const float* __restrict__ W, __half* __restrict__ dst,
            int K, int N) {
    __shared__ float t[64][33];
    int k0 = blockIdx.x*64, n0 = blockIdx.y*32;
    int tid = threadIdx.x;
    int tx = tid & 31, tw = tid >> 5;
#pragma unroll
    for (int i = 0; i < 8; i++) {
        int row = tw + i*8;
        t[row][tx] = W[(size_t)(k0+row)*N + n0 + tx];
    }
    __syncthreads();
#pragma unroll
    for (int i = 0; i < 4; i++) {
        int nc = tw*4 + i;
        __half2 h = __floats2half2_rn(t[tx*2][nc], t[tx*2+1][nc]);
        *(__half2*)&dst[(size_t)(n0 + nc)*K + k0 + tx*2] = h;
    }
}

/* ======================= 16-bit mma.sync GEMM ============================
   MODE 0 = bf16, MODE 1 = fp16.  3-stage cp.async (96KB), 2 CTAs/SM,
   8-row CTA swizzle, stage loop unrolled by 3.                            */
#define GSTAGE 32768
template<int MODE>
__global__ __launch_bounds__(256, 2)
void gemm_mma(const __nv_bfloat16* __restrict__ A, const __nv_bfloat16* __restrict__ B,
              float* __restrict__ C, int Kp, int N) {
    const int tid = threadIdx.x, lane = tid & 31, wid = tid >> 5;
    const int wm = wid & 1, wn = wid >> 1;
    int bid = blockIdx.y * gridDim.x + blockIdx.x;
    int nb = gridDim.x;
    int gsz = nb << 3;
    int grp = bid / gsz;
    int rem = bid - grp*gsz;
    const int m0 = (grp*8 + (rem & 7))*128;
    const int n0 = (rem >> 3)*128;
    const uint32_t sbase = smem_u32(dynsm);
    const int S = Kp >> 6;

    float acc[4][4][4];
#pragma unroll
    for (int mi = 0; mi < 4; mi++)
#pragma unroll
        for (int ni = 0; ni < 4; ni++)
#pragma unroll
            for (int e = 0; e < 4; e++) acc[mi][ni][e] = 0.f;

    int cr[4], cc[4];
    uint32_t sOffA[4];
#pragma unroll
    for (int i = 0; i < 4; i++) {
        int id = tid + (i << 8);
        cr[i] = id >> 3; cc[i] = id & 7;
        sOffA[i] = cr[i]*128 + ((cc[i] ^ (cr[i] & 7)) << 4);
    }

    auto issue_stage = [&](int t, int buf) {
        uint32_t stb = sbase + buf*GSTAGE;
#pragma unroll
        for (int i = 0; i < 4; i++) {
            const __nv_bfloat16* g = A + (size_t)(m0 + cr[i])*Kp + t*64 + (cc[i] << 3);
            CP_ASYNC16(stb + sOffA[i], g);
        }
#pragma unroll
        for (int i = 0; i < 4; i++) {
            const __nv_bfloat16* g = B + (size_t)(n0 + cr[i])*Kp + t*64 + (cc[i] << 3);
            CP_ASYNC16(stb + 16384 + sOffA[i], g);
        }
    };

    issue_stage(0, 0); CP_COMMIT();
    issue_stage(1, 1); CP_COMMIT();

    int rowA[4], swzA[4], rowB[2], swzB[2];
#pragma unroll
    for (int mi = 0; mi < 4; mi++) {
        rowA[mi] = wm*64 + mi*16 + (lane & 15);
        swzA[mi] = rowA[mi] & 7;
    }
#pragma unroll
    for (int ni2 = 0; ni2 < 2; ni2++) {
        rowB[ni2] = wn*32 + ni2*16 + ((lane >> 4) << 3) + (lane & 7);
        swzB[ni2] = rowB[ni2] & 7;
    }
    const int hiA = lane >> 4;
    const int hiB = (lane >> 3) & 1;

    auto do_stage = [&](int s, int bufc) {
        CP_WAIT1();
        __syncthreads();
        if (s + 2 < S) issue_stage(s + 2, (bufc + 2) % 3);
        CP_COMMIT();

        uint32_t sA = sbase + bufc*GSTAGE;
        uint32_t sB = sA + 16384;
#pragma unroll
        for (int kk = 0; kk < 4; kk++) {
            uint32_t a[4][4];
#pragma unroll
            for (int mi = 0; mi < 4; mi++) {
                uint32_t ad = sA + rowA[mi]*128 + ((((kk << 1) | hiA) ^ swzA[mi]) << 4);
                LDSM4(a[mi], ad);
            }
            uint32_t b[2][4];
#pragma unroll
            for (int ni2 = 0; ni2 < 2; ni2++) {
                uint32_t ad = sB + rowB[ni2]*128 + ((((kk << 1) | hiB) ^ swzB[ni2]) << 4);
                LDSM4(b[ni2], ad);
            }
#pragma unroll
            for (int mi = 0; mi < 4; mi++)
#pragma unroll
                for (int ni = 0; ni < 4; ni++) {
                    if (MODE == 0) {
                        MMA16816B(acc[mi][ni], a[mi], b[ni >> 1][(ni & 1)*2], b[ni >> 1][(ni & 1)*2 + 1]);
                    } else {
                        MMA16816H(acc[mi][ni], a[mi], b[ni >> 1][(ni & 1)*2], b[ni >> 1][(ni & 1)*2 + 1]);
                    }
                }
        }
    };

    int s = 0;
    for (; s + 3 <= S; s += 3) { do_stage(s, 0); do_stage(s + 1, 1); do_stage(s + 2, 2); }
    for (; s < S; s++) do_stage(s, s % 3);

    const int g = lane >> 2, tg = lane & 3;
#pragma unroll
    for (int mi = 0; mi < 4; mi++) {
#pragma unroll
        for (int ni = 0; ni < 4; ni++) {
            int row = m0 + wm*64 + mi*16 + g;
            int col = n0 + wn*32 + ni*8 + (tg << 1);
            *(float2*)&C[(size_t)row*N + col]     = make_float2(acc[mi][ni][0], acc[mi][ni][1]);
            *(float2*)&C[(size_t)(row+8)*N + col] = make_float2(acc[mi][ni][2], acc[mi][ni][3]);
        }
    }
}

/* ---------------- ba = hidden @ W_ba : M=4096, K=2048, N=64 --------------- */
__global__ __launch_bounds__(256)
void ba_gemm(const float* __restrict__ A, const float* __restrict__ B) {
    int c = threadIdx.x & 63;
    int rl = threadIdx.x >> 6;
    int row0 = blockIdx.x*16 + rl*4;
    float acc[4] = {0,0,0,0};
#pragma unroll 4
    for (int k4 = 0; k4 < 512; k4++) {
        int k = k4 << 2;
        float b0 = __ldg(&B[(k+0)*64 + c]);
        float b1 = __ldg(&B[(k+1)*64 + c]);
        float b2 = __ldg(&B[(k+2)*64 + c]);
        float b3 = __ldg(&B[(k+3)*64 + c]);
#pragma unroll
        for (int r = 0; r < 4; r++) {
            float4 a = *(const float4*)&A[(size_t)(row0+r)*2048 + k];
            acc[r] += a.x*b0 + a.y*b1 + a.z*b2 + a.w*b3;
        }
    }
#pragma unroll
    for (int r = 0; r < 4; r++) g_ba[(size_t)(row0+r)*64 + c] = acc[r];
}

/* ---------------- depthwise causal conv (ksz=4) + SiLU, float4 ----------- */
__global__ void conv_silu(const float* __restrict__ cw) {
    int idx = (blockIdx.x*blockDim.x + threadIdx.x)*4;
    int s = idx >> 13;
    int c = idx & 8191;
    int col;
    if (c < 2048)      { int kh = c >> 7, d = c & 127;       col = kh*768 + d; }
    else if (c < 4096) { int c2 = c-2048; int kh = c2 >> 7;  col = kh*768 + 128 + (c2 & 127); }
    else               { int c2 = c-4096; int h16 = c2 >> 8; col = h16*768 + 256 + (c2 & 255); }
    float4 acc = make_float4(0.f, 0.f, 0.f, 0.f);
#pragma unroll
    for (int j = 0; j < 4; j++) {
        int t = s - 3 + j;
        if (t >= 0) {
            float4 x = *(const float4*)&g_qkvz[(size_t)t*QKVZ_N + col];
            float4 w = *(const float4*)&cw[j*CONV_DIM + c];
            acc.x += x.x*w.x; acc.y += x.y*w.y; acc.z += x.z*w.z; acc.w += x.w*w.w;
        }
    }
    float4 r;
    r.x = acc.x / (1.f + __expf(-acc.x));
    r.y = acc.y / (1.f + __expf(-acc.y));
    r.z = acc.z / (1.f + __expf(-acc.z));
    r.w = acc.w / (1.f + __expf(-acc.w));
    if (c < 2048) {
        r.x *= QSCALE; r.y *= QSCALE; r.z *= QSCALE; r.w *= QSCALE;
        *(float4*)&g_qc[(size_t)s*2048 + c] = r;
    } else if (c < 4096) {
        *(float4*)&g_kc[(size_t)s*2048 + (c-2048)] = r;
    } else {
        *(float4*)&g_vc[(size_t)s*4096 + (c-4096)] = r;
    }
}

/* ---------------- beta, g, cumsum(g) within chunk ------------------------- */
__global__ void gates_kernel(const float* __restrict__ A_log,
                             const float* __restrict__ dt_bias) {
    int chunk = blockIdx.x, hv = blockIdx.y, t = threadIdx.x;
    int s = chunk*CHUNK + t;
    int base = ((hv >> 1) << 2) + (hv & 1);
    float bg = g_ba[(size_t)s*64 + base];
    float ag = g_ba[(size_t)s*64 + base + 2];
    g_beta[hv*SEQ + s] = 1.f / (1.f + expf(-bg));
    float x = ag + dt_bias[hv];
    float sp = (x > 20.f) ? x : log1pf(expf(x));
    float g = -expf(A_log[hv]) * sp;
    __shared__ float sh[64];
    sh[t] = g;
    __syncthreads();
    for (int off = 1; off < 64; off <<= 1) {
        float v = (t >= off) ? sh[t-off] : 0.f;
        __syncthreads();
        sh[t] += v;
        __syncthreads();
    }
    g_gcum[hv*SEQ + s] = sh[t];
}

/* ------------- per (head, chunk) parallel precompute (R14) ---------------- */
#define KSTR 132
__global__ __launch_bounds__(256, 2)
void precompute_kernel() {
    float* sm    = (float*)dynsm;
    float* ks    = sm;
    float* vs    = ks + 64*KSTR;
    float* Ls    = vs + 64*KSTR;
    float* Xs    = Ls + 4096;
    float* betas = Xs + 4096;
    float* gcs   = betas + 64;
    float* bgm   = gcs + 64;
    const int c = blockIdx.x, hv = blockIdx.y, kh = hv >> 1;
    const int tid = threadIdx.x;
    const int ti = tid >> 4, tj = tid & 15;

    for (int l = tid; l < 2048; l += 256) {
        int row = l >> 5, c4 = (l & 31) << 2;
        *(float4*)&ks[row*KSTR + c4] =
            *(const float4*)&g_kc[(size_t)(c*CHUNK+row)*2048 + kh*128 + c4];
    }
    if (tid < 64) {
        int s = c*CHUNK + tid;
        betas[tid] = g_beta[hv*SEQ + s];
        gcs[tid]   = g_gcum[hv*SEQ + s];
    }
    __syncthreads();
    if (tid < 64) bgm[tid] = betas[tid]*expf(gcs[tid]);

    {
        float2 accP[4][4];
#pragma unroll
        for (int r = 0; r < 4; r++)
#pragma unroll
            for (int q = 0; q < 4; q++) accP[r][q] = make_float2(0.f, 0.f);
        for (int d4 = 0; d4 < 128; d4 += 4) {
            float4 a4[4], b4[4];
#pragma unroll
            for (int r = 0; r < 4; r++) a4[r] = *(float4*)&ks[(ti*4+r)*KSTR + d4];
#pragma unroll
            for (int q = 0; q < 4; q++) b4[q] = *(float4*)&ks[(tj*4+q)*KSTR + d4];
#pragma unroll
            for (int r = 0; r < 4; r++)
#pragma unroll
                for (int q = 0; q < 4; q++) {
                    ffma2(accP[r][q], make_float2(a4[r].x, a4[r].y), make_float2(b4[q].x, b4[q].y));
                    ffma2(accP[r][q], make_float2(a4[r].z, a4[r].w), make_float2(b4[q].z, b4[q].w));
                }
        }
#pragma unroll
        for (int r = 0; r < 4; r++) {
            int i = ti*4 + r;
#pragma unroll
            for (int q = 0; q < 4; q++) {
                int j = tj*4 + q;
                float dot = accP[r][q].x + accP[r][q].y;
                Ls[i*64 + j] = (i > j) ? -betas[i]*dot*expf(gcs[i]-gcs[j]) : 0.f;
            }
        }
    }
    __syncthreads();

    for (int l = tid; l < 2048; l += 256) {
        int row = l >> 5, c4 = (l & 31) << 2;
        *(float4*)&vs[row*KSTR + c4] =
            *(const float4*)&g_qc[(size_t)(c*CHUNK+row)*2048 + kh*128 + c4];
    }
    if (tid < 64) {
        int j = tid;
        for (int i = 0; i < 64; i++) {
            float acc = (i == j) ? 1.f : 0.f;
            for (int m = 0; m < i; m++) acc += Ls[i*64+m]*Xs[m*64+j];
            Xs[i*64+j] = acc;
        }
    }
    __syncthreads();

    {
        float2 accP[4][4];
#pragma unroll
        for (int r = 0; r < 4; r++)
#pragma unroll
            for (int q = 0; q < 4; q++) accP[r][q] = make_float2(0.f, 0.f);
        for (int d4 = 0; d4 < 128; d4 += 4) {
            float4 a4[4], b4[4];
#pragma unroll
            for (int r = 0; r < 4; r++) a4[r] = *(float4*)&vs[(ti*4+r)*KSTR + d4];
#pragma unroll
            for (int q = 0; q < 4; q++) b4[q] = *(float4*)&ks[(tj*4+q)*KSTR + d4];
#pragma unroll
            for (int r = 0; r < 4; r++)
#pragma unroll
                for (int q = 0; q < 4; q++) {
                    ffma2(accP[r][q], make_float2(a4[r].x, a4[r].y), make_float2(b4[q].x, b4[q].y));
                    ffma2(accP[r][q], make_float2(a4[r].z, a4[r].w), make_float2(b4[q].z, b4[q].w));
                }
        }
        size_t outb = (size_t)(hv*NC + c)*4096;
#pragma unroll
        for (int r = 0; r < 4; r++) {
            int i = ti*4 + r;
#pragma unroll
            for (int q = 0; q < 4; q++) {
                int j = tj*4 + q;
                float dot = accP[r][q].x + accP[r][q].y;
                g_attnA[outb + i*64 + j] = (i >= j) ? dot*expf(gcs[i]-gcs[j]) : 0.f;
            }
        }
    }
    __syncthreads();

    for (int l = tid; l < 2048; l += 256) {
        int row = l >> 5, c4 = (l & 31) << 2;
        *(float4*)&vs[row*KSTR + c4] =
            *(const float4*)&g_vc[(size_t)(c*CHUNK+row)*4096 + hv*128 + c4];
    }
    __syncthreads();

    {
        const int iq = tid >> 5;
        const int ln = tid & 31;
        const int i0 = iq*8;
        float2 aK[8][2], aV[8][2];
#pragma unroll
        for (int r = 0; r < 8; r++)
#pragma unroll
            for (int q = 0; q < 2; q++) { aK[r][q] = make_float2(0.f, 0.f); aV[r][q] = make_float2(0.f, 0.f); }
        for (int m = 0; m < 64; m++) {
            float bg = bgm[m], bt = betas[m];
            float2 k01 = make_float2(ks[m*KSTR + ln],      ks[m*KSTR + ln + 32]);
            float2 k23 = make_float2(ks[m*KSTR + ln + 64], ks[m*KSTR + ln + 96]);
            float2 v01 = make_float2(vs[m*KSTR + ln],      vs[m*KSTR + ln + 32]);
            float2 v23 = make_float2(vs[m*KSTR + ln + 64], vs[m*KSTR + ln + 96]);
#pragma unroll
            for (int r = 0; r < 8; r++) {
                float x  = Xs[(i0+r)*64 + m];
                float2 xb2 = make_float2(x*bg, x*bg);
                float2 xv2 = make_float2(x*bt, x*bt);
                ffma2(aK[r][0], k01, xb2);
                ffma2(aK[r][1], k23, xb2);
                ffma2(aV[r][0], v01, xv2);
                ffma2(aV[r][1], v23, xv2);
            }
        }
        size_t ob = (size_t)(hv*NC + c)*CHUNK*128;
#pragma unroll
        for (int r = 0; r < 8; r++) {
            size_t o = ob + (size_t)(i0+r)*128 + ln;
            g_kcd[o]       = aK[r][0].x;  g_kcd[o + 32]   = aK[r][0].y;
            g_kcd[o + 64]  = aK[r][1].x;  g_kcd[o + 96]   = aK[r][1].y;
            g_vintra[o]      = aV[r][0].x;  g_vintra[o + 32] = aV[r][0].y;
            g_vintra[o + 64] = aV[r][1].x;  g_vintra[o + 96] = aV[r][1].y;
        }
    }
}
#define PRE_SMEM ((2*64*KSTR + 4096*2 + 192)*4)

/* ------------- sequential inter-chunk scan (R14) -------------------------- */
__global__ __launch_bounds__(256)
void scan_kernel() {
    float* smf     = (float*)dynsm;
    float2* statev = (float2*)smf;
    float* qs      = smf + 4096;
    float* ksm     = smf + 12288;
    float* vnf     = smf + 49152;
    float2* vn2    = (float2*)vnf;
    float* gcs     = smf + 51200;
    float* wexp    = smf + 51264;
    const uint32_t sb = smem_u32(dynsm);
    const int hv = blockIdx.y, j0 = blockIdx.x*32, kh = hv >> 1;
    const int tid = threadIdx.x, jj = tid & 31, ig = tid >> 5;
    const int i0 = ig*8;

    for (int l = tid; l < 2048; l += 256) statev[l] = make_float2(0.f, 0.f);
    __syncthreads();

    auto prefetch = [&](int c, int buf) {
        const size_t rb = (size_t)(hv*NC + c)*CHUNK;
        uint32_t kb = sb + (20480 + buf*8192)*4;
        const char* ks_src = (const char*)(g_kcd + rb*128);
        for (int i = tid; i < 2048; i += 256)
            CP_ASYNC16(kb + i*16, ks_src + i*16);
        uint32_t ab = sb + (36864 + buf*4096)*4;
        const char* as_src = (const char*)(g_attnA + rb*64);
        for (int i = tid; i < 1024; i += 256)
            CP_ASYNC16(ab + i*16, as_src + i*16);
        uint32_t vb = sb + (45056 + buf*2048)*4;
        for (int i = tid; i < 512; i += 256) {
            int row = i >> 3, off = (i & 7)*16;
            CP_ASYNC16(vb + row*128 + off,
                       (const char*)(g_vintra + (rb+row)*128 + j0) + off);
        }
    };

    prefetch(0, 0); CP_COMMIT();

    for (int c = 0; c < NC; c++) {
        const int cur = c & 1;
        float* kcds   = smf + 20480 + cur*8192;
        float* as_    = smf + 36864 + cur*4096;
        float* vnraw  = smf + 45056 + cur*2048;

        for (int l = tid; l < 2048; l += 256) {
            int row = l >> 5, c4 = (l & 31) << 2;
            *(float4*)&qs[row*128 + c4]  = *(const float4*)&g_qc[(size_t)(c*CHUNK+row)*2048 + kh*128 + c4];
            *(float4*)&ksm[row*128 + c4] = *(const float4*)&g_kc[(size_t)(c*CHUNK+row)*2048 + kh*128 + c4];
        }
        if (tid < 64) gcs[tid] = g_gcum[hv*SEQ + c*CHUNK + tid];
        CP_WAIT0();
        __syncthreads();
        if (c + 1 < NC) { prefetch(c + 1, cur ^ 1); }
        CP_COMMIT();
        if (tid < 64) wexp[tid] = expf(gcs[63] - gcs[tid]);

        float2 kacc[8], qacc[8];
#pragma unroll
        for (int r = 0; r < 8; r++) {
            kacc[r] = make_float2(0.f, 0.f);
            qacc[r] = make_float2(0.f, 0.f);
        }
        for (int dp2 = 0; dp2 < 32; dp2++) {
            float2 sv0 = statev[(dp2*2)*32 + jj];
            float2 sv1 = statev[(dp2*2+1)*32 + jj];
#pragma unroll
            for (int r = 0; r < 8; r++) {
                float4 kq = *(float4*)&kcds[(i0+r)*128 + dp2*4];
                ffma2(kacc[r], make_float2(kq.x, kq.y), sv0);
                ffma2(kacc[r], make_float2(kq.z, kq.w), sv1);
                float4 qq = *(float4*)&qs[(i0+r)*128 + dp2*4];
                ffma2(qacc[r], make_float2(qq.x, qq.y), sv0);
                ffma2(qacc[r], make_float2(qq.z, qq.w), sv1);
            }
        }
        float vnew[8], oo[8];
#pragma unroll
        for (int r = 0; r < 8; r++) {
            vnew[r] = vnraw[(i0+r)*32 + jj] - (kacc[r].x + kacc[r].y);
            oo[r]   = (qacc[r].x + qacc[r].y) * expf(gcs[i0+r]);
        }
#pragma unroll
        for (int rp = 0; rp < 4; rp++)
            vn2[((i0 >> 1) + rp)*32 + jj] = make_float2(vnew[2*rp], vnew[2*rp+1]);
        __syncthreads();

        float2 oacc[8];
#pragma unroll
        for (int r = 0; r < 8; r++) oacc[r] = make_float2(0.f, 0.f);
        for (int mp2 = 0; mp2 < 16; mp2++) {
            float2 vv0 = vn2[(mp2*2)*32 + jj];
            float2 vv1 = vn2[(mp2*2+1)*32 + jj];
#pragma unroll
            for (int r = 0; r < 8; r++) {
                float4 aa = *(float4*)&as_[(i0+r)*64 + mp2*4];
                ffma2(oacc[r], make_float2(aa.x, aa.y), vv0);
                ffma2(oacc[r], make_float2(aa.z, aa.w), vv1);
            }
        }
#pragma unroll
        for (int r = 0; r < 8; r++) {
            float o = oo[r] + oacc[r].x + oacc[r].y;
            g_core[(size_t)(c*CHUNK + i0 + r)*4096 + hv*128 + j0 + jj] = o;
        }

        {
            float eg = expf(gcs[63]);
            float2 sacc[8];
#pragma unroll
            for (int dd = 0; dd < 8; dd++) {
                float2 sv = statev[(i0 + dd)*32 + jj];
                sacc[dd] = make_float2(sv.x*eg, sv.y*eg);
            }
            for (int i = 0; i < 64; i++) {
                float vw = wexp[i] * vnf[(i >> 1)*64 + jj*2 + (i & 1)];
                float2 vw2 = make_float2(vw, vw);
#pragma unroll
                for (int e = 0; e < 4; e++) {
                    float4 kk = *(float4*)&ksm[i*128 + i0*2 + e*4];
                    ffma2(sacc[2*e],   make_float2(kk.x, kk.y), vw2);
                    ffma2(sacc[2*e+1], make_float2(kk.z, kk.w), vw2);
                }
            }
#pragma unroll
            for (int dd = 0; dd < 8; dd++)
                statev[(i0 + dd)*32 + jj] = sacc[dd];
        }
        __syncthreads();
    }
}

/* ------- gated RMSNorm fused with fp16 A2 emission ------------------------ */
__global__ void rmsnorm_kernel(const float* __restrict__ nw) {
    int gw = (blockIdx.x*blockDim.x + threadIdx.x) >> 5;
    int lane = threadIdx.x & 31;
    int s = gw >> 5;
    int hv = gw & 31;
    int d0 = lane*4;
    size_t zbase = (size_t)s*QKVZ_N + (hv >> 1)*768 + 512 + (hv & 1)*128 + d0;
    size_t cbase = (size_t)s*4096 + hv*128 + d0;
    float4 cv = *(const float4*)&g_core[cbase];
    float4 zv = *(const float4*)&g_qkvz[zbase];
    float x[4];
    x[0] = cv.x * (zv.x / (1.f + expf(-zv.x)));
    x[1] = cv.y * (zv.y / (1.f + expf(-zv.y)));
    x[2] = cv.z * (zv.z / (1.f + expf(-zv.z)));
    x[3] = cv.w * (zv.w / (1.f + expf(-zv.w)));
    float ss = x[0]*x[0] + x[1]*x[1] + x[2]*x[2] + x[3]*x[3];
#pragma unroll
    for (int off = 16; off; off >>= 1) ss += __shfl_xor_sync(0xffffffffu, ss, off);
    float inv = rsqrtf(ss*(1.f/128.f) + 1e-6f);
    float y[4];
#pragma unroll
    for (int r = 0; r < 4; r++) y[r] = x[r]*inv*nw[d0 + r];
    *(__half2*)&g_A2h[cbase]     = __floats2half2_rn(y[0], y[1]);
    *(__half2*)&g_A2h[cbase + 2] = __floats2half2_rn(y[2], y[3]);
}

/* ---------------- launcher ------------------------------------------------ */
extern "C" void kernel_launch(void* const* d_in, const int* in_sizes, int n_in,
                              void* d_out, int out_size) {
    const float* hidden  = (const float*)d_in[0];
    const float* W_qkvz  = (const float*)d_in[1];
    const float* W_ba    = (const float*)d_in[2];
    const float* convk   = (const float*)d_in[3];
    const float* A_log   = (const float*)d_in[4];
    const float* dt_bias = (const float*)d_in[5];
    const float* normw   = (const float*)d_in[6];
    const float* W_out   = (const float*)d_in[7];
    float* out = (float*)d_out;

    float *qkvz_p;
    __nv_bfloat16 *A1, *B1;
    __half *A2h, *B2h;
    cudaGetSymbolAddress((void**)&qkvz_p, g_qkvz);
    cudaGetSymbolAddress((void**)&A1, g_A1);
    cudaGetSymbolAddress((void**)&B1, g_B1);
    cudaGetSymbolAddress((void**)&A2h, g_A2h);
    cudaGetSymbolAddress((void**)&B2h, g_B2h);

    cudaFuncSetAttribute(precompute_kernel,
                         cudaFuncAttributeMaxDynamicSharedMemorySize, PRE_SMEM);
    cudaFuncSetAttribute(scan_kernel,
                         cudaFuncAttributeMaxDynamicSharedMemorySize, 205312);
    cudaFuncSetAttribute(gemm_mma<0>,
                         cudaFuncAttributeMaxDynamicSharedMemorySize, 3*GSTAGE);
    cudaFuncSetAttribute(gemm_mma<1>,
                         cudaFuncAttributeMaxDynamicSharedMemorySize, 3*GSTAGE);

    /* conversions for GEMM1 + static W_out (fp16) for GEMM2 */
    cvtA<<<(SEQ*EMB)/512, 256>>>(hidden, A1, 11);              /* K=2048 */
    cvtBt<<<dim3(EMB/64, QKVZ_N/32), 256>>>(W_qkvz, B1, EMB, QKVZ_N);
    cvtBth<<<dim3(4096/64, EMB/32), 256>>>(W_out, B2h, 4096, EMB);

    /* 1. qkvz = hidden @ W_qkvz  (bf16x3 mma.sync, K'=6144) */
    gemm_mma<0><<<dim3(QKVZ_N/128, SEQ/128), 256, 3*GSTAGE>>>(A1, B1, qkvz_p, 3*EMB, QKVZ_N);
    /* 2. ba */
    ba_gemm<<<256, 256>>>(hidden, W_ba);
    /* 3. conv + silu (float4) */
    conv_silu<<<(SEQ*CONV_DIM)/1024, 256>>>(convk);
    /* 4. gates */
    gates_kernel<<<dim3(NC, NVH), 64>>>(A_log, dt_bias);
    /* 5. precompute (f32x2) */
    precompute_kernel<<<dim3(NC, NVH), 256, PRE_SMEM>>>();
    /* 6. scan (f32x2 + float4 + cp.async prefetch) */
    scan_kernel<<<dim3(4, NVH), 256, 205312>>>();
    /* 7. rmsnorm + fp16 A2 emission (fused) */
    rmsnorm_kernel<<<(SEQ*NVH)/8, 256>>>(normw);
    /* 8. out = xf @ W_out  (plain fp16 mma.sync, K=4096) */
    gemm_mma<1><<<dim3(EMB/128, SEQ/128), 256, 3*GSTAGE>>>(
        (const __nv_bfloat16*)A2h, (const __nv_bfloat16*)B2h, out, 4096, EMB);
}